// round 6
// baseline (speedup 1.0000x reference)
#include <cuda_runtime.h>
#include <cuda_bf16.h>
#include <math.h>
#include <stdint.h>

#define BB 4
#define TT 2048
#define CC 1024
#define HH 16
#define DD 64
#define MM (BB*TT)   // 8192

// ---------------------------------------------------------------------------
// Scratch (device globals; no allocation allowed)
// ---------------------------------------------------------------------------
__device__ float g_q[MM * CC];
__device__ float g_k[MM * CC];
__device__ float g_v[MM * CC];
__device__ __nv_bfloat16 g_xhi[MM * CC];
__device__ __nv_bfloat16 g_xlo[MM * CC];
__device__ __nv_bfloat16 g_ahi[MM * CC];
__device__ __nv_bfloat16 g_alo[MM * CC];
__device__ __nv_bfloat16 g_whi[4 * CC * CC];
__device__ __nv_bfloat16 g_wlo[4 * CC * CC];

// ---------------------------------------------------------------------------
__device__ __forceinline__ uint32_t smem_u32(const void* p) {
    uint32_t a;
    asm("{ .reg .u64 t; cvta.to.shared.u64 t, %1; cvt.u32.u64 %0, t; }"
        : "=r"(a) : "l"(p));
    return a;
}

__device__ __forceinline__ void cp16(uint32_t dst, const void* src) {
    asm volatile("cp.async.cg.shared.global [%0], [%1], 16;"
                 :: "r"(dst), "l"(src) : "memory");
}
#define CP_COMMIT() asm volatile("cp.async.commit_group;" ::: "memory")
#define CP_WAIT(n)  asm volatile("cp.async.wait_group %0;" :: "n"(n) : "memory")

__device__ __forceinline__ void mma_bf16(float* d, const uint32_t* a, const uint32_t* b) {
    asm volatile(
        "mma.sync.aligned.m16n8k16.row.col.f32.bf16.bf16.f32 "
        "{%0,%1,%2,%3}, {%4,%5,%6,%7}, {%8,%9}, {%0,%1,%2,%3};"
        : "+f"(d[0]), "+f"(d[1]), "+f"(d[2]), "+f"(d[3])
        : "r"(a[0]), "r"(a[1]), "r"(a[2]), "r"(a[3]), "r"(b[0]), "r"(b[1]));
}

__device__ __forceinline__ void ldm_x4(uint32_t* r, uint32_t addr) {
    asm volatile("ldmatrix.sync.aligned.m8n8.x4.shared.b16 {%0,%1,%2,%3}, [%4];"
                 : "=r"(r[0]), "=r"(r[1]), "=r"(r[2]), "=r"(r[3]) : "r"(addr));
}
__device__ __forceinline__ void ldm_x2(uint32_t* r, uint32_t addr) {
    asm volatile("ldmatrix.sync.aligned.m8n8.x2.shared.b16 {%0,%1}, [%2];"
                 : "=r"(r[0]), "=r"(r[1]) : "r"(addr));
}

__device__ __forceinline__ uint32_t lds32(uint32_t addr) {
    uint32_t v;
    asm volatile("ld.shared.b32 %0, [%1];" : "=r"(v) : "r"(addr));
    return v;
}

__device__ __forceinline__ uint32_t pack_bf16x2(float lo, float hi) {
    uint32_t r;
    asm("cvt.rn.bf16x2.f32 %0, %1, %2;" : "=r"(r) : "f"(hi), "f"(lo));
    return r;
}

// ---------------------------------------------------------------------------
// fp32 -> bf16 hi/lo split
// ---------------------------------------------------------------------------
__global__ void split_kernel(const float* __restrict__ in,
                             __nv_bfloat16* __restrict__ hi,
                             __nv_bfloat16* __restrict__ lo, int n4)
{
    int i = blockIdx.x * blockDim.x + threadIdx.x;
    if (i >= n4) return;
    float4 v = ((const float4*)in)[i];
    __nv_bfloat16 h0 = __float2bfloat16(v.x);
    __nv_bfloat16 h1 = __float2bfloat16(v.y);
    __nv_bfloat16 h2 = __float2bfloat16(v.z);
    __nv_bfloat16 h3 = __float2bfloat16(v.w);
    __nv_bfloat16 l0 = __float2bfloat16(v.x - __bfloat162float(h0));
    __nv_bfloat16 l1 = __float2bfloat16(v.y - __bfloat162float(h1));
    __nv_bfloat16 l2 = __float2bfloat16(v.z - __bfloat162float(h2));
    __nv_bfloat16 l3 = __float2bfloat16(v.w - __bfloat162float(h3));
    __nv_bfloat162* hp = (__nv_bfloat162*)hi;
    __nv_bfloat162* lp = (__nv_bfloat162*)lo;
    hp[2 * i + 0] = __nv_bfloat162(h0, h1);
    hp[2 * i + 1] = __nv_bfloat162(h2, h3);
    lp[2 * i + 0] = __nv_bfloat162(l0, l1);
    lp[2 * i + 1] = __nv_bfloat162(l2, l3);
}

// ---------------------------------------------------------------------------
// Core GEMM tile: C[128,128] = A[M,K] x W[N,K]^T  (hi/lo compensated)
// BK=64, 3-stage cp.async ring, ONE __syncthreads per chunk, ldmatrix loads.
// SMEM rows padded to 144B (64 bf16 data + 8 pad) -> conflict-free ldmatrix.
// ---------------------------------------------------------------------------
#define ROWB 144u
#define TILEB (128u*ROWB)       // 18432
#define STAGEB (4u*TILEB)       // 73728
#define NSTAGE 3
#define NCHUNK (CC/64)          // 16

__device__ __forceinline__ void gemm_tile(
    const __nv_bfloat16* __restrict__ Ahi, const __nv_bfloat16* __restrict__ Alo,
    const __nv_bfloat16* __restrict__ Bhi, const __nv_bfloat16* __restrict__ Blo,
    float* __restrict__ C, int m0, int n0, char* smem)
{
    const uint32_t sb = smem_u32(smem);
    const int tid  = threadIdx.x;
    const int lane = tid & 31;
    const int wid  = tid >> 5;
    const int wm   = wid >> 1;
    const int wn   = wid & 1;

    const __nv_bfloat16* srcs[4] = {
        Ahi + (size_t)m0 * CC, Alo + (size_t)m0 * CC,
        Bhi + (size_t)n0 * CC, Blo + (size_t)n0 * CC };

    // One stage = 4 tiles x 128 rows x 128 data bytes = 4096 x 16B segments.
    auto issue_stage = [&](int chunk, int stage) {
        const int kc = chunk * 64;
        const uint32_t base = sb + (uint32_t)stage * STAGEB;
#pragma unroll
        for (int t = 0; t < 16; t++) {
            int lin  = tid + t * 256;        // 0..4095
            int tile = lin >> 10;            // 0..3
            int idx  = lin & 1023;
            int row  = idx >> 3;             // 0..127
            int seg  = idx & 7;              // 0..7 (16B segments)
            uint32_t dst = base + (uint32_t)tile * TILEB + (uint32_t)row * ROWB + (uint32_t)seg * 16u;
            cp16(dst, srcs[tile] + (size_t)row * CC + kc + seg * 8);
        }
        CP_COMMIT();
    };

    float acc[2][8][4];
#pragma unroll
    for (int i = 0; i < 2; i++)
#pragma unroll
        for (int j = 0; j < 8; j++)
#pragma unroll
            for (int r = 0; r < 4; r++) acc[i][j][r] = 0.f;

    issue_stage(0, 0);
    issue_stage(1, 1);

    const uint32_t a_row  = (uint32_t)(lane & 15);
    const uint32_t a_koff = (uint32_t)(lane >> 4) * 16u;
    const uint32_t b_row  = (uint32_t)(lane & 7);
    const uint32_t b_koff = (uint32_t)((lane >> 3) & 1) * 16u;

    for (int c = 0; c < NCHUNK; c++) {
        const int stage = c % NSTAGE;
        CP_WAIT(1);              // chunk c's group has landed (c+1 may pend)
        __syncthreads();         // all warps done reading stage (c-1)%3
        if (c + 2 < NCHUNK) issue_stage(c + 2, (c + 2) % NSTAGE);

        const uint32_t base  = sb + (uint32_t)stage * STAGEB;
        const uint32_t Aho   = base;
        const uint32_t Alo_o = base + TILEB;
        const uint32_t Bho   = base + 2u * TILEB;
        const uint32_t Blo_o = base + 3u * TILEB;

#pragma unroll
        for (int kk = 0; kk < 4; kk++) {
            const uint32_t ko = (uint32_t)kk * 32u;
            uint32_t ah[2][4], al[2][4];
#pragma unroll
            for (int fi = 0; fi < 2; fi++) {
                uint32_t ra = (uint32_t)(wm * 32 + fi * 16) * ROWB + a_row * ROWB + ko + a_koff;
                ldm_x4(ah[fi], Aho + ra);
                ldm_x4(al[fi], Alo_o + ra);
            }
#pragma unroll
            for (int j = 0; j < 8; j++) {
                uint32_t rb = (uint32_t)(wn * 64 + j * 8) * ROWB + b_row * ROWB + ko + b_koff;
                uint32_t bh[2], bl[2];
                ldm_x2(bh, Bho + rb);
                ldm_x2(bl, Blo_o + rb);
#pragma unroll
                for (int fi = 0; fi < 2; fi++) {
                    mma_bf16(acc[fi][j], ah[fi], bh);
                    mma_bf16(acc[fi][j], ah[fi], bl);
                    mma_bf16(acc[fi][j], al[fi], bh);
                }
            }
        }
    }

#pragma unroll
    for (int fi = 0; fi < 2; fi++) {
        int row0 = m0 + wm * 32 + fi * 16 + (lane >> 2);
#pragma unroll
        for (int j = 0; j < 8; j++) {
            int col = n0 + wn * 64 + j * 8 + (lane & 3) * 2;
            *(float2*)&C[(size_t)row0 * CC + col]       = make_float2(acc[fi][j][0], acc[fi][j][1]);
            *(float2*)&C[(size_t)(row0 + 8) * CC + col] = make_float2(acc[fi][j][2], acc[fi][j][3]);
        }
    }
}

// Fused QKV: grid.x in [0,24): wsel = x>>3 selects weight/output, n0 = (x&7)*128
__global__ __launch_bounds__(256) void gemm_qkv(
    const __nv_bfloat16* __restrict__ xhi, const __nv_bfloat16* __restrict__ xlo,
    const __nv_bfloat16* __restrict__ whi, const __nv_bfloat16* __restrict__ wlo,
    float* __restrict__ q, float* __restrict__ k, float* __restrict__ v)
{
    extern __shared__ char smem[];
    const int wsel = blockIdx.x >> 3;
    const int n0 = (blockIdx.x & 7) * 128;
    const int m0 = blockIdx.y * 128;
    float* outs[3] = { q, k, v };
    gemm_tile(xhi, xlo,
              whi + (size_t)wsel * CC * CC, wlo + (size_t)wsel * CC * CC,
              outs[wsel], m0, n0, smem);
}

__global__ __launch_bounds__(256) void gemm_one(
    const __nv_bfloat16* __restrict__ Ahi, const __nv_bfloat16* __restrict__ Alo,
    const __nv_bfloat16* __restrict__ Bhi, const __nv_bfloat16* __restrict__ Blo,
    float* __restrict__ C)
{
    extern __shared__ char smem[];
    gemm_tile(Ahi, Alo, Bhi, Blo, C, blockIdx.y * 128, blockIdx.x * 128, smem);
}

// ---------------------------------------------------------------------------
// Tensor-core flash attention (causal), bf16 hi/lo MMAs, fp32 softmax.
// Epilogue writes bf16 hi/lo directly (feeds final GEMM, no split pass).
// ---------------------------------------------------------------------------
#define AP 72
#define ATILE (64 * AP)

__global__ __launch_bounds__(128) void attn_tc()
{
    extern __shared__ __nv_bfloat16 ash[];
    __nv_bfloat16* Qh = ash;
    __nv_bfloat16* Ql = Qh + ATILE;
    __nv_bfloat16* Kh = Ql + ATILE;
    __nv_bfloat16* Kl = Kh + ATILE;
    __nv_bfloat16* Vh = Kl + ATILE;
    __nv_bfloat16* Vl = Vh + ATILE;
    const uint32_t sQh = smem_u32(Qh), sQl = smem_u32(Ql);
    const uint32_t sKh = smem_u32(Kh), sKl = smem_u32(Kl);
    const uint32_t sVh = smem_u32(Vh), sVl = smem_u32(Vl);

    const int tid  = threadIdx.x;
    const int lane = tid & 31;
    const int w    = tid >> 5;
    const int qtile = blockIdx.x;
    const int bh = blockIdx.y;
    const int b = bh / HH, h = bh % HH;
    const int q0 = qtile * 64;

    const float* qptr = g_q + (size_t)b * TT * CC + h * DD;
    const float* kptr = g_k + (size_t)b * TT * CC + h * DD;
    const float* vptr = g_v + (size_t)b * TT * CC + h * DD;

#pragma unroll
    for (int it = 0; it < 8; it++) {
        int lin = tid + it * 128;
        int row = lin >> 4;
        int c4  = (lin & 15) * 4;
        float4 v4 = *(const float4*)&qptr[(size_t)(q0 + row) * CC + c4];
        float f[4] = { v4.x * 0.125f, v4.y * 0.125f, v4.z * 0.125f, v4.w * 0.125f };
        __nv_bfloat16 hh[4], ll[4];
#pragma unroll
        for (int e = 0; e < 4; e++) {
            hh[e] = __float2bfloat16(f[e]);
            ll[e] = __float2bfloat16(f[e] - __bfloat162float(hh[e]));
        }
        *(__nv_bfloat162*)&Qh[row * AP + c4]     = __nv_bfloat162(hh[0], hh[1]);
        *(__nv_bfloat162*)&Qh[row * AP + c4 + 2] = __nv_bfloat162(hh[2], hh[3]);
        *(__nv_bfloat162*)&Ql[row * AP + c4]     = __nv_bfloat162(ll[0], ll[1]);
        *(__nv_bfloat162*)&Ql[row * AP + c4 + 2] = __nv_bfloat162(ll[2], ll[3]);
    }
    __syncthreads();

    uint32_t aqh[4][4], aql[4][4];
    {
        const uint32_t kb = (uint32_t)(lane & 3) * 4u;
        const uint32_t r0 = (uint32_t)(w * 16 + (lane >> 2)) * (AP * 2) + kb;
        const uint32_t r1 = r0 + 8u * (AP * 2);
#pragma unroll
        for (int s = 0; s < 4; s++) {
            uint32_t ko = (uint32_t)s * 32u;
            aqh[s][0] = lds32(sQh + r0 + ko);       aqh[s][1] = lds32(sQh + r1 + ko);
            aqh[s][2] = lds32(sQh + r0 + ko + 16u); aqh[s][3] = lds32(sQh + r1 + ko + 16u);
            aql[s][0] = lds32(sQl + r0 + ko);       aql[s][1] = lds32(sQl + r1 + ko);
            aql[s][2] = lds32(sQl + r0 + ko + 16u); aql[s][3] = lds32(sQl + r1 + ko + 16u);
        }
    }

    float m0r = -1e30f, m1r = -1e30f, l0r = 0.f, l1r = 0.f;
    float ofr[8][4];
#pragma unroll
    for (int j = 0; j < 8; j++)
#pragma unroll
        for (int r = 0; r < 4; r++) ofr[j][r] = 0.f;

    const int r0g = q0 + w * 16 + (lane >> 2);
    const int r1g = r0g + 8;

    const int nkt = qtile + 1;
    for (int kt = 0; kt < nkt; kt++) {
        const int k0 = kt * 64;
        __syncthreads();
#pragma unroll
        for (int it = 0; it < 8; it++) {
            int lin = tid + it * 128;
            int row = lin >> 4;
            int c4  = (lin & 15) * 4;
            float4 kv = *(const float4*)&kptr[(size_t)(k0 + row) * CC + c4];
            float kf[4] = { kv.x, kv.y, kv.z, kv.w };
            __nv_bfloat16 khh[4], kll[4];
#pragma unroll
            for (int e = 0; e < 4; e++) {
                khh[e] = __float2bfloat16(kf[e]);
                kll[e] = __float2bfloat16(kf[e] - __bfloat162float(khh[e]));
            }
            *(__nv_bfloat162*)&Kh[row * AP + c4]     = __nv_bfloat162(khh[0], khh[1]);
            *(__nv_bfloat162*)&Kh[row * AP + c4 + 2] = __nv_bfloat162(khh[2], khh[3]);
            *(__nv_bfloat162*)&Kl[row * AP + c4]     = __nv_bfloat162(kll[0], kll[1]);
            *(__nv_bfloat162*)&Kl[row * AP + c4 + 2] = __nv_bfloat162(kll[2], kll[3]);

            float4 vv = *(const float4*)&vptr[(size_t)(k0 + row) * CC + c4];
            float vf[4] = { vv.x, vv.y, vv.z, vv.w };
#pragma unroll
            for (int e = 0; e < 4; e++) {
                __nv_bfloat16 vh = __float2bfloat16(vf[e]);
                __nv_bfloat16 vl = __float2bfloat16(vf[e] - __bfloat162float(vh));
                Vh[(c4 + e) * AP + row] = vh;
                Vl[(c4 + e) * AP + row] = vl;
            }
        }
        __syncthreads();

        float sfr[8][4];
#pragma unroll
        for (int j = 0; j < 8; j++)
#pragma unroll
            for (int r = 0; r < 4; r++) sfr[j][r] = 0.f;

        const uint32_t kb = (uint32_t)(lane & 3) * 4u;
#pragma unroll
        for (int j = 0; j < 8; j++) {
            uint32_t nrow = (uint32_t)(j * 8 + (lane >> 2)) * (AP * 2) + kb;
#pragma unroll
            for (int s = 0; s < 4; s++) {
                uint32_t ko = (uint32_t)s * 32u;
                uint32_t bhf[2], blf[2];
                bhf[0] = lds32(sKh + nrow + ko); bhf[1] = lds32(sKh + nrow + ko + 16u);
                blf[0] = lds32(sKl + nrow + ko); blf[1] = lds32(sKl + nrow + ko + 16u);
                mma_bf16(sfr[j], aqh[s], bhf);
                mma_bf16(sfr[j], aqh[s], blf);
                mma_bf16(sfr[j], aql[s], bhf);
            }
        }

        if (kt == qtile) {
#pragma unroll
            for (int j = 0; j < 8; j++) {
                int cbase = k0 + j * 8 + 2 * (lane & 3);
                if (cbase > r0g)     sfr[j][0] = -1e30f;
                if (cbase + 1 > r0g) sfr[j][1] = -1e30f;
                if (cbase > r1g)     sfr[j][2] = -1e30f;
                if (cbase + 1 > r1g) sfr[j][3] = -1e30f;
            }
        }

        float mx0 = -1e30f, mx1 = -1e30f;
#pragma unroll
        for (int j = 0; j < 8; j++) {
            mx0 = fmaxf(mx0, fmaxf(sfr[j][0], sfr[j][1]));
            mx1 = fmaxf(mx1, fmaxf(sfr[j][2], sfr[j][3]));
        }
        mx0 = fmaxf(mx0, __shfl_xor_sync(0xffffffffu, mx0, 1));
        mx0 = fmaxf(mx0, __shfl_xor_sync(0xffffffffu, mx0, 2));
        mx1 = fmaxf(mx1, __shfl_xor_sync(0xffffffffu, mx1, 1));
        mx1 = fmaxf(mx1, __shfl_xor_sync(0xffffffffu, mx1, 2));

        float mn0 = fmaxf(m0r, mx0), mn1 = fmaxf(m1r, mx1);
        float corr0 = __expf(m0r - mn0), corr1 = __expf(m1r - mn1);
        m0r = mn0; m1r = mn1;

        float rs0 = 0.f, rs1 = 0.f;
#pragma unroll
        for (int j = 0; j < 8; j++) {
            sfr[j][0] = __expf(sfr[j][0] - mn0);
            sfr[j][1] = __expf(sfr[j][1] - mn0);
            sfr[j][2] = __expf(sfr[j][2] - mn1);
            sfr[j][3] = __expf(sfr[j][3] - mn1);
            rs0 += sfr[j][0] + sfr[j][1];
            rs1 += sfr[j][2] + sfr[j][3];
        }
        rs0 += __shfl_xor_sync(0xffffffffu, rs0, 1);
        rs0 += __shfl_xor_sync(0xffffffffu, rs0, 2);
        rs1 += __shfl_xor_sync(0xffffffffu, rs1, 1);
        rs1 += __shfl_xor_sync(0xffffffffu, rs1, 2);
        l0r = l0r * corr0 + rs0;
        l1r = l1r * corr1 + rs1;

#pragma unroll
        for (int j = 0; j < 8; j++) {
            ofr[j][0] *= corr0; ofr[j][1] *= corr0;
            ofr[j][2] *= corr1; ofr[j][3] *= corr1;
        }

        uint32_t pah[4][4], pal[4][4];
#pragma unroll
        for (int s = 0; s < 4; s++) {
            const int ja = 2 * s, jb = 2 * s + 1;
            float p[8] = { sfr[ja][0], sfr[ja][1], sfr[ja][2], sfr[ja][3],
                           sfr[jb][0], sfr[jb][1], sfr[jb][2], sfr[jb][3] };
            __nv_bfloat16 phh[8];
            float pl[8];
#pragma unroll
            for (int e = 0; e < 8; e++) {
                phh[e] = __float2bfloat16(p[e]);
                pl[e] = p[e] - __bfloat162float(phh[e]);
            }
            pah[s][0] = pack_bf16x2(__bfloat162float(phh[0]), __bfloat162float(phh[1]));
            pah[s][1] = pack_bf16x2(__bfloat162float(phh[2]), __bfloat162float(phh[3]));
            pah[s][2] = pack_bf16x2(__bfloat162float(phh[4]), __bfloat162float(phh[5]));
            pah[s][3] = pack_bf16x2(__bfloat162float(phh[6]), __bfloat162float(phh[7]));
            pal[s][0] = pack_bf16x2(pl[0], pl[1]);
            pal[s][1] = pack_bf16x2(pl[2], pl[3]);
            pal[s][2] = pack_bf16x2(pl[4], pl[5]);
            pal[s][3] = pack_bf16x2(pl[6], pl[7]);
        }

#pragma unroll
        for (int j = 0; j < 8; j++) {
            uint32_t drow = (uint32_t)(j * 8 + (lane >> 2)) * (AP * 2) + kb;
#pragma unroll
            for (int s = 0; s < 4; s++) {
                uint32_t ko = (uint32_t)s * 32u;
                uint32_t bvh[2], bvl[2];
                bvh[0] = lds32(sVh + drow + ko); bvh[1] = lds32(sVh + drow + ko + 16u);
                bvl[0] = lds32(sVl + drow + ko); bvl[1] = lds32(sVl + drow + ko + 16u);
                mma_bf16(ofr[j], pah[s], bvh);
                mma_bf16(ofr[j], pah[s], bvl);
                mma_bf16(ofr[j], pal[s], bvh);
            }
        }
    }

    float inv0 = 1.f / l0r, inv1 = 1.f / l1r;
    __nv_bfloat16* ahp = g_ahi + (size_t)b * TT * CC + h * DD;
    __nv_bfloat16* alp = g_alo + (size_t)b * TT * CC + h * DD;
#pragma unroll
    for (int j = 0; j < 8; j++) {
        int col = j * 8 + 2 * (lane & 3);
        float v0 = ofr[j][0] * inv0, v1 = ofr[j][1] * inv0;
        float v2 = ofr[j][2] * inv1, v3 = ofr[j][3] * inv1;
        __nv_bfloat16 h0 = __float2bfloat16(v0), h1 = __float2bfloat16(v1);
        __nv_bfloat16 h2 = __float2bfloat16(v2), h3 = __float2bfloat16(v3);
        *(uint32_t*)&ahp[(size_t)r0g * CC + col] =
            pack_bf16x2(__bfloat162float(h0), __bfloat162float(h1));
        *(uint32_t*)&alp[(size_t)r0g * CC + col] =
            pack_bf16x2(v0 - __bfloat162float(h0), v1 - __bfloat162float(h1));
        *(uint32_t*)&ahp[(size_t)r1g * CC + col] =
            pack_bf16x2(__bfloat162float(h2), __bfloat162float(h3));
        *(uint32_t*)&alp[(size_t)r1g * CC + col] =
            pack_bf16x2(v2 - __bfloat162float(h2), v3 - __bfloat162float(h3));
    }
}

// ---------------------------------------------------------------------------
extern "C" void kernel_launch(void* const* d_in, const int* in_sizes, int n_in,
                              void* d_out, int out_size)
{
    const float* x   = (const float*)d_in[0];
    const float* W_Q = (const float*)d_in[1];
    const float* W_K = (const float*)d_in[2];
    const float* W_V = (const float*)d_in[3];
    const float* W_O = (const float*)d_in[4];
    float* out = (float*)d_out;

    float *q, *k, *v;
    __nv_bfloat16 *xhi, *xlo, *ahi, *alo, *whi, *wlo;
    cudaGetSymbolAddress((void**)&q,    g_q);
    cudaGetSymbolAddress((void**)&k,    g_k);
    cudaGetSymbolAddress((void**)&v,    g_v);
    cudaGetSymbolAddress((void**)&xhi,  g_xhi);
    cudaGetSymbolAddress((void**)&xlo,  g_xlo);
    cudaGetSymbolAddress((void**)&ahi,  g_ahi);
    cudaGetSymbolAddress((void**)&alo,  g_alo);
    cudaGetSymbolAddress((void**)&whi,  g_whi);
    cudaGetSymbolAddress((void**)&wlo,  g_wlo);

    const int gemm_smem = NSTAGE * (int)STAGEB;   // 221184
    cudaFuncSetAttribute(gemm_qkv,
                         cudaFuncAttributeMaxDynamicSharedMemorySize, gemm_smem);
    cudaFuncSetAttribute(gemm_one,
                         cudaFuncAttributeMaxDynamicSharedMemorySize, gemm_smem);
    const int attn_smem = 6 * ATILE * (int)sizeof(__nv_bfloat16);
    cudaFuncSetAttribute(attn_tc,
                         cudaFuncAttributeMaxDynamicSharedMemorySize, attn_smem);

    {
        int n4 = MM * CC / 4;
        split_kernel<<<(n4 + 255) / 256, 256>>>(x, xhi, xlo, n4);
        int w4 = CC * CC / 4;
        split_kernel<<<(w4 + 255) / 256, 256>>>(W_Q, whi + 0 * CC * CC, wlo + 0 * CC * CC, w4);
        split_kernel<<<(w4 + 255) / 256, 256>>>(W_K, whi + 1 * CC * CC, wlo + 1 * CC * CC, w4);
        split_kernel<<<(w4 + 255) / 256, 256>>>(W_V, whi + 2 * CC * CC, wlo + 2 * CC * CC, w4);
        split_kernel<<<(w4 + 255) / 256, 256>>>(W_O, whi + 3 * CC * CC, wlo + 3 * CC * CC, w4);
    }

    dim3 qkvgrid(24, MM / 128);   // (24, 64)
    gemm_qkv<<<qkvgrid, 256, gemm_smem>>>(xhi, xlo, whi, wlo, q, k, v);

    dim3 agrid(TT / 64, BB * HH);
    attn_tc<<<agrid, 128, attn_smem>>>();

    dim3 ogrid(CC / 128, MM / 128);
    gemm_one<<<ogrid, 256, gemm_smem>>>(ahi, alo, whi + 3 * CC * CC, wlo + 3 * CC * CC, out);
}

// round 7
// speedup vs baseline: 1.1457x; 1.1457x over previous
#include <cuda_runtime.h>
#include <cuda_bf16.h>
#include <cuda_fp16.h>
#include <math.h>
#include <stdint.h>

#define BB 4
#define TT 2048
#define CC 1024
#define HH 16
#define DD 64
#define MM (BB*TT)   // 8192

// ---------------------------------------------------------------------------
// Scratch (device globals; no allocation allowed)
// ---------------------------------------------------------------------------
__device__ float g_q[MM * CC];
__device__ float g_k[MM * CC];
__device__ float g_v[MM * CC];
__device__ __half g_xh[MM * CC];     // x hi (fp16)
__device__ __half g_xl[MM * CC];     // x lo (fp16)
__device__ __half g_ah[MM * CC];     // attn-out hi
__device__ __half g_al[MM * CC];     // attn-out lo
__device__ __half g_w16[4 * CC * CC];// weights, single fp16

// ---------------------------------------------------------------------------
__device__ __forceinline__ uint32_t smem_u32(const void* p) {
    uint32_t a;
    asm("{ .reg .u64 t; cvta.to.shared.u64 t, %1; cvt.u32.u64 %0, t; }"
        : "=r"(a) : "l"(p));
    return a;
}

__device__ __forceinline__ void cp16(uint32_t dst, const void* src) {
    asm volatile("cp.async.cg.shared.global [%0], [%1], 16;"
                 :: "r"(dst), "l"(src) : "memory");
}
#define CP_COMMIT() asm volatile("cp.async.commit_group;" ::: "memory")
#define CP_WAIT(n)  asm volatile("cp.async.wait_group %0;" :: "n"(n) : "memory")

__device__ __forceinline__ void mma_bf16(float* d, const uint32_t* a, const uint32_t* b) {
    asm volatile(
        "mma.sync.aligned.m16n8k16.row.col.f32.bf16.bf16.f32 "
        "{%0,%1,%2,%3}, {%4,%5,%6,%7}, {%8,%9}, {%0,%1,%2,%3};"
        : "+f"(d[0]), "+f"(d[1]), "+f"(d[2]), "+f"(d[3])
        : "r"(a[0]), "r"(a[1]), "r"(a[2]), "r"(a[3]), "r"(b[0]), "r"(b[1]));
}

__device__ __forceinline__ void mma_f16(float* d, const uint32_t* a, const uint32_t* b) {
    asm volatile(
        "mma.sync.aligned.m16n8k16.row.col.f32.f16.f16.f32 "
        "{%0,%1,%2,%3}, {%4,%5,%6,%7}, {%8,%9}, {%0,%1,%2,%3};"
        : "+f"(d[0]), "+f"(d[1]), "+f"(d[2]), "+f"(d[3])
        : "r"(a[0]), "r"(a[1]), "r"(a[2]), "r"(a[3]), "r"(b[0]), "r"(b[1]));
}

__device__ __forceinline__ void ldm_x4(uint32_t* r, uint32_t addr) {
    asm volatile("ldmatrix.sync.aligned.m8n8.x4.shared.b16 {%0,%1,%2,%3}, [%4];"
                 : "=r"(r[0]), "=r"(r[1]), "=r"(r[2]), "=r"(r[3]) : "r"(addr));
}
__device__ __forceinline__ void ldm_x2(uint32_t* r, uint32_t addr) {
    asm volatile("ldmatrix.sync.aligned.m8n8.x2.shared.b16 {%0,%1}, [%2];"
                 : "=r"(r[0]), "=r"(r[1]) : "r"(addr));
}

__device__ __forceinline__ uint32_t lds32(uint32_t addr) {
    uint32_t v;
    asm volatile("ld.shared.b32 %0, [%1];" : "=r"(v) : "r"(addr));
    return v;
}

__device__ __forceinline__ uint32_t pack_bf16x2(float lo, float hi) {
    uint32_t r;
    asm("cvt.rn.bf16x2.f32 %0, %1, %2;" : "=r"(r) : "f"(hi), "f"(lo));
    return r;
}

// ---------------------------------------------------------------------------
// Conversion kernels
// ---------------------------------------------------------------------------
// fp32 -> single fp16
__global__ void conv16_kernel(const float* __restrict__ in,
                              __half* __restrict__ out, int n4)
{
    int i = blockIdx.x * blockDim.x + threadIdx.x;
    if (i >= n4) return;
    float4 v = ((const float4*)in)[i];
    __half2* op = (__half2*)out;
    op[2 * i + 0] = __floats2half2_rn(v.x, v.y);
    op[2 * i + 1] = __floats2half2_rn(v.z, v.w);
}

// fp32 -> fp16 hi/lo split
__global__ void split16_kernel(const float* __restrict__ in,
                               __half* __restrict__ hi,
                               __half* __restrict__ lo, int n4)
{
    int i = blockIdx.x * blockDim.x + threadIdx.x;
    if (i >= n4) return;
    float4 v = ((const float4*)in)[i];
    __half h0 = __float2half_rn(v.x);
    __half h1 = __float2half_rn(v.y);
    __half h2 = __float2half_rn(v.z);
    __half h3 = __float2half_rn(v.w);
    __half l0 = __float2half_rn(v.x - __half2float(h0));
    __half l1 = __float2half_rn(v.y - __half2float(h1));
    __half l2 = __float2half_rn(v.z - __half2float(h2));
    __half l3 = __float2half_rn(v.w - __half2float(h3));
    __half2* hp = (__half2*)hi;
    __half2* lp = (__half2*)lo;
    hp[2 * i + 0] = __halves2half2(h0, h1);
    hp[2 * i + 1] = __halves2half2(h2, h3);
    lp[2 * i + 0] = __halves2half2(l0, l1);
    lp[2 * i + 1] = __halves2half2(l2, l3);
}

// ---------------------------------------------------------------------------
// Core GEMM tile: C[128,128] = A[M,K] x W[N,K]^T
// fp16 asymmetric 2-pass: A = Ah + Al (exact), W single fp16.
// BK=64, 3 tiles/stage (Ah, Al, B), 3-stage cp.async ring, ldmatrix.
// ---------------------------------------------------------------------------
#define ROWB 144u
#define TILEB (128u*ROWB)        // 18432
#define STAGEB (3u*TILEB)        // 55296
#define NSTAGE 3
#define NCHUNK (CC/64)           // 16

__device__ __forceinline__ void gemm_tile(
    const __half* __restrict__ Ah, const __half* __restrict__ Al,
    const __half* __restrict__ B,
    float* __restrict__ C, int m0, int n0, char* smem)
{
    const uint32_t sb = smem_u32(smem);
    const int tid  = threadIdx.x;
    const int lane = tid & 31;
    const int wid  = tid >> 5;
    const int wm   = wid >> 1;
    const int wn   = wid & 1;

    const __half* srcs[3] = {
        Ah + (size_t)m0 * CC, Al + (size_t)m0 * CC, B + (size_t)n0 * CC };

    // One stage = 3 tiles x 128 rows x 8 x 16B segments = 3072 segments
    auto issue_stage = [&](int chunk, int stage) {
        const int kc = chunk * 64;
        const uint32_t base = sb + (uint32_t)stage * STAGEB;
#pragma unroll
        for (int t = 0; t < 12; t++) {
            int lin  = tid + t * 256;        // 0..3071
            int tile = lin >> 10;            // 0..2
            int idx  = lin & 1023;
            int row  = idx >> 3;             // 0..127
            int seg  = idx & 7;              // 0..7
            uint32_t dst = base + (uint32_t)tile * TILEB + (uint32_t)row * ROWB + (uint32_t)seg * 16u;
            cp16(dst, srcs[tile] + (size_t)row * CC + kc + seg * 8);
        }
        CP_COMMIT();
    };

    float acc[2][8][4];
#pragma unroll
    for (int i = 0; i < 2; i++)
#pragma unroll
        for (int j = 0; j < 8; j++)
#pragma unroll
            for (int r = 0; r < 4; r++) acc[i][j][r] = 0.f;

    issue_stage(0, 0);
    issue_stage(1, 1);

    const uint32_t a_row  = (uint32_t)(lane & 15);
    const uint32_t a_koff = (uint32_t)(lane >> 4) * 16u;
    const uint32_t b_row  = (uint32_t)(lane & 7);
    const uint32_t b_koff = (uint32_t)((lane >> 3) & 1) * 16u;

    for (int c = 0; c < NCHUNK; c++) {
        const int stage = c % NSTAGE;
        CP_WAIT(1);
        __syncthreads();
        if (c + 2 < NCHUNK) issue_stage(c + 2, (c + 2) % NSTAGE);

        const uint32_t base  = sb + (uint32_t)stage * STAGEB;
        const uint32_t Aho   = base;
        const uint32_t Alo_o = base + TILEB;
        const uint32_t Bo    = base + 2u * TILEB;

#pragma unroll
        for (int kk = 0; kk < 4; kk++) {
            const uint32_t ko = (uint32_t)kk * 32u;
            uint32_t ah[2][4], al[2][4];
#pragma unroll
            for (int fi = 0; fi < 2; fi++) {
                uint32_t ra = (uint32_t)(wm * 32 + fi * 16) * ROWB + a_row * ROWB + ko + a_koff;
                ldm_x4(ah[fi], Aho + ra);
                ldm_x4(al[fi], Alo_o + ra);
            }
#pragma unroll
            for (int j = 0; j < 8; j++) {
                uint32_t rb = (uint32_t)(wn * 64 + j * 8) * ROWB + b_row * ROWB + ko + b_koff;
                uint32_t bf[2];
                ldm_x2(bf, Bo + rb);
#pragma unroll
                for (int fi = 0; fi < 2; fi++) {
                    mma_f16(acc[fi][j], ah[fi], bf);
                    mma_f16(acc[fi][j], al[fi], bf);
                }
            }
        }
    }

#pragma unroll
    for (int fi = 0; fi < 2; fi++) {
        int row0 = m0 + wm * 32 + fi * 16 + (lane >> 2);
#pragma unroll
        for (int j = 0; j < 8; j++) {
            int col = n0 + wn * 64 + j * 8 + (lane & 3) * 2;
            *(float2*)&C[(size_t)row0 * CC + col]       = make_float2(acc[fi][j][0], acc[fi][j][1]);
            *(float2*)&C[(size_t)(row0 + 8) * CC + col] = make_float2(acc[fi][j][2], acc[fi][j][3]);
        }
    }
}

// Fused QKV: grid.x in [0,24): wsel = x>>3, n0 = (x&7)*128
__global__ __launch_bounds__(256) void gemm_qkv(
    const __half* __restrict__ xh, const __half* __restrict__ xl,
    const __half* __restrict__ w16,
    float* __restrict__ q, float* __restrict__ k, float* __restrict__ v)
{
    extern __shared__ char smem[];
    const int wsel = blockIdx.x >> 3;
    const int n0 = (blockIdx.x & 7) * 128;
    const int m0 = blockIdx.y * 128;
    float* outs[3] = { q, k, v };
    gemm_tile(xh, xl, w16 + (size_t)wsel * CC * CC, outs[wsel], m0, n0, smem);
}

__global__ __launch_bounds__(256) void gemm_one(
    const __half* __restrict__ Ah, const __half* __restrict__ Al,
    const __half* __restrict__ B, float* __restrict__ C)
{
    extern __shared__ char smem[];
    gemm_tile(Ah, Al, B, C, blockIdx.y * 128, blockIdx.x * 128, smem);
}

// ---------------------------------------------------------------------------
// Tensor-core flash attention (causal), bf16 hi/lo 3-pass (unchanged math).
// Epilogue writes fp16 hi/lo planes feeding the WO GEMM.
// ---------------------------------------------------------------------------
#define AP 72
#define ATILE (64 * AP)

__global__ __launch_bounds__(128) void attn_tc()
{
    extern __shared__ __nv_bfloat16 ash[];
    __nv_bfloat16* Qh = ash;
    __nv_bfloat16* Ql = Qh + ATILE;
    __nv_bfloat16* Kh = Ql + ATILE;
    __nv_bfloat16* Kl = Kh + ATILE;
    __nv_bfloat16* Vh = Kl + ATILE;
    __nv_bfloat16* Vl = Vh + ATILE;
    const uint32_t sQh = smem_u32(Qh), sQl = smem_u32(Ql);
    const uint32_t sKh = smem_u32(Kh), sKl = smem_u32(Kl);
    const uint32_t sVh = smem_u32(Vh), sVl = smem_u32(Vl);

    const int tid  = threadIdx.x;
    const int lane = tid & 31;
    const int w    = tid >> 5;
    const int qtile = blockIdx.x;
    const int bh = blockIdx.y;
    const int b = bh / HH, h = bh % HH;
    const int q0 = qtile * 64;

    const float* qptr = g_q + (size_t)b * TT * CC + h * DD;
    const float* kptr = g_k + (size_t)b * TT * CC + h * DD;
    const float* vptr = g_v + (size_t)b * TT * CC + h * DD;

#pragma unroll
    for (int it = 0; it < 8; it++) {
        int lin = tid + it * 128;
        int row = lin >> 4;
        int c4  = (lin & 15) * 4;
        float4 v4 = *(const float4*)&qptr[(size_t)(q0 + row) * CC + c4];
        float f[4] = { v4.x * 0.125f, v4.y * 0.125f, v4.z * 0.125f, v4.w * 0.125f };
        __nv_bfloat16 hh[4], ll[4];
#pragma unroll
        for (int e = 0; e < 4; e++) {
            hh[e] = __float2bfloat16(f[e]);
            ll[e] = __float2bfloat16(f[e] - __bfloat162float(hh[e]));
        }
        *(__nv_bfloat162*)&Qh[row * AP + c4]     = __nv_bfloat162(hh[0], hh[1]);
        *(__nv_bfloat162*)&Qh[row * AP + c4 + 2] = __nv_bfloat162(hh[2], hh[3]);
        *(__nv_bfloat162*)&Ql[row * AP + c4]     = __nv_bfloat162(ll[0], ll[1]);
        *(__nv_bfloat162*)&Ql[row * AP + c4 + 2] = __nv_bfloat162(ll[2], ll[3]);
    }
    __syncthreads();

    uint32_t aqh[4][4], aql[4][4];
    {
        const uint32_t kb = (uint32_t)(lane & 3) * 4u;
        const uint32_t r0 = (uint32_t)(w * 16 + (lane >> 2)) * (AP * 2) + kb;
        const uint32_t r1 = r0 + 8u * (AP * 2);
#pragma unroll
        for (int s = 0; s < 4; s++) {
            uint32_t ko = (uint32_t)s * 32u;
            aqh[s][0] = lds32(sQh + r0 + ko);       aqh[s][1] = lds32(sQh + r1 + ko);
            aqh[s][2] = lds32(sQh + r0 + ko + 16u); aqh[s][3] = lds32(sQh + r1 + ko + 16u);
            aql[s][0] = lds32(sQl + r0 + ko);       aql[s][1] = lds32(sQl + r1 + ko);
            aql[s][2] = lds32(sQl + r0 + ko + 16u); aql[s][3] = lds32(sQl + r1 + ko + 16u);
        }
    }

    float m0r = -1e30f, m1r = -1e30f, l0r = 0.f, l1r = 0.f;
    float ofr[8][4];
#pragma unroll
    for (int j = 0; j < 8; j++)
#pragma unroll
        for (int r = 0; r < 4; r++) ofr[j][r] = 0.f;

    const int r0g = q0 + w * 16 + (lane >> 2);
    const int r1g = r0g + 8;

    const int nkt = qtile + 1;
    for (int kt = 0; kt < nkt; kt++) {
        const int k0 = kt * 64;
        __syncthreads();
#pragma unroll
        for (int it = 0; it < 8; it++) {
            int lin = tid + it * 128;
            int row = lin >> 4;
            int c4  = (lin & 15) * 4;
            float4 kv = *(const float4*)&kptr[(size_t)(k0 + row) * CC + c4];
            float kf[4] = { kv.x, kv.y, kv.z, kv.w };
            __nv_bfloat16 khh[4], kll[4];
#pragma unroll
            for (int e = 0; e < 4; e++) {
                khh[e] = __float2bfloat16(kf[e]);
                kll[e] = __float2bfloat16(kf[e] - __bfloat162float(khh[e]));
            }
            *(__nv_bfloat162*)&Kh[row * AP + c4]     = __nv_bfloat162(khh[0], khh[1]);
            *(__nv_bfloat162*)&Kh[row * AP + c4 + 2] = __nv_bfloat162(khh[2], khh[3]);
            *(__nv_bfloat162*)&Kl[row * AP + c4]     = __nv_bfloat162(kll[0], kll[1]);
            *(__nv_bfloat162*)&Kl[row * AP + c4 + 2] = __nv_bfloat162(kll[2], kll[3]);

            float4 vv = *(const float4*)&vptr[(size_t)(k0 + row) * CC + c4];
            float vf[4] = { vv.x, vv.y, vv.z, vv.w };
#pragma unroll
            for (int e = 0; e < 4; e++) {
                __nv_bfloat16 vh = __float2bfloat16(vf[e]);
                __nv_bfloat16 vl = __float2bfloat16(vf[e] - __bfloat162float(vh));
                Vh[(c4 + e) * AP + row] = vh;
                Vl[(c4 + e) * AP + row] = vl;
            }
        }
        __syncthreads();

        float sfr[8][4];
#pragma unroll
        for (int j = 0; j < 8; j++)
#pragma unroll
            for (int r = 0; r < 4; r++) sfr[j][r] = 0.f;

        const uint32_t kb = (uint32_t)(lane & 3) * 4u;
#pragma unroll
        for (int j = 0; j < 8; j++) {
            uint32_t nrow = (uint32_t)(j * 8 + (lane >> 2)) * (AP * 2) + kb;
#pragma unroll
            for (int s = 0; s < 4; s++) {
                uint32_t ko = (uint32_t)s * 32u;
                uint32_t bhf[2], blf[2];
                bhf[0] = lds32(sKh + nrow + ko); bhf[1] = lds32(sKh + nrow + ko + 16u);
                blf[0] = lds32(sKl + nrow + ko); blf[1] = lds32(sKl + nrow + ko + 16u);
                mma_bf16(sfr[j], aqh[s], bhf);
                mma_bf16(sfr[j], aqh[s], blf);
                mma_bf16(sfr[j], aql[s], bhf);
            }
        }

        if (kt == qtile) {
#pragma unroll
            for (int j = 0; j < 8; j++) {
                int cbase = k0 + j * 8 + 2 * (lane & 3);
                if (cbase > r0g)     sfr[j][0] = -1e30f;
                if (cbase + 1 > r0g) sfr[j][1] = -1e30f;
                if (cbase > r1g)     sfr[j][2] = -1e30f;
                if (cbase + 1 > r1g) sfr[j][3] = -1e30f;
            }
        }

        float mx0 = -1e30f, mx1 = -1e30f;
#pragma unroll
        for (int j = 0; j < 8; j++) {
            mx0 = fmaxf(mx0, fmaxf(sfr[j][0], sfr[j][1]));
            mx1 = fmaxf(mx1, fmaxf(sfr[j][2], sfr[j][3]));
        }
        mx0 = fmaxf(mx0, __shfl_xor_sync(0xffffffffu, mx0, 1));
        mx0 = fmaxf(mx0, __shfl_xor_sync(0xffffffffu, mx0, 2));
        mx1 = fmaxf(mx1, __shfl_xor_sync(0xffffffffu, mx1, 1));
        mx1 = fmaxf(mx1, __shfl_xor_sync(0xffffffffu, mx1, 2));

        float mn0 = fmaxf(m0r, mx0), mn1 = fmaxf(m1r, mx1);
        float corr0 = __expf(m0r - mn0), corr1 = __expf(m1r - mn1);
        m0r = mn0; m1r = mn1;

        float rs0 = 0.f, rs1 = 0.f;
#pragma unroll
        for (int j = 0; j < 8; j++) {
            sfr[j][0] = __expf(sfr[j][0] - mn0);
            sfr[j][1] = __expf(sfr[j][1] - mn0);
            sfr[j][2] = __expf(sfr[j][2] - mn1);
            sfr[j][3] = __expf(sfr[j][3] - mn1);
            rs0 += sfr[j][0] + sfr[j][1];
            rs1 += sfr[j][2] + sfr[j][3];
        }
        rs0 += __shfl_xor_sync(0xffffffffu, rs0, 1);
        rs0 += __shfl_xor_sync(0xffffffffu, rs0, 2);
        rs1 += __shfl_xor_sync(0xffffffffu, rs1, 1);
        rs1 += __shfl_xor_sync(0xffffffffu, rs1, 2);
        l0r = l0r * corr0 + rs0;
        l1r = l1r * corr1 + rs1;

#pragma unroll
        for (int j = 0; j < 8; j++) {
            ofr[j][0] *= corr0; ofr[j][1] *= corr0;
            ofr[j][2] *= corr1; ofr[j][3] *= corr1;
        }

        uint32_t pah[4][4], pal[4][4];
#pragma unroll
        for (int s = 0; s < 4; s++) {
            const int ja = 2 * s, jb = 2 * s + 1;
            float p[8] = { sfr[ja][0], sfr[ja][1], sfr[ja][2], sfr[ja][3],
                           sfr[jb][0], sfr[jb][1], sfr[jb][2], sfr[jb][3] };
            __nv_bfloat16 phh[8];
            float pl[8];
#pragma unroll
            for (int e = 0; e < 8; e++) {
                phh[e] = __float2bfloat16(p[e]);
                pl[e] = p[e] - __bfloat162float(phh[e]);
            }
            pah[s][0] = pack_bf16x2(__bfloat162float(phh[0]), __bfloat162float(phh[1]));
            pah[s][1] = pack_bf16x2(__bfloat162float(phh[2]), __bfloat162float(phh[3]));
            pah[s][2] = pack_bf16x2(__bfloat162float(phh[4]), __bfloat162float(phh[5]));
            pah[s][3] = pack_bf16x2(__bfloat162float(phh[6]), __bfloat162float(phh[7]));
            pal[s][0] = pack_bf16x2(pl[0], pl[1]);
            pal[s][1] = pack_bf16x2(pl[2], pl[3]);
            pal[s][2] = pack_bf16x2(pl[4], pl[5]);
            pal[s][3] = pack_bf16x2(pl[6], pl[7]);
        }

#pragma unroll
        for (int j = 0; j < 8; j++) {
            uint32_t drow = (uint32_t)(j * 8 + (lane >> 2)) * (AP * 2) + kb;
#pragma unroll
            for (int s = 0; s < 4; s++) {
                uint32_t ko = (uint32_t)s * 32u;
                uint32_t bvh[2], bvl[2];
                bvh[0] = lds32(sVh + drow + ko); bvh[1] = lds32(sVh + drow + ko + 16u);
                bvl[0] = lds32(sVl + drow + ko); bvl[1] = lds32(sVl + drow + ko + 16u);
                mma_bf16(ofr[j], pah[s], bvh);
                mma_bf16(ofr[j], pah[s], bvl);
                mma_bf16(ofr[j], pal[s], bvh);
            }
        }
    }

    // Epilogue: normalize, split to fp16 hi/lo planes for the WO GEMM
    float inv0 = 1.f / l0r, inv1 = 1.f / l1r;
    __half* ahp = g_ah + (size_t)b * TT * CC + h * DD;
    __half* alp = g_al + (size_t)b * TT * CC + h * DD;
#pragma unroll
    for (int j = 0; j < 8; j++) {
        int col = j * 8 + 2 * (lane & 3);
        float v0 = ofr[j][0] * inv0, v1 = ofr[j][1] * inv0;
        float v2 = ofr[j][2] * inv1, v3 = ofr[j][3] * inv1;
        __half h0 = __float2half_rn(v0), h1 = __float2half_rn(v1);
        __half h2 = __float2half_rn(v2), h3 = __float2half_rn(v3);
        *(__half2*)&ahp[(size_t)r0g * CC + col] = __halves2half2(h0, h1);
        *(__half2*)&alp[(size_t)r0g * CC + col] =
            __halves2half2(__float2half_rn(v0 - __half2float(h0)),
                           __float2half_rn(v1 - __half2float(h1)));
        *(__half2*)&ahp[(size_t)r1g * CC + col] = __halves2half2(h2, h3);
        *(__half2*)&alp[(size_t)r1g * CC + col] =
            __halves2half2(__float2half_rn(v2 - __half2float(h2)),
                           __float2half_rn(v3 - __half2float(h3)));
    }
}

// ---------------------------------------------------------------------------
extern "C" void kernel_launch(void* const* d_in, const int* in_sizes, int n_in,
                              void* d_out, int out_size)
{
    const float* x   = (const float*)d_in[0];
    const float* W_Q = (const float*)d_in[1];
    const float* W_K = (const float*)d_in[2];
    const float* W_V = (const float*)d_in[3];
    const float* W_O = (const float*)d_in[4];
    float* out = (float*)d_out;

    float *q, *k, *v;
    __half *xh, *xl, *ah, *al, *w16;
    cudaGetSymbolAddress((void**)&q,   g_q);
    cudaGetSymbolAddress((void**)&k,   g_k);
    cudaGetSymbolAddress((void**)&v,   g_v);
    cudaGetSymbolAddress((void**)&xh,  g_xh);
    cudaGetSymbolAddress((void**)&xl,  g_xl);
    cudaGetSymbolAddress((void**)&ah,  g_ah);
    cudaGetSymbolAddress((void**)&al,  g_al);
    cudaGetSymbolAddress((void**)&w16, g_w16);

    const int gemm_smem = NSTAGE * (int)STAGEB;   // 165888
    cudaFuncSetAttribute(gemm_qkv,
                         cudaFuncAttributeMaxDynamicSharedMemorySize, gemm_smem);
    cudaFuncSetAttribute(gemm_one,
                         cudaFuncAttributeMaxDynamicSharedMemorySize, gemm_smem);
    const int attn_smem = 6 * ATILE * (int)sizeof(__nv_bfloat16);
    cudaFuncSetAttribute(attn_tc,
                         cudaFuncAttributeMaxDynamicSharedMemorySize, attn_smem);

    {
        int n4 = MM * CC / 4;
        split16_kernel<<<(n4 + 255) / 256, 256>>>(x, xh, xl, n4);
        int w4 = CC * CC / 4;
        conv16_kernel<<<(w4 + 255) / 256, 256>>>(W_Q, w16 + 0 * CC * CC, w4);
        conv16_kernel<<<(w4 + 255) / 256, 256>>>(W_K, w16 + 1 * CC * CC, w4);
        conv16_kernel<<<(w4 + 255) / 256, 256>>>(W_V, w16 + 2 * CC * CC, w4);
        conv16_kernel<<<(w4 + 255) / 256, 256>>>(W_O, w16 + 3 * CC * CC, w4);
    }

    dim3 qkvgrid(24, MM / 128);   // (24, 64)
    gemm_qkv<<<qkvgrid, 256, gemm_smem>>>(xh, xl, w16, q, k, v);

    dim3 agrid(TT / 64, BB * HH);
    attn_tc<<<agrid, 128, attn_smem>>>();

    dim3 ogrid(CC / 128, MM / 128);
    gemm_one<<<ogrid, 256, gemm_smem>>>(ah, al, w16 + 3 * CC * CC, out);
}

// round 8
// speedup vs baseline: 1.2188x; 1.0638x over previous
#include <cuda_runtime.h>
#include <cuda_bf16.h>
#include <cuda_fp16.h>
#include <math.h>
#include <stdint.h>

#define BB 4
#define TT 2048
#define CC 1024
#define HH 16
#define DD 64
#define MM (BB*TT)   // 8192

// ---------------------------------------------------------------------------
// Scratch (device globals; no allocation allowed)
// ---------------------------------------------------------------------------
__device__ float g_q[MM * CC];
__device__ float g_k[MM * CC];
__device__ float g_v[MM * CC];
__device__ __half g_xh[MM * CC];
__device__ __half g_xl[MM * CC];
__device__ __half g_ah[MM * CC];
__device__ __half g_al[MM * CC];
__device__ __half g_w16[4 * CC * CC];

// ---------------------------------------------------------------------------
__device__ __forceinline__ uint32_t smem_u32(const void* p) {
    uint32_t a;
    asm("{ .reg .u64 t; cvta.to.shared.u64 t, %1; cvt.u32.u64 %0, t; }"
        : "=r"(a) : "l"(p));
    return a;
}

__device__ __forceinline__ void cp16(uint32_t dst, const void* src) {
    asm volatile("cp.async.cg.shared.global [%0], [%1], 16;"
                 :: "r"(dst), "l"(src) : "memory");
}
#define CP_COMMIT() asm volatile("cp.async.commit_group;" ::: "memory")
#define CP_WAIT(n)  asm volatile("cp.async.wait_group %0;" :: "n"(n) : "memory")

__device__ __forceinline__ void mma_bf16(float* d, const uint32_t* a, const uint32_t* b) {
    asm volatile(
        "mma.sync.aligned.m16n8k16.row.col.f32.bf16.bf16.f32 "
        "{%0,%1,%2,%3}, {%4,%5,%6,%7}, {%8,%9}, {%0,%1,%2,%3};"
        : "+f"(d[0]), "+f"(d[1]), "+f"(d[2]), "+f"(d[3])
        : "r"(a[0]), "r"(a[1]), "r"(a[2]), "r"(a[3]), "r"(b[0]), "r"(b[1]));
}

__device__ __forceinline__ void mma_f16(float* d, const uint32_t* a, const uint32_t* b) {
    asm volatile(
        "mma.sync.aligned.m16n8k16.row.col.f32.f16.f16.f32 "
        "{%0,%1,%2,%3}, {%4,%5,%6,%7}, {%8,%9}, {%0,%1,%2,%3};"
        : "+f"(d[0]), "+f"(d[1]), "+f"(d[2]), "+f"(d[3])
        : "r"(a[0]), "r"(a[1]), "r"(a[2]), "r"(a[3]), "r"(b[0]), "r"(b[1]));
}

__device__ __forceinline__ void ldm_x4(uint32_t* r, uint32_t addr) {
    asm volatile("ldmatrix.sync.aligned.m8n8.x4.shared.b16 {%0,%1,%2,%3}, [%4];"
                 : "=r"(r[0]), "=r"(r[1]), "=r"(r[2]), "=r"(r[3]) : "r"(addr));
}
__device__ __forceinline__ void ldm_x2(uint32_t* r, uint32_t addr) {
    asm volatile("ldmatrix.sync.aligned.m8n8.x2.shared.b16 {%0,%1}, [%2];"
                 : "=r"(r[0]), "=r"(r[1]) : "r"(addr));
}

__device__ __forceinline__ uint32_t lds32(uint32_t addr) {
    uint32_t v;
    asm volatile("ld.shared.b32 %0, [%1];" : "=r"(v) : "r"(addr));
    return v;
}

__device__ __forceinline__ uint32_t pack_bf16x2(float lo, float hi) {
    uint32_t r;
    asm("cvt.rn.bf16x2.f32 %0, %1, %2;" : "=r"(r) : "f"(hi), "f"(lo));
    return r;
}

// ---------------------------------------------------------------------------
// Conversion kernels
// ---------------------------------------------------------------------------
__global__ void conv16_kernel(const float* __restrict__ in,
                              __half* __restrict__ out, int n4)
{
    int i = blockIdx.x * blockDim.x + threadIdx.x;
    if (i >= n4) return;
    float4 v = ((const float4*)in)[i];
    __half2* op = (__half2*)out;
    op[2 * i + 0] = __floats2half2_rn(v.x, v.y);
    op[2 * i + 1] = __floats2half2_rn(v.z, v.w);
}

__global__ void split16_kernel(const float* __restrict__ in,
                               __half* __restrict__ hi,
                               __half* __restrict__ lo, int n4)
{
    int i = blockIdx.x * blockDim.x + threadIdx.x;
    if (i >= n4) return;
    float4 v = ((const float4*)in)[i];
    __half h0 = __float2half_rn(v.x);
    __half h1 = __float2half_rn(v.y);
    __half h2 = __float2half_rn(v.z);
    __half h3 = __float2half_rn(v.w);
    __half l0 = __float2half_rn(v.x - __half2float(h0));
    __half l1 = __float2half_rn(v.y - __half2float(h1));
    __half l2 = __float2half_rn(v.z - __half2float(h2));
    __half l3 = __float2half_rn(v.w - __half2float(h3));
    __half2* hp = (__half2*)hi;
    __half2* lp = (__half2*)lo;
    hp[2 * i + 0] = __halves2half2(h0, h1);
    hp[2 * i + 1] = __halves2half2(h2, h3);
    lp[2 * i + 0] = __halves2half2(l0, l1);
    lp[2 * i + 1] = __halves2half2(l2, l3);
}

// ---------------------------------------------------------------------------
// Core GEMM tile: C[128,128] = A[M,K] x W[N,K]^T
// fp16 asymmetric 2-pass: A = Ah + Al (exact), W single fp16.
// BK=64, 2-stage cp.async ring, 2 CTAs/SM for latency overlap.
// ---------------------------------------------------------------------------
#define ROWB 144u
#define TILEB (128u*ROWB)        // 18432
#define STAGEB (3u*TILEB)        // 55296
#define NSTAGE 2
#define NCHUNK (CC/64)           // 16

__device__ __forceinline__ void gemm_tile(
    const __half* __restrict__ Ah, const __half* __restrict__ Al,
    const __half* __restrict__ B,
    float* __restrict__ C, int m0, int n0, char* smem)
{
    const uint32_t sb = smem_u32(smem);
    const int tid  = threadIdx.x;
    const int lane = tid & 31;
    const int wid  = tid >> 5;
    const int wm   = wid >> 1;
    const int wn   = wid & 1;

    const __half* srcs[3] = {
        Ah + (size_t)m0 * CC, Al + (size_t)m0 * CC, B + (size_t)n0 * CC };

    auto issue_stage = [&](int chunk, int stage) {
        const int kc = chunk * 64;
        const uint32_t base = sb + (uint32_t)stage * STAGEB;
#pragma unroll
        for (int t = 0; t < 12; t++) {
            int lin  = tid + t * 256;        // 0..3071
            int tile = lin >> 10;            // 0..2
            int idx  = lin & 1023;
            int row  = idx >> 3;             // 0..127
            int seg  = idx & 7;              // 0..7
            uint32_t dst = base + (uint32_t)tile * TILEB + (uint32_t)row * ROWB + (uint32_t)seg * 16u;
            cp16(dst, srcs[tile] + (size_t)row * CC + kc + seg * 8);
        }
        CP_COMMIT();
    };

    float acc[2][8][4];
#pragma unroll
    for (int i = 0; i < 2; i++)
#pragma unroll
        for (int j = 0; j < 8; j++)
#pragma unroll
            for (int r = 0; r < 4; r++) acc[i][j][r] = 0.f;

    issue_stage(0, 0);

    const uint32_t a_row  = (uint32_t)(lane & 15);
    const uint32_t a_koff = (uint32_t)(lane >> 4) * 16u;
    const uint32_t b_row  = (uint32_t)(lane & 7);
    const uint32_t b_koff = (uint32_t)((lane >> 3) & 1) * 16u;

    for (int c = 0; c < NCHUNK; c++) {
        const int stage = c & 1;
        if (c + 1 < NCHUNK) { issue_stage(c + 1, stage ^ 1); CP_WAIT(1); }
        else                { CP_WAIT(0); }
        __syncthreads();

        const uint32_t base  = sb + (uint32_t)stage * STAGEB;
        const uint32_t Aho   = base;
        const uint32_t Alo_o = base + TILEB;
        const uint32_t Bo    = base + 2u * TILEB;

#pragma unroll
        for (int kk = 0; kk < 4; kk++) {
            const uint32_t ko = (uint32_t)kk * 32u;
            uint32_t ah[2][4], al[2][4];
#pragma unroll
            for (int fi = 0; fi < 2; fi++) {
                uint32_t ra = (uint32_t)(wm * 32 + fi * 16) * ROWB + a_row * ROWB + ko + a_koff;
                ldm_x4(ah[fi], Aho + ra);
                ldm_x4(al[fi], Alo_o + ra);
            }
#pragma unroll
            for (int j = 0; j < 8; j++) {
                uint32_t rb = (uint32_t)(wn * 64 + j * 8) * ROWB + b_row * ROWB + ko + b_koff;
                uint32_t bf[2];
                ldm_x2(bf, Bo + rb);
#pragma unroll
                for (int fi = 0; fi < 2; fi++) {
                    mma_f16(acc[fi][j], ah[fi], bf);
                    mma_f16(acc[fi][j], al[fi], bf);
                }
            }
        }
        __syncthreads();
    }

#pragma unroll
    for (int fi = 0; fi < 2; fi++) {
        int row0 = m0 + wm * 32 + fi * 16 + (lane >> 2);
#pragma unroll
        for (int j = 0; j < 8; j++) {
            int col = n0 + wn * 64 + j * 8 + (lane & 3) * 2;
            *(float2*)&C[(size_t)row0 * CC + col]       = make_float2(acc[fi][j][0], acc[fi][j][1]);
            *(float2*)&C[(size_t)(row0 + 8) * CC + col] = make_float2(acc[fi][j][2], acc[fi][j][3]);
        }
    }
}

// Fused QKV: grid.x in [0,24): wsel = x>>3, n0 = (x&7)*128
__global__ __launch_bounds__(256, 2) void gemm_qkv(
    const __half* __restrict__ xh, const __half* __restrict__ xl,
    const __half* __restrict__ w16,
    float* __restrict__ q, float* __restrict__ k, float* __restrict__ v)
{
    extern __shared__ char smem[];
    const int wsel = blockIdx.x >> 3;
    const int n0 = (blockIdx.x & 7) * 128;
    const int m0 = blockIdx.y * 128;
    float* outs[3] = { q, k, v };
    gemm_tile(xh, xl, w16 + (size_t)wsel * CC * CC, outs[wsel], m0, n0, smem);
}

__global__ __launch_bounds__(256, 2) void gemm_one(
    const __half* __restrict__ Ah, const __half* __restrict__ Al,
    const __half* __restrict__ B, float* __restrict__ C)
{
    extern __shared__ char smem[];
    gemm_tile(Ah, Al, B, C, blockIdx.y * 128, blockIdx.x * 128, smem);
}

// ---------------------------------------------------------------------------
// Tensor-core flash attention (causal), bf16 hi/lo 3-pass (unchanged math).
// Epilogue writes fp16 hi/lo planes feeding the WO GEMM.
// ---------------------------------------------------------------------------
#define AP 72
#define ATILE (64 * AP)

__global__ __launch_bounds__(128) void attn_tc()
{
    extern __shared__ __nv_bfloat16 ash[];
    __nv_bfloat16* Qh = ash;
    __nv_bfloat16* Ql = Qh + ATILE;
    __nv_bfloat16* Kh = Ql + ATILE;
    __nv_bfloat16* Kl = Kh + ATILE;
    __nv_bfloat16* Vh = Kl + ATILE;
    __nv_bfloat16* Vl = Vh + ATILE;
    const uint32_t sQh = smem_u32(Qh), sQl = smem_u32(Ql);
    const uint32_t sKh = smem_u32(Kh), sKl = smem_u32(Kl);
    const uint32_t sVh = smem_u32(Vh), sVl = smem_u32(Vl);

    const int tid  = threadIdx.x;
    const int lane = tid & 31;
    const int w    = tid >> 5;
    const int qtile = blockIdx.x;
    const int bh = blockIdx.y;
    const int b = bh / HH, h = bh % HH;
    const int q0 = qtile * 64;

    const float* qptr = g_q + (size_t)b * TT * CC + h * DD;
    const float* kptr = g_k + (size_t)b * TT * CC + h * DD;
    const float* vptr = g_v + (size_t)b * TT * CC + h * DD;

#pragma unroll
    for (int it = 0; it < 8; it++) {
        int lin = tid + it * 128;
        int row = lin >> 4;
        int c4  = (lin & 15) * 4;
        float4 v4 = *(const float4*)&qptr[(size_t)(q0 + row) * CC + c4];
        float f[4] = { v4.x * 0.125f, v4.y * 0.125f, v4.z * 0.125f, v4.w * 0.125f };
        __nv_bfloat16 hh[4], ll[4];
#pragma unroll
        for (int e = 0; e < 4; e++) {
            hh[e] = __float2bfloat16(f[e]);
            ll[e] = __float2bfloat16(f[e] - __bfloat162float(hh[e]));
        }
        *(__nv_bfloat162*)&Qh[row * AP + c4]     = __nv_bfloat162(hh[0], hh[1]);
        *(__nv_bfloat162*)&Qh[row * AP + c4 + 2] = __nv_bfloat162(hh[2], hh[3]);
        *(__nv_bfloat162*)&Ql[row * AP + c4]     = __nv_bfloat162(ll[0], ll[1]);
        *(__nv_bfloat162*)&Ql[row * AP + c4 + 2] = __nv_bfloat162(ll[2], ll[3]);
    }
    __syncthreads();

    uint32_t aqh[4][4], aql[4][4];
    {
        const uint32_t kb = (uint32_t)(lane & 3) * 4u;
        const uint32_t r0 = (uint32_t)(w * 16 + (lane >> 2)) * (AP * 2) + kb;
        const uint32_t r1 = r0 + 8u * (AP * 2);
#pragma unroll
        for (int s = 0; s < 4; s++) {
            uint32_t ko = (uint32_t)s * 32u;
            aqh[s][0] = lds32(sQh + r0 + ko);       aqh[s][1] = lds32(sQh + r1 + ko);
            aqh[s][2] = lds32(sQh + r0 + ko + 16u); aqh[s][3] = lds32(sQh + r1 + ko + 16u);
            aql[s][0] = lds32(sQl + r0 + ko);       aql[s][1] = lds32(sQl + r1 + ko);
            aql[s][2] = lds32(sQl + r0 + ko + 16u); aql[s][3] = lds32(sQl + r1 + ko + 16u);
        }
    }

    float m0r = -1e30f, m1r = -1e30f, l0r = 0.f, l1r = 0.f;
    float ofr[8][4];
#pragma unroll
    for (int j = 0; j < 8; j++)
#pragma unroll
        for (int r = 0; r < 4; r++) ofr[j][r] = 0.f;

    const int r0g = q0 + w * 16 + (lane >> 2);
    const int r1g = r0g + 8;

    const int nkt = qtile + 1;
    for (int kt = 0; kt < nkt; kt++) {
        const int k0 = kt * 64;
        __syncthreads();
#pragma unroll
        for (int it = 0; it < 8; it++) {
            int lin = tid + it * 128;
            int row = lin >> 4;
            int c4  = (lin & 15) * 4;
            float4 kv = *(const float4*)&kptr[(size_t)(k0 + row) * CC + c4];
            float kf[4] = { kv.x, kv.y, kv.z, kv.w };
            __nv_bfloat16 khh[4], kll[4];
#pragma unroll
            for (int e = 0; e < 4; e++) {
                khh[e] = __float2bfloat16(kf[e]);
                kll[e] = __float2bfloat16(kf[e] - __bfloat162float(khh[e]));
            }
            *(__nv_bfloat162*)&Kh[row * AP + c4]     = __nv_bfloat162(khh[0], khh[1]);
            *(__nv_bfloat162*)&Kh[row * AP + c4 + 2] = __nv_bfloat162(khh[2], khh[3]);
            *(__nv_bfloat162*)&Kl[row * AP + c4]     = __nv_bfloat162(kll[0], kll[1]);
            *(__nv_bfloat162*)&Kl[row * AP + c4 + 2] = __nv_bfloat162(kll[2], kll[3]);

            float4 vv = *(const float4*)&vptr[(size_t)(k0 + row) * CC + c4];
            float vf[4] = { vv.x, vv.y, vv.z, vv.w };
#pragma unroll
            for (int e = 0; e < 4; e++) {
                __nv_bfloat16 vh = __float2bfloat16(vf[e]);
                __nv_bfloat16 vl = __float2bfloat16(vf[e] - __bfloat162float(vh));
                Vh[(c4 + e) * AP + row] = vh;
                Vl[(c4 + e) * AP + row] = vl;
            }
        }
        __syncthreads();

        float sfr[8][4];
#pragma unroll
        for (int j = 0; j < 8; j++)
#pragma unroll
            for (int r = 0; r < 4; r++) sfr[j][r] = 0.f;

        const uint32_t kb = (uint32_t)(lane & 3) * 4u;
#pragma unroll
        for (int j = 0; j < 8; j++) {
            uint32_t nrow = (uint32_t)(j * 8 + (lane >> 2)) * (AP * 2) + kb;
#pragma unroll
            for (int s = 0; s < 4; s++) {
                uint32_t ko = (uint32_t)s * 32u;
                uint32_t bhf[2], blf[2];
                bhf[0] = lds32(sKh + nrow + ko); bhf[1] = lds32(sKh + nrow + ko + 16u);
                blf[0] = lds32(sKl + nrow + ko); blf[1] = lds32(sKl + nrow + ko + 16u);
                mma_bf16(sfr[j], aqh[s], bhf);
                mma_bf16(sfr[j], aqh[s], blf);
                mma_bf16(sfr[j], aql[s], bhf);
            }
        }

        if (kt == qtile) {
#pragma unroll
            for (int j = 0; j < 8; j++) {
                int cbase = k0 + j * 8 + 2 * (lane & 3);
                if (cbase > r0g)     sfr[j][0] = -1e30f;
                if (cbase + 1 > r0g) sfr[j][1] = -1e30f;
                if (cbase > r1g)     sfr[j][2] = -1e30f;
                if (cbase + 1 > r1g) sfr[j][3] = -1e30f;
            }
        }

        float mx0 = -1e30f, mx1 = -1e30f;
#pragma unroll
        for (int j = 0; j < 8; j++) {
            mx0 = fmaxf(mx0, fmaxf(sfr[j][0], sfr[j][1]));
            mx1 = fmaxf(mx1, fmaxf(sfr[j][2], sfr[j][3]));
        }
        mx0 = fmaxf(mx0, __shfl_xor_sync(0xffffffffu, mx0, 1));
        mx0 = fmaxf(mx0, __shfl_xor_sync(0xffffffffu, mx0, 2));
        mx1 = fmaxf(mx1, __shfl_xor_sync(0xffffffffu, mx1, 1));
        mx1 = fmaxf(mx1, __shfl_xor_sync(0xffffffffu, mx1, 2));

        float mn0 = fmaxf(m0r, mx0), mn1 = fmaxf(m1r, mx1);
        float corr0 = __expf(m0r - mn0), corr1 = __expf(m1r - mn1);
        m0r = mn0; m1r = mn1;

        float rs0 = 0.f, rs1 = 0.f;
#pragma unroll
        for (int j = 0; j < 8; j++) {
            sfr[j][0] = __expf(sfr[j][0] - mn0);
            sfr[j][1] = __expf(sfr[j][1] - mn0);
            sfr[j][2] = __expf(sfr[j][2] - mn1);
            sfr[j][3] = __expf(sfr[j][3] - mn1);
            rs0 += sfr[j][0] + sfr[j][1];
            rs1 += sfr[j][2] + sfr[j][3];
        }
        rs0 += __shfl_xor_sync(0xffffffffu, rs0, 1);
        rs0 += __shfl_xor_sync(0xffffffffu, rs0, 2);
        rs1 += __shfl_xor_sync(0xffffffffu, rs1, 1);
        rs1 += __shfl_xor_sync(0xffffffffu, rs1, 2);
        l0r = l0r * corr0 + rs0;
        l1r = l1r * corr1 + rs1;

#pragma unroll
        for (int j = 0; j < 8; j++) {
            ofr[j][0] *= corr0; ofr[j][1] *= corr0;
            ofr[j][2] *= corr1; ofr[j][3] *= corr1;
        }

        uint32_t pah[4][4], pal[4][4];
#pragma unroll
        for (int s = 0; s < 4; s++) {
            const int ja = 2 * s, jb = 2 * s + 1;
            float p[8] = { sfr[ja][0], sfr[ja][1], sfr[ja][2], sfr[ja][3],
                           sfr[jb][0], sfr[jb][1], sfr[jb][2], sfr[jb][3] };
            __nv_bfloat16 phh[8];
            float pl[8];
#pragma unroll
            for (int e = 0; e < 8; e++) {
                phh[e] = __float2bfloat16(p[e]);
                pl[e] = p[e] - __bfloat162float(phh[e]);
            }
            pah[s][0] = pack_bf16x2(__bfloat162float(phh[0]), __bfloat162float(phh[1]));
            pah[s][1] = pack_bf16x2(__bfloat162float(phh[2]), __bfloat162float(phh[3]));
            pah[s][2] = pack_bf16x2(__bfloat162float(phh[4]), __bfloat162float(phh[5]));
            pah[s][3] = pack_bf16x2(__bfloat162float(phh[6]), __bfloat162float(phh[7]));
            pal[s][0] = pack_bf16x2(pl[0], pl[1]);
            pal[s][1] = pack_bf16x2(pl[2], pl[3]);
            pal[s][2] = pack_bf16x2(pl[4], pl[5]);
            pal[s][3] = pack_bf16x2(pl[6], pl[7]);
        }

#pragma unroll
        for (int j = 0; j < 8; j++) {
            uint32_t drow = (uint32_t)(j * 8 + (lane >> 2)) * (AP * 2) + kb;
#pragma unroll
            for (int s = 0; s < 4; s++) {
                uint32_t ko = (uint32_t)s * 32u;
                uint32_t bvh[2], bvl[2];
                bvh[0] = lds32(sVh + drow + ko); bvh[1] = lds32(sVh + drow + ko + 16u);
                bvl[0] = lds32(sVl + drow + ko); bvl[1] = lds32(sVl + drow + ko + 16u);
                mma_bf16(ofr[j], pah[s], bvh);
                mma_bf16(ofr[j], pah[s], bvl);
                mma_bf16(ofr[j], pal[s], bvh);
            }
        }
    }

    float inv0 = 1.f / l0r, inv1 = 1.f / l1r;
    __half* ahp = g_ah + (size_t)b * TT * CC + h * DD;
    __half* alp = g_al + (size_t)b * TT * CC + h * DD;
#pragma unroll
    for (int j = 0; j < 8; j++) {
        int col = j * 8 + 2 * (lane & 3);
        float v0 = ofr[j][0] * inv0, v1 = ofr[j][1] * inv0;
        float v2 = ofr[j][2] * inv1, v3 = ofr[j][3] * inv1;
        __half h0 = __float2half_rn(v0), h1 = __float2half_rn(v1);
        __half h2 = __float2half_rn(v2), h3 = __float2half_rn(v3);
        *(__half2*)&ahp[(size_t)r0g * CC + col] = __halves2half2(h0, h1);
        *(__half2*)&alp[(size_t)r0g * CC + col] =
            __halves2half2(__float2half_rn(v0 - __half2float(h0)),
                           __float2half_rn(v1 - __half2float(h1)));
        *(__half2*)&ahp[(size_t)r1g * CC + col] = __halves2half2(h2, h3);
        *(__half2*)&alp[(size_t)r1g * CC + col] =
            __halves2half2(__float2half_rn(v2 - __half2float(h2)),
                           __float2half_rn(v3 - __half2float(h3)));
    }
}

// ---------------------------------------------------------------------------
extern "C" void kernel_launch(void* const* d_in, const int* in_sizes, int n_in,
                              void* d_out, int out_size)
{
    const float* x   = (const float*)d_in[0];
    const float* W_Q = (const float*)d_in[1];
    const float* W_K = (const float*)d_in[2];
    const float* W_V = (const float*)d_in[3];
    const float* W_O = (const float*)d_in[4];
    float* out = (float*)d_out;

    float *q, *k, *v;
    __half *xh, *xl, *ah, *al, *w16;
    cudaGetSymbolAddress((void**)&q,   g_q);
    cudaGetSymbolAddress((void**)&k,   g_k);
    cudaGetSymbolAddress((void**)&v,   g_v);
    cudaGetSymbolAddress((void**)&xh,  g_xh);
    cudaGetSymbolAddress((void**)&xl,  g_xl);
    cudaGetSymbolAddress((void**)&ah,  g_ah);
    cudaGetSymbolAddress((void**)&al,  g_al);
    cudaGetSymbolAddress((void**)&w16, g_w16);

    const int gemm_smem = NSTAGE * (int)STAGEB;   // 110592 -> 2 CTAs/SM
    cudaFuncSetAttribute(gemm_qkv,
                         cudaFuncAttributeMaxDynamicSharedMemorySize, gemm_smem);
    cudaFuncSetAttribute(gemm_one,
                         cudaFuncAttributeMaxDynamicSharedMemorySize, gemm_smem);
    const int attn_smem = 6 * ATILE * (int)sizeof(__nv_bfloat16);
    cudaFuncSetAttribute(attn_tc,
                         cudaFuncAttributeMaxDynamicSharedMemorySize, attn_smem);

    {
        int n4 = MM * CC / 4;
        split16_kernel<<<(n4 + 255) / 256, 256>>>(x, xh, xl, n4);
        int w4 = CC * CC / 4;
        conv16_kernel<<<(w4 + 255) / 256, 256>>>(W_Q, w16 + 0 * CC * CC, w4);
        conv16_kernel<<<(w4 + 255) / 256, 256>>>(W_K, w16 + 1 * CC * CC, w4);
        conv16_kernel<<<(w4 + 255) / 256, 256>>>(W_V, w16 + 2 * CC * CC, w4);
        conv16_kernel<<<(w4 + 255) / 256, 256>>>(W_O, w16 + 3 * CC * CC, w4);
    }

    dim3 qkvgrid(24, MM / 128);   // (24, 64)
    gemm_qkv<<<qkvgrid, 256, gemm_smem>>>(xh, xl, w16, q, k, v);

    dim3 agrid(TT / 64, BB * HH);
    attn_tc<<<agrid, 128, attn_smem>>>();

    dim3 ogrid(CC / 128, MM / 128);
    gemm_one<<<ogrid, 256, gemm_smem>>>(ah, al, w16 + 3 * CC * CC, out);
}

// round 9
// speedup vs baseline: 1.6117x; 1.3224x over previous
#include <cuda_runtime.h>
#include <cuda_bf16.h>
#include <cuda_fp16.h>
#include <math.h>
#include <stdint.h>

#define BB 4
#define TT 2048
#define CC 1024
#define HH 16
#define DD 64
#define MM (BB*TT)   // 8192

// ---------------------------------------------------------------------------
// Scratch (device globals; no allocation allowed)
// ---------------------------------------------------------------------------
__device__ float g_q[MM * CC];
__device__ float g_k[MM * CC];
__device__ float g_v[MM * CC];
__device__ __half g_xh[MM * CC];
__device__ __half g_xl[MM * CC];
__device__ __half g_ah[MM * CC];
__device__ __half g_al[MM * CC];
__device__ __half g_w16[4 * CC * CC];

// ---------------------------------------------------------------------------
__device__ __forceinline__ uint32_t smem_u32(const void* p) {
    uint32_t a;
    asm("{ .reg .u64 t; cvta.to.shared.u64 t, %1; cvt.u32.u64 %0, t; }"
        : "=r"(a) : "l"(p));
    return a;
}

__device__ __forceinline__ void cp16(uint32_t dst, const void* src) {
    asm volatile("cp.async.cg.shared.global [%0], [%1], 16;"
                 :: "r"(dst), "l"(src) : "memory");
}
#define CP_COMMIT() asm volatile("cp.async.commit_group;" ::: "memory")
#define CP_WAIT(n)  asm volatile("cp.async.wait_group %0;" :: "n"(n) : "memory")

__device__ __forceinline__ void mma_f16(float* d, const uint32_t* a, const uint32_t* b) {
    asm volatile(
        "mma.sync.aligned.m16n8k16.row.col.f32.f16.f16.f32 "
        "{%0,%1,%2,%3}, {%4,%5,%6,%7}, {%8,%9}, {%0,%1,%2,%3};"
        : "+f"(d[0]), "+f"(d[1]), "+f"(d[2]), "+f"(d[3])
        : "r"(a[0]), "r"(a[1]), "r"(a[2]), "r"(a[3]), "r"(b[0]), "r"(b[1]));
}

__device__ __forceinline__ void ldm_x4(uint32_t* r, uint32_t addr) {
    asm volatile("ldmatrix.sync.aligned.m8n8.x4.shared.b16 {%0,%1,%2,%3}, [%4];"
                 : "=r"(r[0]), "=r"(r[1]), "=r"(r[2]), "=r"(r[3]) : "r"(addr));
}
__device__ __forceinline__ void ldm_x2(uint32_t* r, uint32_t addr) {
    asm volatile("ldmatrix.sync.aligned.m8n8.x2.shared.b16 {%0,%1}, [%2];"
                 : "=r"(r[0]), "=r"(r[1]) : "r"(addr));
}

__device__ __forceinline__ uint32_t lds32(uint32_t addr) {
    uint32_t v;
    asm volatile("ld.shared.b32 %0, [%1];" : "=r"(v) : "r"(addr));
    return v;
}

__device__ __forceinline__ uint32_t pack_f16x2(float lo, float hi) {
    __half2 hv = __floats2half2_rn(lo, hi);
    return *(uint32_t*)&hv;
}

// ---------------------------------------------------------------------------
// Conversion kernels
// ---------------------------------------------------------------------------
// Fused: all 4 weights -> fp16 in one launch (blockIdx.y selects weight)
__global__ void conv16x4_kernel(const float* __restrict__ w0,
                                const float* __restrict__ w1,
                                const float* __restrict__ w2,
                                const float* __restrict__ w3,
                                __half* __restrict__ out, int n4)
{
    int i = blockIdx.x * blockDim.x + threadIdx.x;
    if (i >= n4) return;
    const float* src = (blockIdx.y == 0) ? w0 : (blockIdx.y == 1) ? w1
                     : (blockIdx.y == 2) ? w2 : w3;
    float4 v = ((const float4*)src)[i];
    __half2* op = (__half2*)(out + (size_t)blockIdx.y * CC * CC);
    op[2 * i + 0] = __floats2half2_rn(v.x, v.y);
    op[2 * i + 1] = __floats2half2_rn(v.z, v.w);
}

__global__ void split16_kernel(const float* __restrict__ in,
                               __half* __restrict__ hi,
                               __half* __restrict__ lo, int n4)
{
    int i = blockIdx.x * blockDim.x + threadIdx.x;
    if (i >= n4) return;
    float4 v = ((const float4*)in)[i];
    __half h0 = __float2half_rn(v.x);
    __half h1 = __float2half_rn(v.y);
    __half h2 = __float2half_rn(v.z);
    __half h3 = __float2half_rn(v.w);
    __half l0 = __float2half_rn(v.x - __half2float(h0));
    __half l1 = __float2half_rn(v.y - __half2float(h1));
    __half l2 = __float2half_rn(v.z - __half2float(h2));
    __half l3 = __float2half_rn(v.w - __half2float(h3));
    __half2* hp = (__half2*)hi;
    __half2* lp = (__half2*)lo;
    hp[2 * i + 0] = __halves2half2(h0, h1);
    hp[2 * i + 1] = __halves2half2(h2, h3);
    lp[2 * i + 0] = __halves2half2(l0, l1);
    lp[2 * i + 1] = __halves2half2(l2, l3);
}

// ---------------------------------------------------------------------------
// Core GEMM tile: C[128,128] = A[M,K] x W[N,K]^T  (fp16 asymmetric 2-pass)
// BK=64, 2-stage cp.async ring, 2 CTAs/SM. (Unchanged from round 8.)
// ---------------------------------------------------------------------------
#define ROWB 144u
#define TILEB (128u*ROWB)        // 18432
#define STAGEB (3u*TILEB)        // 55296
#define NSTAGE 2
#define NCHUNK (CC/64)           // 16

__device__ __forceinline__ void gemm_tile(
    const __half* __restrict__ Ah, const __half* __restrict__ Al,
    const __half* __restrict__ B,
    float* __restrict__ C, int m0, int n0, char* smem)
{
    const uint32_t sb = smem_u32(smem);
    const int tid  = threadIdx.x;
    const int lane = tid & 31;
    const int wid  = tid >> 5;
    const int wm   = wid >> 1;
    const int wn   = wid & 1;

    const __half* srcs[3] = {
        Ah + (size_t)m0 * CC, Al + (size_t)m0 * CC, B + (size_t)n0 * CC };

    auto issue_stage = [&](int chunk, int stage) {
        const int kc = chunk * 64;
        const uint32_t base = sb + (uint32_t)stage * STAGEB;
#pragma unroll
        for (int t = 0; t < 12; t++) {
            int lin  = tid + t * 256;
            int tile = lin >> 10;
            int idx  = lin & 1023;
            int row  = idx >> 3;
            int seg  = idx & 7;
            uint32_t dst = base + (uint32_t)tile * TILEB + (uint32_t)row * ROWB + (uint32_t)seg * 16u;
            cp16(dst, srcs[tile] + (size_t)row * CC + kc + seg * 8);
        }
        CP_COMMIT();
    };

    float acc[2][8][4];
#pragma unroll
    for (int i = 0; i < 2; i++)
#pragma unroll
        for (int j = 0; j < 8; j++)
#pragma unroll
            for (int r = 0; r < 4; r++) acc[i][j][r] = 0.f;

    issue_stage(0, 0);

    const uint32_t a_row  = (uint32_t)(lane & 15);
    const uint32_t a_koff = (uint32_t)(lane >> 4) * 16u;
    const uint32_t b_row  = (uint32_t)(lane & 7);
    const uint32_t b_koff = (uint32_t)((lane >> 3) & 1) * 16u;

    for (int c = 0; c < NCHUNK; c++) {
        const int stage = c & 1;
        if (c + 1 < NCHUNK) { issue_stage(c + 1, stage ^ 1); CP_WAIT(1); }
        else                { CP_WAIT(0); }
        __syncthreads();

        const uint32_t base  = sb + (uint32_t)stage * STAGEB;
        const uint32_t Aho   = base;
        const uint32_t Alo_o = base + TILEB;
        const uint32_t Bo    = base + 2u * TILEB;

#pragma unroll
        for (int kk = 0; kk < 4; kk++) {
            const uint32_t ko = (uint32_t)kk * 32u;
            uint32_t ah[2][4], al[2][4];
#pragma unroll
            for (int fi = 0; fi < 2; fi++) {
                uint32_t ra = (uint32_t)(wm * 32 + fi * 16) * ROWB + a_row * ROWB + ko + a_koff;
                ldm_x4(ah[fi], Aho + ra);
                ldm_x4(al[fi], Alo_o + ra);
            }
#pragma unroll
            for (int j = 0; j < 8; j++) {
                uint32_t rb = (uint32_t)(wn * 64 + j * 8) * ROWB + b_row * ROWB + ko + b_koff;
                uint32_t bf[2];
                ldm_x2(bf, Bo + rb);
#pragma unroll
                for (int fi = 0; fi < 2; fi++) {
                    mma_f16(acc[fi][j], ah[fi], bf);
                    mma_f16(acc[fi][j], al[fi], bf);
                }
            }
        }
        __syncthreads();
    }

#pragma unroll
    for (int fi = 0; fi < 2; fi++) {
        int row0 = m0 + wm * 32 + fi * 16 + (lane >> 2);
#pragma unroll
        for (int j = 0; j < 8; j++) {
            int col = n0 + wn * 64 + j * 8 + (lane & 3) * 2;
            *(float2*)&C[(size_t)row0 * CC + col]       = make_float2(acc[fi][j][0], acc[fi][j][1]);
            *(float2*)&C[(size_t)(row0 + 8) * CC + col] = make_float2(acc[fi][j][2], acc[fi][j][3]);
        }
    }
}

__global__ __launch_bounds__(256, 2) void gemm_qkv(
    const __half* __restrict__ xh, const __half* __restrict__ xl,
    const __half* __restrict__ w16,
    float* __restrict__ q, float* __restrict__ k, float* __restrict__ v)
{
    extern __shared__ char smem[];
    const int wsel = blockIdx.x >> 3;
    const int n0 = (blockIdx.x & 7) * 128;
    const int m0 = blockIdx.y * 128;
    float* outs[3] = { q, k, v };
    gemm_tile(xh, xl, w16 + (size_t)wsel * CC * CC, outs[wsel], m0, n0, smem);
}

__global__ __launch_bounds__(256, 2) void gemm_one(
    const __half* __restrict__ Ah, const __half* __restrict__ Al,
    const __half* __restrict__ B, float* __restrict__ C)
{
    extern __shared__ char smem[];
    gemm_tile(Ah, Al, B, C, blockIdx.y * 128, blockIdx.x * 128, smem);
}

// ---------------------------------------------------------------------------
// Tensor-core flash attention (causal), fp16 asymmetric 2-pass:
//   S = (Qh+Ql) * K^T       (Q hi/lo fp16, K single fp16)
//   O = (Ph+Pl) * V         (P hi/lo fp16, V single fp16, transposed)
// fp32 softmax. SMEM: Qh, Ql, Kf, Vf — 4 x 64 x 72 fp16 = 36 KB.
// ---------------------------------------------------------------------------
#define AP 72
#define ATILE (64 * AP)

__global__ __launch_bounds__(128) void attn_tc()
{
    extern __shared__ __half ash[];
    __half* Qh = ash;
    __half* Ql = Qh + ATILE;
    __half* Kf = Ql + ATILE;
    __half* Vf = Kf + ATILE;
    const uint32_t sQh = smem_u32(Qh), sQl = smem_u32(Ql);
    const uint32_t sKf = smem_u32(Kf), sVf = smem_u32(Vf);

    const int tid  = threadIdx.x;
    const int lane = tid & 31;
    const int w    = tid >> 5;
    const int qtile = blockIdx.x;
    const int bh = blockIdx.y;
    const int b = bh / HH, h = bh % HH;
    const int q0 = qtile * 64;

    const float* qptr = g_q + (size_t)b * TT * CC + h * DD;
    const float* kptr = g_k + (size_t)b * TT * CC + h * DD;
    const float* vptr = g_v + (size_t)b * TT * CC + h * DD;

    // ---- load Q (scaled 1/8), split fp16 hi/lo ----
#pragma unroll
    for (int it = 0; it < 8; it++) {
        int lin = tid + it * 128;
        int row = lin >> 4;
        int c4  = (lin & 15) * 4;
        float4 v4 = *(const float4*)&qptr[(size_t)(q0 + row) * CC + c4];
        float f[4] = { v4.x * 0.125f, v4.y * 0.125f, v4.z * 0.125f, v4.w * 0.125f };
        __half hh[4], ll[4];
#pragma unroll
        for (int e = 0; e < 4; e++) {
            hh[e] = __float2half_rn(f[e]);
            ll[e] = __float2half_rn(f[e] - __half2float(hh[e]));
        }
        *(__half2*)&Qh[row * AP + c4]     = __halves2half2(hh[0], hh[1]);
        *(__half2*)&Qh[row * AP + c4 + 2] = __halves2half2(hh[2], hh[3]);
        *(__half2*)&Ql[row * AP + c4]     = __halves2half2(ll[0], ll[1]);
        *(__half2*)&Ql[row * AP + c4 + 2] = __halves2half2(ll[2], ll[3]);
    }
    __syncthreads();

    // ---- hoist Q A-fragments ----
    uint32_t aqh[4][4], aql[4][4];
    {
        const uint32_t kb = (uint32_t)(lane & 3) * 4u;
        const uint32_t r0 = (uint32_t)(w * 16 + (lane >> 2)) * (AP * 2) + kb;
        const uint32_t r1 = r0 + 8u * (AP * 2);
#pragma unroll
        for (int s = 0; s < 4; s++) {
            uint32_t ko = (uint32_t)s * 32u;
            aqh[s][0] = lds32(sQh + r0 + ko);       aqh[s][1] = lds32(sQh + r1 + ko);
            aqh[s][2] = lds32(sQh + r0 + ko + 16u); aqh[s][3] = lds32(sQh + r1 + ko + 16u);
            aql[s][0] = lds32(sQl + r0 + ko);       aql[s][1] = lds32(sQl + r1 + ko);
            aql[s][2] = lds32(sQl + r0 + ko + 16u); aql[s][3] = lds32(sQl + r1 + ko + 16u);
        }
    }

    float m0r = -1e30f, m1r = -1e30f, l0r = 0.f, l1r = 0.f;
    float ofr[8][4];
#pragma unroll
    for (int j = 0; j < 8; j++)
#pragma unroll
        for (int r = 0; r < 4; r++) ofr[j][r] = 0.f;

    const int r0g = q0 + w * 16 + (lane >> 2);
    const int r1g = r0g + 8;

    const int nkt = qtile + 1;
    for (int kt = 0; kt < nkt; kt++) {
        const int k0 = kt * 64;
        __syncthreads();
        // ---- load K (single fp16) and V (single fp16, transposed) ----
#pragma unroll
        for (int it = 0; it < 8; it++) {
            int lin = tid + it * 128;
            int row = lin >> 4;
            int c4  = (lin & 15) * 4;
            float4 kv = *(const float4*)&kptr[(size_t)(k0 + row) * CC + c4];
            *(__half2*)&Kf[row * AP + c4]     = __floats2half2_rn(kv.x, kv.y);
            *(__half2*)&Kf[row * AP + c4 + 2] = __floats2half2_rn(kv.z, kv.w);

            float4 vv = *(const float4*)&vptr[(size_t)(k0 + row) * CC + c4];
            Vf[(c4 + 0) * AP + row] = __float2half_rn(vv.x);
            Vf[(c4 + 1) * AP + row] = __float2half_rn(vv.y);
            Vf[(c4 + 2) * AP + row] = __float2half_rn(vv.z);
            Vf[(c4 + 3) * AP + row] = __float2half_rn(vv.w);
        }
        __syncthreads();

        // ---- S = Q*K^T (2-pass fp16) ----
        float sfr[8][4];
#pragma unroll
        for (int j = 0; j < 8; j++)
#pragma unroll
            for (int r = 0; r < 4; r++) sfr[j][r] = 0.f;

        const uint32_t kb = (uint32_t)(lane & 3) * 4u;
#pragma unroll
        for (int j = 0; j < 8; j++) {
            uint32_t nrow = (uint32_t)(j * 8 + (lane >> 2)) * (AP * 2) + kb;
#pragma unroll
            for (int s = 0; s < 4; s++) {
                uint32_t ko = (uint32_t)s * 32u;
                uint32_t bkf[2];
                bkf[0] = lds32(sKf + nrow + ko); bkf[1] = lds32(sKf + nrow + ko + 16u);
                mma_f16(sfr[j], aqh[s], bkf);
                mma_f16(sfr[j], aql[s], bkf);
            }
        }

        // ---- causal mask on diagonal tile ----
        if (kt == qtile) {
#pragma unroll
            for (int j = 0; j < 8; j++) {
                int cbase = k0 + j * 8 + 2 * (lane & 3);
                if (cbase > r0g)     sfr[j][0] = -1e30f;
                if (cbase + 1 > r0g) sfr[j][1] = -1e30f;
                if (cbase > r1g)     sfr[j][2] = -1e30f;
                if (cbase + 1 > r1g) sfr[j][3] = -1e30f;
            }
        }

        // ---- online softmax ----
        float mx0 = -1e30f, mx1 = -1e30f;
#pragma unroll
        for (int j = 0; j < 8; j++) {
            mx0 = fmaxf(mx0, fmaxf(sfr[j][0], sfr[j][1]));
            mx1 = fmaxf(mx1, fmaxf(sfr[j][2], sfr[j][3]));
        }
        mx0 = fmaxf(mx0, __shfl_xor_sync(0xffffffffu, mx0, 1));
        mx0 = fmaxf(mx0, __shfl_xor_sync(0xffffffffu, mx0, 2));
        mx1 = fmaxf(mx1, __shfl_xor_sync(0xffffffffu, mx1, 1));
        mx1 = fmaxf(mx1, __shfl_xor_sync(0xffffffffu, mx1, 2));

        float mn0 = fmaxf(m0r, mx0), mn1 = fmaxf(m1r, mx1);
        float corr0 = __expf(m0r - mn0), corr1 = __expf(m1r - mn1);
        m0r = mn0; m1r = mn1;

        float rs0 = 0.f, rs1 = 0.f;
#pragma unroll
        for (int j = 0; j < 8; j++) {
            sfr[j][0] = __expf(sfr[j][0] - mn0);
            sfr[j][1] = __expf(sfr[j][1] - mn0);
            sfr[j][2] = __expf(sfr[j][2] - mn1);
            sfr[j][3] = __expf(sfr[j][3] - mn1);
            rs0 += sfr[j][0] + sfr[j][1];
            rs1 += sfr[j][2] + sfr[j][3];
        }
        rs0 += __shfl_xor_sync(0xffffffffu, rs0, 1);
        rs0 += __shfl_xor_sync(0xffffffffu, rs0, 2);
        rs1 += __shfl_xor_sync(0xffffffffu, rs1, 1);
        rs1 += __shfl_xor_sync(0xffffffffu, rs1, 2);
        l0r = l0r * corr0 + rs0;
        l1r = l1r * corr1 + rs1;

#pragma unroll
        for (int j = 0; j < 8; j++) {
            ofr[j][0] *= corr0; ofr[j][1] *= corr0;
            ofr[j][2] *= corr1; ofr[j][3] *= corr1;
        }

        // ---- pack P to fp16 hi/lo A-fragments ----
        uint32_t pah[4][4], pal[4][4];
#pragma unroll
        for (int s = 0; s < 4; s++) {
            const int ja = 2 * s, jb = 2 * s + 1;
            float p[8] = { sfr[ja][0], sfr[ja][1], sfr[ja][2], sfr[ja][3],
                           sfr[jb][0], sfr[jb][1], sfr[jb][2], sfr[jb][3] };
            __half phh[8];
            float pl[8];
#pragma unroll
            for (int e = 0; e < 8; e++) {
                phh[e] = __float2half_rn(p[e]);
                pl[e] = p[e] - __half2float(phh[e]);
            }
            pah[s][0] = pack_f16x2(__half2float(phh[0]), __half2float(phh[1]));
            pah[s][1] = pack_f16x2(__half2float(phh[2]), __half2float(phh[3]));
            pah[s][2] = pack_f16x2(__half2float(phh[4]), __half2float(phh[5]));
            pah[s][3] = pack_f16x2(__half2float(phh[6]), __half2float(phh[7]));
            pal[s][0] = pack_f16x2(pl[0], pl[1]);
            pal[s][1] = pack_f16x2(pl[2], pl[3]);
            pal[s][2] = pack_f16x2(pl[4], pl[5]);
            pal[s][3] = pack_f16x2(pl[6], pl[7]);
        }

        // ---- O += P*V (2-pass fp16) ----
#pragma unroll
        for (int j = 0; j < 8; j++) {
            uint32_t drow = (uint32_t)(j * 8 + (lane >> 2)) * (AP * 2) + kb;
#pragma unroll
            for (int s = 0; s < 4; s++) {
                uint32_t ko = (uint32_t)s * 32u;
                uint32_t bvf[2];
                bvf[0] = lds32(sVf + drow + ko); bvf[1] = lds32(sVf + drow + ko + 16u);
                mma_f16(ofr[j], pah[s], bvf);
                mma_f16(ofr[j], pal[s], bvf);
            }
        }
    }

    // ---- epilogue: normalize, split fp16 hi/lo for WO GEMM ----
    float inv0 = 1.f / l0r, inv1 = 1.f / l1r;
    __half* ahp = g_ah + (size_t)b * TT * CC + h * DD;
    __half* alp = g_al + (size_t)b * TT * CC + h * DD;
#pragma unroll
    for (int j = 0; j < 8; j++) {
        int col = j * 8 + 2 * (lane & 3);
        float v0 = ofr[j][0] * inv0, v1 = ofr[j][1] * inv0;
        float v2 = ofr[j][2] * inv1, v3 = ofr[j][3] * inv1;
        __half h0 = __float2half_rn(v0), h1 = __float2half_rn(v1);
        __half h2 = __float2half_rn(v2), h3 = __float2half_rn(v3);
        *(__half2*)&ahp[(size_t)r0g * CC + col] = __halves2half2(h0, h1);
        *(__half2*)&alp[(size_t)r0g * CC + col] =
            __halves2half2(__float2half_rn(v0 - __half2float(h0)),
                           __float2half_rn(v1 - __half2float(h1)));
        *(__half2*)&ahp[(size_t)r1g * CC + col] = __halves2half2(h2, h3);
        *(__half2*)&alp[(size_t)r1g * CC + col] =
            __halves2half2(__float2half_rn(v2 - __half2float(h2)),
                           __float2half_rn(v3 - __half2float(h3)));
    }
}

// ---------------------------------------------------------------------------
extern "C" void kernel_launch(void* const* d_in, const int* in_sizes, int n_in,
                              void* d_out, int out_size)
{
    const float* x   = (const float*)d_in[0];
    const float* W_Q = (const float*)d_in[1];
    const float* W_K = (const float*)d_in[2];
    const float* W_V = (const float*)d_in[3];
    const float* W_O = (const float*)d_in[4];
    float* out = (float*)d_out;

    float *q, *k, *v;
    __half *xh, *xl, *ah, *al, *w16;
    cudaGetSymbolAddress((void**)&q,   g_q);
    cudaGetSymbolAddress((void**)&k,   g_k);
    cudaGetSymbolAddress((void**)&v,   g_v);
    cudaGetSymbolAddress((void**)&xh,  g_xh);
    cudaGetSymbolAddress((void**)&xl,  g_xl);
    cudaGetSymbolAddress((void**)&ah,  g_ah);
    cudaGetSymbolAddress((void**)&al,  g_al);
    cudaGetSymbolAddress((void**)&w16, g_w16);

    const int gemm_smem = NSTAGE * (int)STAGEB;   // 110592 -> 2 CTAs/SM
    cudaFuncSetAttribute(gemm_qkv,
                         cudaFuncAttributeMaxDynamicSharedMemorySize, gemm_smem);
    cudaFuncSetAttribute(gemm_one,
                         cudaFuncAttributeMaxDynamicSharedMemorySize, gemm_smem);
    const int attn_smem = 4 * ATILE * (int)sizeof(__half);   // 36864
    cudaFuncSetAttribute(attn_tc,
                         cudaFuncAttributeMaxDynamicSharedMemorySize, attn_smem);

    {
        int n4 = MM * CC / 4;
        split16_kernel<<<(n4 + 255) / 256, 256>>>(x, xh, xl, n4);
        int w4 = CC * CC / 4;
        dim3 wg((w4 + 255) / 256, 4);
        conv16x4_kernel<<<wg, 256>>>(W_Q, W_K, W_V, W_O, w16, w4);
    }

    dim3 qkvgrid(24, MM / 128);   // (24, 64)
    gemm_qkv<<<qkvgrid, 256, gemm_smem>>>(xh, xl, w16, q, k, v);

    dim3 agrid(TT / 64, BB * HH);
    attn_tc<<<agrid, 128, attn_smem>>>();

    dim3 ogrid(CC / 128, MM / 128);
    gemm_one<<<ogrid, 256, gemm_smem>>>(ah, al, w16 + 3 * CC * CC, out);
}

// round 11
// speedup vs baseline: 1.6410x; 1.0181x over previous
#include <cuda_runtime.h>
#include <cuda_bf16.h>
#include <cuda_fp16.h>
#include <math.h>
#include <stdint.h>

#define BB 4
#define TT 2048
#define CC 1024
#define HH 16
#define DD 64
#define MM (BB*TT)   // 8192

// ---------------------------------------------------------------------------
// Scratch (device globals; no allocation allowed)
// ---------------------------------------------------------------------------
__device__ __half g_xh[MM * CC];
__device__ __half g_xl[MM * CC];
__device__ __half g_qh[MM * CC];   // Q scaled 1/8, hi plane
__device__ __half g_ql[MM * CC];   // Q scaled 1/8, lo plane
__device__ __half g_kf[MM * CC];   // K fp16
__device__ __half g_vf[MM * CC];   // V fp16
__device__ __half g_ah[MM * CC];   // attn-out hi
__device__ __half g_al[MM * CC];   // attn-out lo
__device__ __half g_w16[4 * CC * CC];

// ---------------------------------------------------------------------------
__device__ __forceinline__ uint32_t smem_u32(const void* p) {
    uint32_t a;
    asm("{ .reg .u64 t; cvta.to.shared.u64 t, %1; cvt.u32.u64 %0, t; }"
        : "=r"(a) : "l"(p));
    return a;
}

__device__ __forceinline__ void cp16(uint32_t dst, const void* src) {
    asm volatile("cp.async.cg.shared.global [%0], [%1], 16;"
                 :: "r"(dst), "l"(src) : "memory");
}
#define CP_COMMIT() asm volatile("cp.async.commit_group;" ::: "memory")
#define CP_WAIT(n)  asm volatile("cp.async.wait_group %0;" :: "n"(n) : "memory")

__device__ __forceinline__ void mma_f16(float* d, const uint32_t* a, const uint32_t* b) {
    asm volatile(
        "mma.sync.aligned.m16n8k16.row.col.f32.f16.f16.f32 "
        "{%0,%1,%2,%3}, {%4,%5,%6,%7}, {%8,%9}, {%0,%1,%2,%3};"
        : "+f"(d[0]), "+f"(d[1]), "+f"(d[2]), "+f"(d[3])
        : "r"(a[0]), "r"(a[1]), "r"(a[2]), "r"(a[3]), "r"(b[0]), "r"(b[1]));
}

__device__ __forceinline__ void ldm_x4(uint32_t* r, uint32_t addr) {
    asm volatile("ldmatrix.sync.aligned.m8n8.x4.shared.b16 {%0,%1,%2,%3}, [%4];"
                 : "=r"(r[0]), "=r"(r[1]), "=r"(r[2]), "=r"(r[3]) : "r"(addr));
}
__device__ __forceinline__ void ldm_x2(uint32_t* r, uint32_t addr) {
    asm volatile("ldmatrix.sync.aligned.m8n8.x2.shared.b16 {%0,%1}, [%2];"
                 : "=r"(r[0]), "=r"(r[1]) : "r"(addr));
}

__device__ __forceinline__ uint32_t lds32(uint32_t addr) {
    uint32_t v;
    asm volatile("ld.shared.b32 %0, [%1];" : "=r"(v) : "r"(addr));
    return v;
}

__device__ __forceinline__ uint32_t pack_f16x2(float lo, float hi) {
    __half2 hv = __floats2half2_rn(lo, hi);
    return *(uint32_t*)&hv;
}

// ---------------------------------------------------------------------------
// Conversion kernels
// ---------------------------------------------------------------------------
__global__ void conv16x4_kernel(const float* __restrict__ w0,
                                const float* __restrict__ w1,
                                const float* __restrict__ w2,
                                const float* __restrict__ w3,
                                __half* __restrict__ out, int n4)
{
    int i = blockIdx.x * blockDim.x + threadIdx.x;
    if (i >= n4) return;
    const float* src = (blockIdx.y == 0) ? w0 : (blockIdx.y == 1) ? w1
                     : (blockIdx.y == 2) ? w2 : w3;
    float4 v = ((const float4*)src)[i];
    __half2* op = (__half2*)(out + (size_t)blockIdx.y * CC * CC);
    op[2 * i + 0] = __floats2half2_rn(v.x, v.y);
    op[2 * i + 1] = __floats2half2_rn(v.z, v.w);
}

__global__ void split16_kernel(const float* __restrict__ in,
                               __half* __restrict__ hi,
                               __half* __restrict__ lo, int n4)
{
    int i = blockIdx.x * blockDim.x + threadIdx.x;
    if (i >= n4) return;
    float4 v = ((const float4*)in)[i];
    __half h0 = __float2half_rn(v.x);
    __half h1 = __float2half_rn(v.y);
    __half h2 = __float2half_rn(v.z);
    __half h3 = __float2half_rn(v.w);
    __half l0 = __float2half_rn(v.x - __half2float(h0));
    __half l1 = __float2half_rn(v.y - __half2float(h1));
    __half l2 = __float2half_rn(v.z - __half2float(h2));
    __half l3 = __float2half_rn(v.w - __half2float(h3));
    __half2* hp = (__half2*)hi;
    __half2* lp = (__half2*)lo;
    hp[2 * i + 0] = __halves2half2(h0, h1);
    hp[2 * i + 1] = __halves2half2(h2, h3);
    lp[2 * i + 0] = __halves2half2(l0, l1);
    lp[2 * i + 1] = __halves2half2(l2, l3);
}

// ---------------------------------------------------------------------------
// Core GEMM tile: C[128,128] = A[M,K] x W[N,K]^T  (fp16 asymmetric 2-pass)
// BK=64, 2-stage cp.async ring, 2 CTAs/SM.
// Epilogue modes: 0 = fp32 C; 1 = fp16 hi/lo scaled 1/8 (Q); 2 = fp16 (K/V).
// ---------------------------------------------------------------------------
#define ROWB 144u
#define TILEB (128u*ROWB)        // 18432
#define STAGEB (3u*TILEB)        // 55296
#define NSTAGE 2
#define NCHUNK (CC/64)           // 16

__device__ __forceinline__ void gemm_tile(
    const __half* __restrict__ Ah, const __half* __restrict__ Al,
    const __half* __restrict__ B,
    void* out0, void* out1, int mode,
    int m0, int n0, char* smem)
{
    const uint32_t sb = smem_u32(smem);
    const int tid  = threadIdx.x;
    const int lane = tid & 31;
    const int wid  = tid >> 5;
    const int wm   = wid >> 1;
    const int wn   = wid & 1;

    const __half* srcs[3] = {
        Ah + (size_t)m0 * CC, Al + (size_t)m0 * CC, B + (size_t)n0 * CC };

    auto issue_stage = [&](int chunk, int stage) {
        const int kc = chunk * 64;
        const uint32_t base = sb + (uint32_t)stage * STAGEB;
#pragma unroll
        for (int t = 0; t < 12; t++) {
            int lin  = tid + t * 256;
            int tile = lin >> 10;
            int idx  = lin & 1023;
            int row  = idx >> 3;
            int seg  = idx & 7;
            uint32_t dst = base + (uint32_t)tile * TILEB + (uint32_t)row * ROWB + (uint32_t)seg * 16u;
            cp16(dst, srcs[tile] + (size_t)row * CC + kc + seg * 8);
        }
        CP_COMMIT();
    };

    float acc[2][8][4];
#pragma unroll
    for (int i = 0; i < 2; i++)
#pragma unroll
        for (int j = 0; j < 8; j++)
#pragma unroll
            for (int r = 0; r < 4; r++) acc[i][j][r] = 0.f;

    issue_stage(0, 0);

    const uint32_t a_row  = (uint32_t)(lane & 15);
    const uint32_t a_koff = (uint32_t)(lane >> 4) * 16u;
    const uint32_t b_row  = (uint32_t)(lane & 7);
    const uint32_t b_koff = (uint32_t)((lane >> 3) & 1) * 16u;

    for (int c = 0; c < NCHUNK; c++) {
        const int stage = c & 1;
        if (c + 1 < NCHUNK) { issue_stage(c + 1, stage ^ 1); CP_WAIT(1); }
        else                { CP_WAIT(0); }
        __syncthreads();

        const uint32_t base  = sb + (uint32_t)stage * STAGEB;
        const uint32_t Aho   = base;
        const uint32_t Alo_o = base + TILEB;
        const uint32_t Bo    = base + 2u * TILEB;

#pragma unroll
        for (int kk = 0; kk < 4; kk++) {
            const uint32_t ko = (uint32_t)kk * 32u;
            uint32_t ah[2][4], al[2][4];
#pragma unroll
            for (int fi = 0; fi < 2; fi++) {
                uint32_t ra = (uint32_t)(wm * 32 + fi * 16) * ROWB + a_row * ROWB + ko + a_koff;
                ldm_x4(ah[fi], Aho + ra);
                ldm_x4(al[fi], Alo_o + ra);
            }
#pragma unroll
            for (int j = 0; j < 8; j++) {
                uint32_t rb = (uint32_t)(wn * 64 + j * 8) * ROWB + b_row * ROWB + ko + b_koff;
                uint32_t bf[2];
                ldm_x2(bf, Bo + rb);
#pragma unroll
                for (int fi = 0; fi < 2; fi++) {
                    mma_f16(acc[fi][j], ah[fi], bf);
                    mma_f16(acc[fi][j], al[fi], bf);
                }
            }
        }
        __syncthreads();
    }

#pragma unroll
    for (int fi = 0; fi < 2; fi++) {
        int row0 = m0 + wm * 32 + fi * 16 + (lane >> 2);
#pragma unroll
        for (int j = 0; j < 8; j++) {
            int col = n0 + wn * 64 + j * 8 + (lane & 3) * 2;
            float a0 = acc[fi][j][0], a1 = acc[fi][j][1];
            float a2 = acc[fi][j][2], a3 = acc[fi][j][3];
            if (mode == 0) {
                float* C = (float*)out0;
                *(float2*)&C[(size_t)row0 * CC + col]       = make_float2(a0, a1);
                *(float2*)&C[(size_t)(row0 + 8) * CC + col] = make_float2(a2, a3);
            } else if (mode == 1) {
                // Q: scale 1/8, split fp16 hi/lo
                __half* qh = (__half*)out0;
                __half* ql = (__half*)out1;
                a0 *= 0.125f; a1 *= 0.125f; a2 *= 0.125f; a3 *= 0.125f;
                __half h0 = __float2half_rn(a0), h1 = __float2half_rn(a1);
                __half h2 = __float2half_rn(a2), h3 = __float2half_rn(a3);
                *(__half2*)&qh[(size_t)row0 * CC + col] = __halves2half2(h0, h1);
                *(__half2*)&ql[(size_t)row0 * CC + col] =
                    __halves2half2(__float2half_rn(a0 - __half2float(h0)),
                                   __float2half_rn(a1 - __half2float(h1)));
                *(__half2*)&qh[(size_t)(row0 + 8) * CC + col] = __halves2half2(h2, h3);
                *(__half2*)&ql[(size_t)(row0 + 8) * CC + col] =
                    __halves2half2(__float2half_rn(a2 - __half2float(h2)),
                                   __float2half_rn(a3 - __half2float(h3)));
            } else {
                __half* Cf = (__half*)out0;
                *(__half2*)&Cf[(size_t)row0 * CC + col]       = __floats2half2_rn(a0, a1);
                *(__half2*)&Cf[(size_t)(row0 + 8) * CC + col] = __floats2half2_rn(a2, a3);
            }
        }
    }
}

// Fused QKV: grid.x in [0,24): wsel = x>>3, n0 = (x&7)*128
__global__ __launch_bounds__(256, 2) void gemm_qkv(
    const __half* __restrict__ xh, const __half* __restrict__ xl,
    const __half* __restrict__ w16,
    __half* __restrict__ qh, __half* __restrict__ ql,
    __half* __restrict__ kf, __half* __restrict__ vf)
{
    extern __shared__ char smem[];
    const int wsel = blockIdx.x >> 3;
    const int n0 = (blockIdx.x & 7) * 128;
    const int m0 = blockIdx.y * 128;
    if (wsel == 0)
        gemm_tile(xh, xl, w16, qh, ql, 1, m0, n0, smem);
    else if (wsel == 1)
        gemm_tile(xh, xl, w16 + (size_t)CC * CC, kf, nullptr, 2, m0, n0, smem);
    else
        gemm_tile(xh, xl, w16 + 2 * (size_t)CC * CC, vf, nullptr, 2, m0, n0, smem);
}

__global__ __launch_bounds__(256, 2) void gemm_one(
    const __half* __restrict__ Ah, const __half* __restrict__ Al,
    const __half* __restrict__ B, float* __restrict__ C)
{
    extern __shared__ char smem[];
    gemm_tile(Ah, Al, B, C, nullptr, 0, blockIdx.y * 128, blockIdx.x * 128, smem);
}

// ---------------------------------------------------------------------------
// Tensor-core flash attention (causal), fp16 asymmetric 2-pass.
// 256 threads / 8 warps, 128 queries per CTA (warp w owns rows w*16..+15).
// All inputs pre-converted fp16 (Q pre-scaled + split). fp32 softmax.
// SMEM: Qh,Ql [128][72] + Kf,Vf [64][72] fp16 = 54 KB.
// ---------------------------------------------------------------------------
#define AP 72
#define QTILE_ELE (128 * AP)
#define KTILE_ELE (64 * AP)

__global__ __launch_bounds__(256) void attn_tc()
{
    extern __shared__ __half ash[];
    __half* Qh = ash;
    __half* Ql = Qh + QTILE_ELE;
    __half* Kf = Ql + QTILE_ELE;
    __half* Vf = Kf + KTILE_ELE;
    const uint32_t sQh = smem_u32(Qh), sQl = smem_u32(Ql);
    const uint32_t sKf = smem_u32(Kf), sVf = smem_u32(Vf);

    const int tid  = threadIdx.x;
    const int lane = tid & 31;
    const int w    = tid >> 5;            // 0..7
    const int qt   = blockIdx.x;          // 0..15
    const int bh = blockIdx.y;
    const int b = bh / HH, h = bh % HH;
    const int q0 = qt * 128;

    const size_t hoff = (size_t)b * TT * CC + h * DD;
    const __half* qhp = g_qh + hoff;
    const __half* qlp = g_ql + hoff;
    const __half* kfp = g_kf + hoff;
    const __half* vfp = g_vf + hoff;

    // ---- load Q hi/lo (straight fp16 copies, 16B chunks) ----
#pragma unroll
    for (int it = 0; it < 4; it++) {
        int lin = tid + it * 256;       // 0..1023
        int row = lin >> 3;             // 0..127
        int seg = lin & 7;              // 0..7 (8 halves each)
        uint4 vh = *(const uint4*)&qhp[(size_t)(q0 + row) * CC + seg * 8];
        uint4 vl = *(const uint4*)&qlp[(size_t)(q0 + row) * CC + seg * 8];
        *(uint4*)&Qh[row * AP + seg * 8] = vh;
        *(uint4*)&Ql[row * AP + seg * 8] = vl;
    }
    __syncthreads();

    // ---- hoist Q A-fragments ----
    uint32_t aqh[4][4], aql[4][4];
    {
        const uint32_t kb = (uint32_t)(lane & 3) * 4u;
        const uint32_t r0 = (uint32_t)(w * 16 + (lane >> 2)) * (AP * 2) + kb;
        const uint32_t r1 = r0 + 8u * (AP * 2);
#pragma unroll
        for (int s = 0; s < 4; s++) {
            uint32_t ko = (uint32_t)s * 32u;
            aqh[s][0] = lds32(sQh + r0 + ko);       aqh[s][1] = lds32(sQh + r1 + ko);
            aqh[s][2] = lds32(sQh + r0 + ko + 16u); aqh[s][3] = lds32(sQh + r1 + ko + 16u);
            aql[s][0] = lds32(sQl + r0 + ko);       aql[s][1] = lds32(sQl + r1 + ko);
            aql[s][2] = lds32(sQl + r0 + ko + 16u); aql[s][3] = lds32(sQl + r1 + ko + 16u);
        }
    }

    float m0r = -1e30f, m1r = -1e30f, l0r = 0.f, l1r = 0.f;
    float ofr[8][4];
#pragma unroll
    for (int j = 0; j < 8; j++)
#pragma unroll
        for (int r = 0; r < 4; r++) ofr[j][r] = 0.f;

    const int r0g = q0 + w * 16 + (lane >> 2);
    const int r1g = r0g + 8;

    const int nkt = 2 * qt + 2;
    for (int kt = 0; kt < nkt; kt++) {
        const int k0 = kt * 64;
        __syncthreads();
        // ---- load K (straight) and V (transposed), both fp16 ----
#pragma unroll
        for (int it = 0; it < 2; it++) {
            int lin = tid + it * 256;   // 0..511
            int row = lin >> 3;         // 0..63
            int seg = lin & 7;
            uint4 kv = *(const uint4*)&kfp[(size_t)(k0 + row) * CC + seg * 8];
            *(uint4*)&Kf[row * AP + seg * 8] = kv;
        }
#pragma unroll
        for (int it = 0; it < 8; it++) {
            int lin = tid + it * 256;   // 0..2047
            int k   = lin >> 5;         // 0..63
            int d2  = lin & 31;         // 0..31
            __half2 hv = *(const __half2*)&vfp[(size_t)(k0 + k) * CC + d2 * 2];
            Vf[(d2 * 2 + 0) * AP + k] = __low2half(hv);
            Vf[(d2 * 2 + 1) * AP + k] = __high2half(hv);
        }
        __syncthreads();

        // Fully-masked warps skip compute entirely
        const bool skip = (k0 > q0 + w * 16 + 15);
        if (!skip) {
            // ---- S = Q*K^T (2-pass fp16) ----
            float sfr[8][4];
#pragma unroll
            for (int j = 0; j < 8; j++)
#pragma unroll
                for (int r = 0; r < 4; r++) sfr[j][r] = 0.f;

            const uint32_t kb = (uint32_t)(lane & 3) * 4u;
#pragma unroll
            for (int j = 0; j < 8; j++) {
                uint32_t nrow = (uint32_t)(j * 8 + (lane >> 2)) * (AP * 2) + kb;
#pragma unroll
                for (int s = 0; s < 4; s++) {
                    uint32_t ko = (uint32_t)s * 32u;
                    uint32_t bkf[2];
                    bkf[0] = lds32(sKf + nrow + ko); bkf[1] = lds32(sKf + nrow + ko + 16u);
                    mma_f16(sfr[j], aqh[s], bkf);
                    mma_f16(sfr[j], aql[s], bkf);
                }
            }

            // ---- causal mask (only when tile crosses this warp's diagonal) ----
            if (k0 + 63 > q0 + w * 16) {
#pragma unroll
                for (int j = 0; j < 8; j++) {
                    int cbase = k0 + j * 8 + 2 * (lane & 3);
                    if (cbase > r0g)     sfr[j][0] = -1e30f;
                    if (cbase + 1 > r0g) sfr[j][1] = -1e30f;
                    if (cbase > r1g)     sfr[j][2] = -1e30f;
                    if (cbase + 1 > r1g) sfr[j][3] = -1e30f;
                }
            }

            // ---- online softmax ----
            float mx0 = -1e30f, mx1 = -1e30f;
#pragma unroll
            for (int j = 0; j < 8; j++) {
                mx0 = fmaxf(mx0, fmaxf(sfr[j][0], sfr[j][1]));
                mx1 = fmaxf(mx1, fmaxf(sfr[j][2], sfr[j][3]));
            }
            mx0 = fmaxf(mx0, __shfl_xor_sync(0xffffffffu, mx0, 1));
            mx0 = fmaxf(mx0, __shfl_xor_sync(0xffffffffu, mx0, 2));
            mx1 = fmaxf(mx1, __shfl_xor_sync(0xffffffffu, mx1, 1));
            mx1 = fmaxf(mx1, __shfl_xor_sync(0xffffffffu, mx1, 2));

            float mn0 = fmaxf(m0r, mx0), mn1 = fmaxf(m1r, mx1);
            float corr0 = __expf(m0r - mn0), corr1 = __expf(m1r - mn1);
            m0r = mn0; m1r = mn1;

            float rs0 = 0.f, rs1 = 0.f;
#pragma unroll
            for (int j = 0; j < 8; j++) {
                sfr[j][0] = __expf(sfr[j][0] - mn0);
                sfr[j][1] = __expf(sfr[j][1] - mn0);
                sfr[j][2] = __expf(sfr[j][2] - mn1);
                sfr[j][3] = __expf(sfr[j][3] - mn1);
                rs0 += sfr[j][0] + sfr[j][1];
                rs1 += sfr[j][2] + sfr[j][3];
            }
            rs0 += __shfl_xor_sync(0xffffffffu, rs0, 1);
            rs0 += __shfl_xor_sync(0xffffffffu, rs0, 2);
            rs1 += __shfl_xor_sync(0xffffffffu, rs1, 1);
            rs1 += __shfl_xor_sync(0xffffffffu, rs1, 2);
            l0r = l0r * corr0 + rs0;
            l1r = l1r * corr1 + rs1;

#pragma unroll
            for (int j = 0; j < 8; j++) {
                ofr[j][0] *= corr0; ofr[j][1] *= corr0;
                ofr[j][2] *= corr1; ofr[j][3] *= corr1;
            }

            // ---- pack P to fp16 hi/lo A-fragments ----
            uint32_t pah[4][4], pal[4][4];
#pragma unroll
            for (int s = 0; s < 4; s++) {
                const int ja = 2 * s, jb = 2 * s + 1;
                float p[8] = { sfr[ja][0], sfr[ja][1], sfr[ja][2], sfr[ja][3],
                               sfr[jb][0], sfr[jb][1], sfr[jb][2], sfr[jb][3] };
                __half phh[8];
                float pl[8];
#pragma unroll
                for (int e = 0; e < 8; e++) {
                    phh[e] = __float2half_rn(p[e]);
                    pl[e] = p[e] - __half2float(phh[e]);
                }
                pah[s][0] = pack_f16x2(__half2float(phh[0]), __half2float(phh[1]));
                pah[s][1] = pack_f16x2(__half2float(phh[2]), __half2float(phh[3]));
                pah[s][2] = pack_f16x2(__half2float(phh[4]), __half2float(phh[5]));
                pah[s][3] = pack_f16x2(__half2float(phh[6]), __half2float(phh[7]));
                pal[s][0] = pack_f16x2(pl[0], pl[1]);
                pal[s][1] = pack_f16x2(pl[2], pl[3]);
                pal[s][2] = pack_f16x2(pl[4], pl[5]);
                pal[s][3] = pack_f16x2(pl[6], pl[7]);
            }

            // ---- O += P*V (2-pass fp16) ----
#pragma unroll
            for (int j = 0; j < 8; j++) {
                uint32_t drow = (uint32_t)(j * 8 + (lane >> 2)) * (AP * 2) + kb;
#pragma unroll
                for (int s = 0; s < 4; s++) {
                    uint32_t ko = (uint32_t)s * 32u;
                    uint32_t bvf[2];
                    bvf[0] = lds32(sVf + drow + ko); bvf[1] = lds32(sVf + drow + ko + 16u);
                    mma_f16(ofr[j], pah[s], bvf);
                    mma_f16(ofr[j], pal[s], bvf);
                }
            }
        }
    }

    // ---- epilogue: normalize, split fp16 hi/lo for WO GEMM ----
    float inv0 = 1.f / l0r, inv1 = 1.f / l1r;
    __half* ahp = g_ah + hoff;
    __half* alp = g_al + hoff;
#pragma unroll
    for (int j = 0; j < 8; j++) {
        int col = j * 8 + 2 * (lane & 3);
        float v0 = ofr[j][0] * inv0, v1 = ofr[j][1] * inv0;
        float v2 = ofr[j][2] * inv1, v3 = ofr[j][3] * inv1;
        __half h0 = __float2half_rn(v0), h1 = __float2half_rn(v1);
        __half h2 = __float2half_rn(v2), h3 = __float2half_rn(v3);
        *(__half2*)&ahp[(size_t)r0g * CC + col] = __halves2half2(h0, h1);
        *(__half2*)&alp[(size_t)r0g * CC + col] =
            __halves2half2(__float2half_rn(v0 - __half2float(h0)),
                           __float2half_rn(v1 - __half2float(h1)));
        *(__half2*)&ahp[(size_t)r1g * CC + col] = __halves2half2(h2, h3);
        *(__half2*)&alp[(size_t)r1g * CC + col] =
            __halves2half2(__float2half_rn(v2 - __half2float(h2)),
                           __float2half_rn(v3 - __half2float(h3)));
    }
}

// ---------------------------------------------------------------------------
extern "C" void kernel_launch(void* const* d_in, const int* in_sizes, int n_in,
                              void* d_out, int out_size)
{
    const float* x   = (const float*)d_in[0];
    const float* W_Q = (const float*)d_in[1];
    const float* W_K = (const float*)d_in[2];
    const float* W_V = (const float*)d_in[3];
    const float* W_O = (const float*)d_in[4];
    float* out = (float*)d_out;

    __half *xh, *xl, *qh, *ql, *kf, *vf, *ah, *al, *w16;
    cudaGetSymbolAddress((void**)&xh,  g_xh);
    cudaGetSymbolAddress((void**)&xl,  g_xl);
    cudaGetSymbolAddress((void**)&qh,  g_qh);
    cudaGetSymbolAddress((void**)&ql,  g_ql);
    cudaGetSymbolAddress((void**)&kf,  g_kf);
    cudaGetSymbolAddress((void**)&vf,  g_vf);
    cudaGetSymbolAddress((void**)&ah,  g_ah);
    cudaGetSymbolAddress((void**)&al,  g_al);
    cudaGetSymbolAddress((void**)&w16, g_w16);

    const int gemm_smem = NSTAGE * (int)STAGEB;   // 110592 -> 2 CTAs/SM
    cudaFuncSetAttribute(gemm_qkv,
                         cudaFuncAttributeMaxDynamicSharedMemorySize, gemm_smem);
    cudaFuncSetAttribute(gemm_one,
                         cudaFuncAttributeMaxDynamicSharedMemorySize, gemm_smem);
    const int attn_smem = (2 * QTILE_ELE + 2 * KTILE_ELE) * (int)sizeof(__half); // 55296
    cudaFuncSetAttribute(attn_tc,
                         cudaFuncAttributeMaxDynamicSharedMemorySize, attn_smem);

    {
        int n4 = MM * CC / 4;
        split16_kernel<<<(n4 + 255) / 256, 256>>>(x, xh, xl, n4);
        int w4 = CC * CC / 4;
        dim3 wg((w4 + 255) / 256, 4);
        conv16x4_kernel<<<wg, 256>>>(W_Q, W_K, W_V, W_O, w16, w4);
    }

    dim3 qkvgrid(24, MM / 128);   // (24, 64)
    gemm_qkv<<<qkvgrid, 256, gemm_smem>>>(xh, xl, w16, qh, ql, kf, vf);

    dim3 agrid(TT / 128, BB * HH);   // (16, 64)
    attn_tc<<<agrid, 256, attn_smem>>>();

    dim3 ogrid(CC / 128, MM / 128);
    gemm_one<<<ogrid, 256, gemm_smem>>>(ah, al, w16 + 3 * (size_t)CC * CC, out);
}

// round 12
// speedup vs baseline: 2.0316x; 1.2381x over previous
#include <cuda_runtime.h>
#include <cuda_bf16.h>
#include <cuda_fp16.h>
#include <math.h>
#include <stdint.h>

#define BB 4
#define TT 2048
#define CC 1024
#define HH 16
#define DD 64
#define MM (BB*TT)   // 8192

// ---------------------------------------------------------------------------
// Scratch (device globals; no allocation allowed)
// ---------------------------------------------------------------------------
__device__ __half g_xh[MM * CC];
__device__ __half g_xl[MM * CC];
__device__ __half g_qh[MM * CC];   // Q scaled 1/8, hi plane
__device__ __half g_ql[MM * CC];   // Q scaled 1/8, lo plane
__device__ __half g_kf[MM * CC];   // K fp16
__device__ __half g_vf[MM * CC];   // V fp16
__device__ __half g_ah[MM * CC];   // attn-out hi
__device__ __half g_al[MM * CC];   // attn-out lo
__device__ __half g_w16[4 * CC * CC];

// ---------------------------------------------------------------------------
__device__ __forceinline__ uint32_t smem_u32(const void* p) {
    uint32_t a;
    asm("{ .reg .u64 t; cvta.to.shared.u64 t, %1; cvt.u32.u64 %0, t; }"
        : "=r"(a) : "l"(p));
    return a;
}

__device__ __forceinline__ void cp16(uint32_t dst, const void* src) {
    asm volatile("cp.async.cg.shared.global [%0], [%1], 16;"
                 :: "r"(dst), "l"(src) : "memory");
}
#define CP_COMMIT() asm volatile("cp.async.commit_group;" ::: "memory")
#define CP_WAIT(n)  asm volatile("cp.async.wait_group %0;" :: "n"(n) : "memory")

__device__ __forceinline__ void mma_f16(float* d, const uint32_t* a, const uint32_t* b) {
    asm volatile(
        "mma.sync.aligned.m16n8k16.row.col.f32.f16.f16.f32 "
        "{%0,%1,%2,%3}, {%4,%5,%6,%7}, {%8,%9}, {%0,%1,%2,%3};"
        : "+f"(d[0]), "+f"(d[1]), "+f"(d[2]), "+f"(d[3])
        : "r"(a[0]), "r"(a[1]), "r"(a[2]), "r"(a[3]), "r"(b[0]), "r"(b[1]));
}

__device__ __forceinline__ void ldm_x4(uint32_t* r, uint32_t addr) {
    asm volatile("ldmatrix.sync.aligned.m8n8.x4.shared.b16 {%0,%1,%2,%3}, [%4];"
                 : "=r"(r[0]), "=r"(r[1]), "=r"(r[2]), "=r"(r[3]) : "r"(addr));
}
__device__ __forceinline__ void ldm_x2(uint32_t* r, uint32_t addr) {
    asm volatile("ldmatrix.sync.aligned.m8n8.x2.shared.b16 {%0,%1}, [%2];"
                 : "=r"(r[0]), "=r"(r[1]) : "r"(addr));
}
__device__ __forceinline__ void ldm_x2t(uint32_t* r, uint32_t addr) {
    asm volatile("ldmatrix.sync.aligned.m8n8.x2.trans.shared.b16 {%0,%1}, [%2];"
                 : "=r"(r[0]), "=r"(r[1]) : "r"(addr));
}

__device__ __forceinline__ uint32_t pack_f16x2(float lo, float hi) {
    __half2 hv = __floats2half2_rn(lo, hi);
    return *(uint32_t*)&hv;
}

// ---------------------------------------------------------------------------
// Conversion kernels
// ---------------------------------------------------------------------------
__global__ void conv16x4_kernel(const float* __restrict__ w0,
                                const float* __restrict__ w1,
                                const float* __restrict__ w2,
                                const float* __restrict__ w3,
                                __half* __restrict__ out, int n4)
{
    int i = blockIdx.x * blockDim.x + threadIdx.x;
    if (i >= n4) return;
    const float* src = (blockIdx.y == 0) ? w0 : (blockIdx.y == 1) ? w1
                     : (blockIdx.y == 2) ? w2 : w3;
    float4 v = ((const float4*)src)[i];
    __half2* op = (__half2*)(out + (size_t)blockIdx.y * CC * CC);
    op[2 * i + 0] = __floats2half2_rn(v.x, v.y);
    op[2 * i + 1] = __floats2half2_rn(v.z, v.w);
}

__global__ void split16_kernel(const float* __restrict__ in,
                               __half* __restrict__ hi,
                               __half* __restrict__ lo, int n4)
{
    int i = blockIdx.x * blockDim.x + threadIdx.x;
    if (i >= n4) return;
    float4 v = ((const float4*)in)[i];
    __half h0 = __float2half_rn(v.x);
    __half h1 = __float2half_rn(v.y);
    __half h2 = __float2half_rn(v.z);
    __half h3 = __float2half_rn(v.w);
    __half l0 = __float2half_rn(v.x - __half2float(h0));
    __half l1 = __float2half_rn(v.y - __half2float(h1));
    __half l2 = __float2half_rn(v.z - __half2float(h2));
    __half l3 = __float2half_rn(v.w - __half2float(h3));
    __half2* hp = (__half2*)hi;
    __half2* lp = (__half2*)lo;
    hp[2 * i + 0] = __halves2half2(h0, h1);
    hp[2 * i + 1] = __halves2half2(h2, h3);
    lp[2 * i + 0] = __halves2half2(l0, l1);
    lp[2 * i + 1] = __halves2half2(l2, l3);
}

// ---------------------------------------------------------------------------
// Core GEMM tile: C[128,128] = A[M,K] x W[N,K]^T  (fp16 asymmetric 2-pass)
// BK=64, 2-stage cp.async ring, 2 CTAs/SM. (Unchanged from round 8/9.)
// Epilogue modes: 0 = fp32 C; 1 = fp16 hi/lo scaled 1/8 (Q); 2 = fp16 (K/V).
// ---------------------------------------------------------------------------
#define ROWB 144u
#define TILEB (128u*ROWB)        // 18432
#define STAGEB (3u*TILEB)        // 55296
#define NSTAGE 2
#define NCHUNK (CC/64)           // 16

__device__ __forceinline__ void gemm_tile(
    const __half* __restrict__ Ah, const __half* __restrict__ Al,
    const __half* __restrict__ B,
    void* out0, void* out1, int mode,
    int m0, int n0, char* smem)
{
    const uint32_t sb = smem_u32(smem);
    const int tid  = threadIdx.x;
    const int lane = tid & 31;
    const int wid  = tid >> 5;
    const int wm   = wid >> 1;
    const int wn   = wid & 1;

    const __half* srcs[3] = {
        Ah + (size_t)m0 * CC, Al + (size_t)m0 * CC, B + (size_t)n0 * CC };

    auto issue_stage = [&](int chunk, int stage) {
        const int kc = chunk * 64;
        const uint32_t base = sb + (uint32_t)stage * STAGEB;
#pragma unroll
        for (int t = 0; t < 12; t++) {
            int lin  = tid + t * 256;
            int tile = lin >> 10;
            int idx  = lin & 1023;
            int row  = idx >> 3;
            int seg  = idx & 7;
            uint32_t dst = base + (uint32_t)tile * TILEB + (uint32_t)row * ROWB + (uint32_t)seg * 16u;
            cp16(dst, srcs[tile] + (size_t)row * CC + kc + seg * 8);
        }
        CP_COMMIT();
    };

    float acc[2][8][4];
#pragma unroll
    for (int i = 0; i < 2; i++)
#pragma unroll
        for (int j = 0; j < 8; j++)
#pragma unroll
            for (int r = 0; r < 4; r++) acc[i][j][r] = 0.f;

    issue_stage(0, 0);

    const uint32_t a_row  = (uint32_t)(lane & 15);
    const uint32_t a_koff = (uint32_t)(lane >> 4) * 16u;
    const uint32_t b_row  = (uint32_t)(lane & 7);
    const uint32_t b_koff = (uint32_t)((lane >> 3) & 1) * 16u;

    for (int c = 0; c < NCHUNK; c++) {
        const int stage = c & 1;
        if (c + 1 < NCHUNK) { issue_stage(c + 1, stage ^ 1); CP_WAIT(1); }
        else                { CP_WAIT(0); }
        __syncthreads();

        const uint32_t base  = sb + (uint32_t)stage * STAGEB;
        const uint32_t Aho   = base;
        const uint32_t Alo_o = base + TILEB;
        const uint32_t Bo    = base + 2u * TILEB;

#pragma unroll
        for (int kk = 0; kk < 4; kk++) {
            const uint32_t ko = (uint32_t)kk * 32u;
            uint32_t ah[2][4], al[2][4];
#pragma unroll
            for (int fi = 0; fi < 2; fi++) {
                uint32_t ra = (uint32_t)(wm * 32 + fi * 16) * ROWB + a_row * ROWB + ko + a_koff;
                ldm_x4(ah[fi], Aho + ra);
                ldm_x4(al[fi], Alo_o + ra);
            }
#pragma unroll
            for (int j = 0; j < 8; j++) {
                uint32_t rb = (uint32_t)(wn * 64 + j * 8) * ROWB + b_row * ROWB + ko + b_koff;
                uint32_t bf[2];
                ldm_x2(bf, Bo + rb);
#pragma unroll
                for (int fi = 0; fi < 2; fi++) {
                    mma_f16(acc[fi][j], ah[fi], bf);
                    mma_f16(acc[fi][j], al[fi], bf);
                }
            }
        }
        __syncthreads();
    }

#pragma unroll
    for (int fi = 0; fi < 2; fi++) {
        int row0 = m0 + wm * 32 + fi * 16 + (lane >> 2);
#pragma unroll
        for (int j = 0; j < 8; j++) {
            int col = n0 + wn * 64 + j * 8 + (lane & 3) * 2;
            float a0 = acc[fi][j][0], a1 = acc[fi][j][1];
            float a2 = acc[fi][j][2], a3 = acc[fi][j][3];
            if (mode == 0) {
                float* C = (float*)out0;
                *(float2*)&C[(size_t)row0 * CC + col]       = make_float2(a0, a1);
                *(float2*)&C[(size_t)(row0 + 8) * CC + col] = make_float2(a2, a3);
            } else if (mode == 1) {
                __half* qh = (__half*)out0;
                __half* ql = (__half*)out1;
                a0 *= 0.125f; a1 *= 0.125f; a2 *= 0.125f; a3 *= 0.125f;
                __half h0 = __float2half_rn(a0), h1 = __float2half_rn(a1);
                __half h2 = __float2half_rn(a2), h3 = __float2half_rn(a3);
                *(__half2*)&qh[(size_t)row0 * CC + col] = __halves2half2(h0, h1);
                *(__half2*)&ql[(size_t)row0 * CC + col] =
                    __halves2half2(__float2half_rn(a0 - __half2float(h0)),
                                   __float2half_rn(a1 - __half2float(h1)));
                *(__half2*)&qh[(size_t)(row0 + 8) * CC + col] = __halves2half2(h2, h3);
                *(__half2*)&ql[(size_t)(row0 + 8) * CC + col] =
                    __halves2half2(__float2half_rn(a2 - __half2float(h2)),
                                   __float2half_rn(a3 - __half2float(h3)));
            } else {
                __half* Cf = (__half*)out0;
                *(__half2*)&Cf[(size_t)row0 * CC + col]       = __floats2half2_rn(a0, a1);
                *(__half2*)&Cf[(size_t)(row0 + 8) * CC + col] = __floats2half2_rn(a2, a3);
            }
        }
    }
}

__global__ __launch_bounds__(256, 2) void gemm_qkv(
    const __half* __restrict__ xh, const __half* __restrict__ xl,
    const __half* __restrict__ w16,
    __half* __restrict__ qh, __half* __restrict__ ql,
    __half* __restrict__ kf, __half* __restrict__ vf)
{
    extern __shared__ char smem[];
    const int wsel = blockIdx.x >> 3;
    const int n0 = (blockIdx.x & 7) * 128;
    const int m0 = blockIdx.y * 128;
    if (wsel == 0)
        gemm_tile(xh, xl, w16, qh, ql, 1, m0, n0, smem);
    else if (wsel == 1)
        gemm_tile(xh, xl, w16 + (size_t)CC * CC, kf, nullptr, 2, m0, n0, smem);
    else
        gemm_tile(xh, xl, w16 + 2 * (size_t)CC * CC, vf, nullptr, 2, m0, n0, smem);
}

__global__ __launch_bounds__(256, 2) void gemm_one(
    const __half* __restrict__ Ah, const __half* __restrict__ Al,
    const __half* __restrict__ B, float* __restrict__ C)
{
    extern __shared__ char smem[];
    gemm_tile(Ah, Al, B, C, nullptr, 0, blockIdx.y * 128, blockIdx.x * 128, smem);
}

// ---------------------------------------------------------------------------
// Tensor-core flash attention (causal), fp16 asymmetric 2-pass.
// 128 threads / 4 warps, 64 queries/CTA, 4 CTAs/SM (<=128 regs).
// All operand loads via ldmatrix; V loaded with ldmatrix.trans (stored [k][d]).
// SMEM: Qh, Ql, Kf, Vf — 4 x 64 x 72 fp16 = 36 KB.
// ---------------------------------------------------------------------------
#define AP 72
#define APB (AP * 2)          // 144 bytes per row
#define ATILE (64 * AP)

__global__ __launch_bounds__(128, 4) void attn_tc()
{
    extern __shared__ __half ash[];
    __half* Qh = ash;
    __half* Ql = Qh + ATILE;
    __half* Kf = Ql + ATILE;
    __half* Vf = Kf + ATILE;
    const uint32_t sQh = smem_u32(Qh), sQl = smem_u32(Ql);
    const uint32_t sKf = smem_u32(Kf), sVf = smem_u32(Vf);

    const int tid  = threadIdx.x;
    const int lane = tid & 31;
    const int w    = tid >> 5;            // 0..3
    const int qtile = blockIdx.x;         // 0..31
    const int bh = blockIdx.y;
    const int b = bh / HH, h = bh % HH;
    const int q0 = qtile * 64;

    const size_t hoff = (size_t)b * TT * CC + h * DD;
    const __half* qhp = g_qh + hoff;
    const __half* qlp = g_ql + hoff;
    const __half* kfp = g_kf + hoff;
    const __half* vfp = g_vf + hoff;

    // ---- load Q hi/lo (straight 16B copies) ----
#pragma unroll
    for (int it = 0; it < 4; it++) {
        int lin = tid + it * 128;       // 0..511
        int row = lin >> 3;             // 0..63
        int seg = lin & 7;
        uint4 vh = *(const uint4*)&qhp[(size_t)(q0 + row) * CC + seg * 8];
        uint4 vl = *(const uint4*)&qlp[(size_t)(q0 + row) * CC + seg * 8];
        *(uint4*)&Qh[row * AP + seg * 8] = vh;
        *(uint4*)&Ql[row * AP + seg * 8] = vl;
    }

    float m0r = -1e30f, m1r = -1e30f, l0r = 0.f, l1r = 0.f;
    float ofr[8][4];
#pragma unroll
    for (int j = 0; j < 8; j++)
#pragma unroll
        for (int r = 0; r < 4; r++) ofr[j][r] = 0.f;

    const int r0g = q0 + w * 16 + (lane >> 2);
    const int r1g = r0g + 8;

    // ldmatrix lane-address components
    const uint32_t a_row  = (uint32_t)(lane & 15);
    const uint32_t a_koff = (uint32_t)(lane >> 4) * 16u;
    const uint32_t b_row  = (uint32_t)(lane & 7);
    const uint32_t b_koff = (uint32_t)((lane >> 3) & 1) * 16u;
    const uint32_t v_row  = (uint32_t)(lane & 15);

    const int nkt = qtile + 1;
    for (int kt = 0; kt < nkt; kt++) {
        const int k0 = kt * 64;
        __syncthreads();
        // ---- load K and V (straight 16B copies; V transposed later by ldmatrix) ----
#pragma unroll
        for (int it = 0; it < 4; it++) {
            int lin = tid + it * 128;   // 0..511
            int row = lin >> 3;
            int seg = lin & 7;
            uint4 kv = *(const uint4*)&kfp[(size_t)(k0 + row) * CC + seg * 8];
            uint4 vv = *(const uint4*)&vfp[(size_t)(k0 + row) * CC + seg * 8];
            *(uint4*)&Kf[row * AP + seg * 8] = kv;
            *(uint4*)&Vf[row * AP + seg * 8] = vv;
        }
        __syncthreads();

        // ---- S = Q*K^T (2-pass fp16): s-outer so only current A-frags live ----
        float sfr[8][4];
#pragma unroll
        for (int j = 0; j < 8; j++)
#pragma unroll
            for (int r = 0; r < 4; r++) sfr[j][r] = 0.f;

#pragma unroll
        for (int s = 0; s < 4; s++) {
            const uint32_t ko = (uint32_t)s * 32u;
            uint32_t aqh[4], aql[4];
            uint32_t ra = (uint32_t)(w * 16) * APB + a_row * APB + ko + a_koff;
            ldm_x4(aqh, sQh + ra);
            ldm_x4(aql, sQl + ra);
#pragma unroll
            for (int j = 0; j < 8; j++) {
                uint32_t rb = (uint32_t)(j * 8) * APB + b_row * APB + ko + b_koff;
                uint32_t bkf[2];
                ldm_x2(bkf, sKf + rb);
                mma_f16(sfr[j], aqh, bkf);
                mma_f16(sfr[j], aql, bkf);
            }
        }

        // ---- causal mask on diagonal tile ----
        if (kt == qtile) {
#pragma unroll
            for (int j = 0; j < 8; j++) {
                int cbase = k0 + j * 8 + 2 * (lane & 3);
                if (cbase > r0g)     sfr[j][0] = -1e30f;
                if (cbase + 1 > r0g) sfr[j][1] = -1e30f;
                if (cbase > r1g)     sfr[j][2] = -1e30f;
                if (cbase + 1 > r1g) sfr[j][3] = -1e30f;
            }
        }

        // ---- online softmax ----
        float mx0 = -1e30f, mx1 = -1e30f;
#pragma unroll
        for (int j = 0; j < 8; j++) {
            mx0 = fmaxf(mx0, fmaxf(sfr[j][0], sfr[j][1]));
            mx1 = fmaxf(mx1, fmaxf(sfr[j][2], sfr[j][3]));
        }
        mx0 = fmaxf(mx0, __shfl_xor_sync(0xffffffffu, mx0, 1));
        mx0 = fmaxf(mx0, __shfl_xor_sync(0xffffffffu, mx0, 2));
        mx1 = fmaxf(mx1, __shfl_xor_sync(0xffffffffu, mx1, 1));
        mx1 = fmaxf(mx1, __shfl_xor_sync(0xffffffffu, mx1, 2));

        float mn0 = fmaxf(m0r, mx0), mn1 = fmaxf(m1r, mx1);
        float corr0 = __expf(m0r - mn0), corr1 = __expf(m1r - mn1);
        m0r = mn0; m1r = mn1;

        float rs0 = 0.f, rs1 = 0.f;
#pragma unroll
        for (int j = 0; j < 8; j++) {
            sfr[j][0] = __expf(sfr[j][0] - mn0);
            sfr[j][1] = __expf(sfr[j][1] - mn0);
            sfr[j][2] = __expf(sfr[j][2] - mn1);
            sfr[j][3] = __expf(sfr[j][3] - mn1);
            rs0 += sfr[j][0] + sfr[j][1];
            rs1 += sfr[j][2] + sfr[j][3];
        }
        rs0 += __shfl_xor_sync(0xffffffffu, rs0, 1);
        rs0 += __shfl_xor_sync(0xffffffffu, rs0, 2);
        rs1 += __shfl_xor_sync(0xffffffffu, rs1, 1);
        rs1 += __shfl_xor_sync(0xffffffffu, rs1, 2);
        l0r = l0r * corr0 + rs0;
        l1r = l1r * corr1 + rs1;

#pragma unroll
        for (int j = 0; j < 8; j++) {
            ofr[j][0] *= corr0; ofr[j][1] *= corr0;
            ofr[j][2] *= corr1; ofr[j][3] *= corr1;
        }

        // ---- pack P to fp16 hi/lo A-fragments (indexed by k16-step s) ----
        uint32_t pah[4][4], pal[4][4];
#pragma unroll
        for (int s = 0; s < 4; s++) {
            const int ja = 2 * s, jb = 2 * s + 1;
            float p[8] = { sfr[ja][0], sfr[ja][1], sfr[ja][2], sfr[ja][3],
                           sfr[jb][0], sfr[jb][1], sfr[jb][2], sfr[jb][3] };
            __half phh[8];
            float pl[8];
#pragma unroll
            for (int e = 0; e < 8; e++) {
                phh[e] = __float2half_rn(p[e]);
                pl[e] = p[e] - __half2float(phh[e]);
            }
            pah[s][0] = pack_f16x2(__half2float(phh[0]), __half2float(phh[1]));
            pah[s][1] = pack_f16x2(__half2float(phh[2]), __half2float(phh[3]));
            pah[s][2] = pack_f16x2(__half2float(phh[4]), __half2float(phh[5]));
            pah[s][3] = pack_f16x2(__half2float(phh[6]), __half2float(phh[7]));
            pal[s][0] = pack_f16x2(pl[0], pl[1]);
            pal[s][1] = pack_f16x2(pl[2], pl[3]);
            pal[s][2] = pack_f16x2(pl[4], pl[5]);
            pal[s][3] = pack_f16x2(pl[6], pl[7]);
        }

        // ---- O += P*V (2-pass fp16), V B-frags via ldmatrix.trans ----
#pragma unroll
        for (int j = 0; j < 8; j++) {          // j = d-group (output cols j*8..+7)
#pragma unroll
            for (int s = 0; s < 4; s++) {      // s = k16-step
                uint32_t rv = (uint32_t)(s * 16 + v_row) * APB + (uint32_t)j * 16u;
                uint32_t bvf[2];
                ldm_x2t(bvf, sVf + rv);
                mma_f16(ofr[j], pah[s], bvf);
                mma_f16(ofr[j], pal[s], bvf);
            }
        }
    }

    // ---- epilogue: normalize, split fp16 hi/lo for WO GEMM ----
    float inv0 = 1.f / l0r, inv1 = 1.f / l1r;
    __half* ahp = g_ah + hoff;
    __half* alp = g_al + hoff;
#pragma unroll
    for (int j = 0; j < 8; j++) {
        int col = j * 8 + 2 * (lane & 3);
        float v0 = ofr[j][0] * inv0, v1 = ofr[j][1] * inv0;
        float v2 = ofr[j][2] * inv1, v3 = ofr[j][3] * inv1;
        __half h0 = __float2half_rn(v0), h1 = __float2half_rn(v1);
        __half h2 = __float2half_rn(v2), h3 = __float2half_rn(v3);
        *(__half2*)&ahp[(size_t)r0g * CC + col] = __halves2half2(h0, h1);
        *(__half2*)&alp[(size_t)r0g * CC + col] =
            __halves2half2(__float2half_rn(v0 - __half2float(h0)),
                           __float2half_rn(v1 - __half2float(h1)));
        *(__half2*)&ahp[(size_t)r1g * CC + col] = __halves2half2(h2, h3);
        *(__half2*)&alp[(size_t)r1g * CC + col] =
            __halves2half2(__float2half_rn(v2 - __half2float(h2)),
                           __float2half_rn(v3 - __half2float(h3)));
    }
}

// ---------------------------------------------------------------------------
extern "C" void kernel_launch(void* const* d_in, const int* in_sizes, int n_in,
                              void* d_out, int out_size)
{
    const float* x   = (const float*)d_in[0];
    const float* W_Q = (const float*)d_in[1];
    const float* W_K = (const float*)d_in[2];
    const float* W_V = (const float*)d_in[3];
    const float* W_O = (const float*)d_in[4];
    float* out = (float*)d_out;

    __half *xh, *xl, *qh, *ql, *kf, *vf, *ah, *al, *w16;
    cudaGetSymbolAddress((void**)&xh,  g_xh);
    cudaGetSymbolAddress((void**)&xl,  g_xl);
    cudaGetSymbolAddress((void**)&qh,  g_qh);
    cudaGetSymbolAddress((void**)&ql,  g_ql);
    cudaGetSymbolAddress((void**)&kf,  g_kf);
    cudaGetSymbolAddress((void**)&vf,  g_vf);
    cudaGetSymbolAddress((void**)&ah,  g_ah);
    cudaGetSymbolAddress((void**)&al,  g_al);
    cudaGetSymbolAddress((void**)&w16, g_w16);

    const int gemm_smem = NSTAGE * (int)STAGEB;   // 110592 -> 2 CTAs/SM
    cudaFuncSetAttribute(gemm_qkv,
                         cudaFuncAttributeMaxDynamicSharedMemorySize, gemm_smem);
    cudaFuncSetAttribute(gemm_one,
                         cudaFuncAttributeMaxDynamicSharedMemorySize, gemm_smem);
    const int attn_smem = 4 * ATILE * (int)sizeof(__half);   // 36864 -> 4 CTAs/SM
    cudaFuncSetAttribute(attn_tc,
                         cudaFuncAttributeMaxDynamicSharedMemorySize, attn_smem);

    {
        int n4 = MM * CC / 4;
        split16_kernel<<<(n4 + 255) / 256, 256>>>(x, xh, xl, n4);
        int w4 = CC * CC / 4;
        dim3 wg((w4 + 255) / 256, 4);
        conv16x4_kernel<<<wg, 256>>>(W_Q, W_K, W_V, W_O, w16, w4);
    }

    dim3 qkvgrid(24, MM / 128);   // (24, 64)
    gemm_qkv<<<qkvgrid, 256, gemm_smem>>>(xh, xl, w16, qh, ql, kf, vf);

    dim3 agrid(TT / 64, BB * HH);   // (32, 64)
    attn_tc<<<agrid, 128, attn_smem>>>();

    dim3 ogrid(CC / 128, MM / 128);
    gemm_one<<<ogrid, 256, gemm_smem>>>(ah, al, w16 + 3 * (size_t)CC * CC, out);
}

// round 13
// speedup vs baseline: 2.4563x; 1.2090x over previous
#include <cuda_runtime.h>
#include <cuda_bf16.h>
#include <cuda_fp16.h>
#include <math.h>
#include <stdint.h>

#define BB 4
#define TT 2048
#define CC 1024
#define HH 16
#define DD 64
#define MM (BB*TT)   // 8192

// ---------------------------------------------------------------------------
// Scratch (device globals; no allocation allowed)
// ---------------------------------------------------------------------------
__device__ __half g_xh[MM * CC];
__device__ __half g_xl[MM * CC];
__device__ __half g_qh[MM * CC];   // Q scaled 1/8, hi plane
__device__ __half g_ql[MM * CC];   // Q scaled 1/8, lo plane
__device__ __half g_kf[MM * CC];   // K fp16
__device__ __half g_vf[MM * CC];   // V fp16
__device__ __half g_af[MM * CC];   // attn-out fp16
__device__ __half g_w16[4 * CC * CC];

// ---------------------------------------------------------------------------
__device__ __forceinline__ uint32_t smem_u32(const void* p) {
    uint32_t a;
    asm("{ .reg .u64 t; cvta.to.shared.u64 t, %1; cvt.u32.u64 %0, t; }"
        : "=r"(a) : "l"(p));
    return a;
}

__device__ __forceinline__ void cp16(uint32_t dst, const void* src) {
    asm volatile("cp.async.cg.shared.global [%0], [%1], 16;"
                 :: "r"(dst), "l"(src) : "memory");
}
#define CP_COMMIT() asm volatile("cp.async.commit_group;" ::: "memory")
#define CP_WAIT(n)  asm volatile("cp.async.wait_group %0;" :: "n"(n) : "memory")

__device__ __forceinline__ void mma_f16(float* d, const uint32_t* a, const uint32_t* b) {
    asm volatile(
        "mma.sync.aligned.m16n8k16.row.col.f32.f16.f16.f32 "
        "{%0,%1,%2,%3}, {%4,%5,%6,%7}, {%8,%9}, {%0,%1,%2,%3};"
        : "+f"(d[0]), "+f"(d[1]), "+f"(d[2]), "+f"(d[3])
        : "r"(a[0]), "r"(a[1]), "r"(a[2]), "r"(a[3]), "r"(b[0]), "r"(b[1]));
}

__device__ __forceinline__ void ldm_x4(uint32_t* r, uint32_t addr) {
    asm volatile("ldmatrix.sync.aligned.m8n8.x4.shared.b16 {%0,%1,%2,%3}, [%4];"
                 : "=r"(r[0]), "=r"(r[1]), "=r"(r[2]), "=r"(r[3]) : "r"(addr));
}
__device__ __forceinline__ void ldm_x2(uint32_t* r, uint32_t addr) {
    asm volatile("ldmatrix.sync.aligned.m8n8.x2.shared.b16 {%0,%1}, [%2];"
                 : "=r"(r[0]), "=r"(r[1]) : "r"(addr));
}
__device__ __forceinline__ void ldm_x2t(uint32_t* r, uint32_t addr) {
    asm volatile("ldmatrix.sync.aligned.m8n8.x2.trans.shared.b16 {%0,%1}, [%2];"
                 : "=r"(r[0]), "=r"(r[1]) : "r"(addr));
}

__device__ __forceinline__ uint32_t pack_f16x2(float lo, float hi) {
    __half2 hv = __floats2half2_rn(lo, hi);
    return *(uint32_t*)&hv;
}

// ---------------------------------------------------------------------------
// Conversion kernels
// ---------------------------------------------------------------------------
__global__ void conv16x4_kernel(const float* __restrict__ w0,
                                const float* __restrict__ w1,
                                const float* __restrict__ w2,
                                const float* __restrict__ w3,
                                __half* __restrict__ out, int n4)
{
    int i = blockIdx.x * blockDim.x + threadIdx.x;
    if (i >= n4) return;
    const float* src = (blockIdx.y == 0) ? w0 : (blockIdx.y == 1) ? w1
                     : (blockIdx.y == 2) ? w2 : w3;
    float4 v = ((const float4*)src)[i];
    __half2* op = (__half2*)(out + (size_t)blockIdx.y * CC * CC);
    op[2 * i + 0] = __floats2half2_rn(v.x, v.y);
    op[2 * i + 1] = __floats2half2_rn(v.z, v.w);
}

__global__ void split16_kernel(const float* __restrict__ in,
                               __half* __restrict__ hi,
                               __half* __restrict__ lo, int n4)
{
    int i = blockIdx.x * blockDim.x + threadIdx.x;
    if (i >= n4) return;
    float4 v = ((const float4*)in)[i];
    __half h0 = __float2half_rn(v.x);
    __half h1 = __float2half_rn(v.y);
    __half h2 = __float2half_rn(v.z);
    __half h3 = __float2half_rn(v.w);
    __half l0 = __float2half_rn(v.x - __half2float(h0));
    __half l1 = __float2half_rn(v.y - __half2float(h1));
    __half l2 = __float2half_rn(v.z - __half2float(h2));
    __half l3 = __float2half_rn(v.w - __half2float(h3));
    __half2* hp = (__half2*)hi;
    __half2* lp = (__half2*)lo;
    hp[2 * i + 0] = __halves2half2(h0, h1);
    hp[2 * i + 1] = __halves2half2(h2, h3);
    lp[2 * i + 0] = __halves2half2(l0, l1);
    lp[2 * i + 1] = __halves2half2(l2, l3);
}

// ---------------------------------------------------------------------------
// Core GEMM tile: C[128,128] = A[M,K] x W[N,K]^T
// TWO=true : fp16 asymmetric 2-pass (A = Ah + Al), 3 SMEM tiles/stage.
// TWO=false: single-pass fp16 (A = Ah only), 2 SMEM tiles/stage.
// BK=64, 2-stage cp.async ring, 2 CTAs/SM.
// Epilogue modes: 0 = fp32 C; 1 = fp16 hi/lo scaled 1/8 (Q); 2 = fp16 (K/V).
// ---------------------------------------------------------------------------
#define ROWB 144u
#define TILEB (128u*ROWB)        // 18432
#define STAGEB (3u*TILEB)        // 55296
#define NSTAGE 2
#define NCHUNK (CC/64)           // 16

template<bool TWO>
__device__ __forceinline__ void gemm_tile(
    const __half* __restrict__ Ah, const __half* __restrict__ Al,
    const __half* __restrict__ B,
    void* out0, void* out1, int mode,
    int m0, int n0, char* smem)
{
    const uint32_t sb = smem_u32(smem);
    const int tid  = threadIdx.x;
    const int lane = tid & 31;
    const int wid  = tid >> 5;
    const int wm   = wid >> 1;
    const int wn   = wid & 1;

    const __half* srcA0 = Ah + (size_t)m0 * CC;
    const __half* srcA1 = TWO ? (Al + (size_t)m0 * CC) : nullptr;
    const __half* srcB  = B + (size_t)n0 * CC;

    auto issue_stage = [&](int chunk, int stage) {
        const int kc = chunk * 64;
        const uint32_t base = sb + (uint32_t)stage * STAGEB;
        const int NT = TWO ? 12 : 8;
#pragma unroll
        for (int t = 0; t < NT; t++) {
            int lin  = tid + t * 256;
            int tile = lin >> 10;            // 0..2 (TWO) or 0..1
            int idx  = lin & 1023;
            int row  = idx >> 3;
            int seg  = idx & 7;
            const __half* src;
            uint32_t slot;
            if (TWO) {
                src  = (tile == 0) ? srcA0 : (tile == 1) ? srcA1 : srcB;
                slot = (uint32_t)tile;
            } else {
                src  = (tile == 0) ? srcA0 : srcB;
                slot = (tile == 0) ? 0u : 2u;
            }
            uint32_t dst = base + slot * TILEB + (uint32_t)row * ROWB + (uint32_t)seg * 16u;
            cp16(dst, src + (size_t)row * CC + kc + seg * 8);
        }
        CP_COMMIT();
    };

    float acc[2][8][4];
#pragma unroll
    for (int i = 0; i < 2; i++)
#pragma unroll
        for (int j = 0; j < 8; j++)
#pragma unroll
            for (int r = 0; r < 4; r++) acc[i][j][r] = 0.f;

    issue_stage(0, 0);

    const uint32_t a_row  = (uint32_t)(lane & 15);
    const uint32_t a_koff = (uint32_t)(lane >> 4) * 16u;
    const uint32_t b_row  = (uint32_t)(lane & 7);
    const uint32_t b_koff = (uint32_t)((lane >> 3) & 1) * 16u;

    for (int c = 0; c < NCHUNK; c++) {
        const int stage = c & 1;
        if (c + 1 < NCHUNK) { issue_stage(c + 1, stage ^ 1); CP_WAIT(1); }
        else                { CP_WAIT(0); }
        __syncthreads();

        const uint32_t base  = sb + (uint32_t)stage * STAGEB;
        const uint32_t Aho   = base;
        const uint32_t Alo_o = base + TILEB;
        const uint32_t Bo    = base + 2u * TILEB;

#pragma unroll
        for (int kk = 0; kk < 4; kk++) {
            const uint32_t ko = (uint32_t)kk * 32u;
            uint32_t ah[2][4], al[2][4];
#pragma unroll
            for (int fi = 0; fi < 2; fi++) {
                uint32_t ra = (uint32_t)(wm * 32 + fi * 16) * ROWB + a_row * ROWB + ko + a_koff;
                ldm_x4(ah[fi], Aho + ra);
                if (TWO) ldm_x4(al[fi], Alo_o + ra);
            }
#pragma unroll
            for (int j = 0; j < 8; j++) {
                uint32_t rb = (uint32_t)(wn * 64 + j * 8) * ROWB + b_row * ROWB + ko + b_koff;
                uint32_t bf[2];
                ldm_x2(bf, Bo + rb);
#pragma unroll
                for (int fi = 0; fi < 2; fi++) {
                    mma_f16(acc[fi][j], ah[fi], bf);
                    if (TWO) mma_f16(acc[fi][j], al[fi], bf);
                }
            }
        }
        __syncthreads();
    }

#pragma unroll
    for (int fi = 0; fi < 2; fi++) {
        int row0 = m0 + wm * 32 + fi * 16 + (lane >> 2);
#pragma unroll
        for (int j = 0; j < 8; j++) {
            int col = n0 + wn * 64 + j * 8 + (lane & 3) * 2;
            float a0 = acc[fi][j][0], a1 = acc[fi][j][1];
            float a2 = acc[fi][j][2], a3 = acc[fi][j][3];
            if (mode == 0) {
                float* C = (float*)out0;
                *(float2*)&C[(size_t)row0 * CC + col]       = make_float2(a0, a1);
                *(float2*)&C[(size_t)(row0 + 8) * CC + col] = make_float2(a2, a3);
            } else if (mode == 1) {
                __half* qh = (__half*)out0;
                __half* ql = (__half*)out1;
                a0 *= 0.125f; a1 *= 0.125f; a2 *= 0.125f; a3 *= 0.125f;
                __half h0 = __float2half_rn(a0), h1 = __float2half_rn(a1);
                __half h2 = __float2half_rn(a2), h3 = __float2half_rn(a3);
                *(__half2*)&qh[(size_t)row0 * CC + col] = __halves2half2(h0, h1);
                *(__half2*)&ql[(size_t)row0 * CC + col] =
                    __halves2half2(__float2half_rn(a0 - __half2float(h0)),
                                   __float2half_rn(a1 - __half2float(h1)));
                *(__half2*)&qh[(size_t)(row0 + 8) * CC + col] = __halves2half2(h2, h3);
                *(__half2*)&ql[(size_t)(row0 + 8) * CC + col] =
                    __halves2half2(__float2half_rn(a2 - __half2float(h2)),
                                   __float2half_rn(a3 - __half2float(h3)));
            } else {
                __half* Cf = (__half*)out0;
                *(__half2*)&Cf[(size_t)row0 * CC + col]       = __floats2half2_rn(a0, a1);
                *(__half2*)&Cf[(size_t)(row0 + 8) * CC + col] = __floats2half2_rn(a2, a3);
            }
        }
    }
}

// Fused QKV: grid.x in [0,24): wsel = x>>3, n0 = (x&7)*128
// Q, K: 2-pass (score path). V: single-pass (value path).
__global__ __launch_bounds__(256, 2) void gemm_qkv(
    const __half* __restrict__ xh, const __half* __restrict__ xl,
    const __half* __restrict__ w16,
    __half* __restrict__ qh, __half* __restrict__ ql,
    __half* __restrict__ kf, __half* __restrict__ vf)
{
    extern __shared__ char smem[];
    const int wsel = blockIdx.x >> 3;
    const int n0 = (blockIdx.x & 7) * 128;
    const int m0 = blockIdx.y * 128;
    if (wsel == 0)
        gemm_tile<true>(xh, xl, w16, qh, ql, 1, m0, n0, smem);
    else if (wsel == 1)
        gemm_tile<true>(xh, xl, w16 + (size_t)CC * CC, kf, nullptr, 2, m0, n0, smem);
    else
        gemm_tile<false>(xh, nullptr, w16 + 2 * (size_t)CC * CC, vf, nullptr, 2, m0, n0, smem);
}

// Output projection: single-pass fp16 (value path).
__global__ __launch_bounds__(256, 2) void gemm_one(
    const __half* __restrict__ Af,
    const __half* __restrict__ B, float* __restrict__ C)
{
    extern __shared__ char smem[];
    gemm_tile<false>(Af, nullptr, B, C, nullptr, 0, blockIdx.y * 128, blockIdx.x * 128, smem);
}

// ---------------------------------------------------------------------------
// Tensor-core flash attention (causal).
// S = (Qh+Ql)*K^T (2-pass); O = P*V (single-pass, value path).
// 128 threads / 4 warps, 64 queries/CTA, 4 CTAs/SM.
// SMEM: Qh, Ql, Kf, Vf — 4 x 64 x 72 fp16 = 36 KB.
// ---------------------------------------------------------------------------
#define AP 72
#define APB (AP * 2)          // 144 bytes per row
#define ATILE (64 * AP)

__global__ __launch_bounds__(128, 4) void attn_tc()
{
    extern __shared__ __half ash[];
    __half* Qh = ash;
    __half* Ql = Qh + ATILE;
    __half* Kf = Ql + ATILE;
    __half* Vf = Kf + ATILE;
    const uint32_t sQh = smem_u32(Qh), sQl = smem_u32(Ql);
    const uint32_t sKf = smem_u32(Kf), sVf = smem_u32(Vf);

    const int tid  = threadIdx.x;
    const int lane = tid & 31;
    const int w    = tid >> 5;            // 0..3
    const int qtile = blockIdx.x;         // 0..31
    const int bh = blockIdx.y;
    const int b = bh / HH, h = bh % HH;
    const int q0 = qtile * 64;

    const size_t hoff = (size_t)b * TT * CC + h * DD;
    const __half* qhp = g_qh + hoff;
    const __half* qlp = g_ql + hoff;
    const __half* kfp = g_kf + hoff;
    const __half* vfp = g_vf + hoff;

    // ---- load Q hi/lo (straight 16B copies) ----
#pragma unroll
    for (int it = 0; it < 4; it++) {
        int lin = tid + it * 128;       // 0..511
        int row = lin >> 3;             // 0..63
        int seg = lin & 7;
        uint4 vh = *(const uint4*)&qhp[(size_t)(q0 + row) * CC + seg * 8];
        uint4 vl = *(const uint4*)&qlp[(size_t)(q0 + row) * CC + seg * 8];
        *(uint4*)&Qh[row * AP + seg * 8] = vh;
        *(uint4*)&Ql[row * AP + seg * 8] = vl;
    }

    float m0r = -1e30f, m1r = -1e30f, l0r = 0.f, l1r = 0.f;
    float ofr[8][4];
#pragma unroll
    for (int j = 0; j < 8; j++)
#pragma unroll
        for (int r = 0; r < 4; r++) ofr[j][r] = 0.f;

    const int r0g = q0 + w * 16 + (lane >> 2);
    const int r1g = r0g + 8;

    const uint32_t a_row  = (uint32_t)(lane & 15);
    const uint32_t a_koff = (uint32_t)(lane >> 4) * 16u;
    const uint32_t b_row  = (uint32_t)(lane & 7);
    const uint32_t b_koff = (uint32_t)((lane >> 3) & 1) * 16u;
    const uint32_t v_row  = (uint32_t)(lane & 15);

    const int nkt = qtile + 1;
    for (int kt = 0; kt < nkt; kt++) {
        const int k0 = kt * 64;
        __syncthreads();
#pragma unroll
        for (int it = 0; it < 4; it++) {
            int lin = tid + it * 128;   // 0..511
            int row = lin >> 3;
            int seg = lin & 7;
            uint4 kv = *(const uint4*)&kfp[(size_t)(k0 + row) * CC + seg * 8];
            uint4 vv = *(const uint4*)&vfp[(size_t)(k0 + row) * CC + seg * 8];
            *(uint4*)&Kf[row * AP + seg * 8] = kv;
            *(uint4*)&Vf[row * AP + seg * 8] = vv;
        }
        __syncthreads();

        // ---- S = Q*K^T (2-pass fp16) ----
        float sfr[8][4];
#pragma unroll
        for (int j = 0; j < 8; j++)
#pragma unroll
            for (int r = 0; r < 4; r++) sfr[j][r] = 0.f;

#pragma unroll
        for (int s = 0; s < 4; s++) {
            const uint32_t ko = (uint32_t)s * 32u;
            uint32_t aqh[4], aql[4];
            uint32_t ra = (uint32_t)(w * 16) * APB + a_row * APB + ko + a_koff;
            ldm_x4(aqh, sQh + ra);
            ldm_x4(aql, sQl + ra);
#pragma unroll
            for (int j = 0; j < 8; j++) {
                uint32_t rb = (uint32_t)(j * 8) * APB + b_row * APB + ko + b_koff;
                uint32_t bkf[2];
                ldm_x2(bkf, sKf + rb);
                mma_f16(sfr[j], aqh, bkf);
                mma_f16(sfr[j], aql, bkf);
            }
        }

        // ---- causal mask on diagonal tile ----
        if (kt == qtile) {
#pragma unroll
            for (int j = 0; j < 8; j++) {
                int cbase = k0 + j * 8 + 2 * (lane & 3);
                if (cbase > r0g)     sfr[j][0] = -1e30f;
                if (cbase + 1 > r0g) sfr[j][1] = -1e30f;
                if (cbase > r1g)     sfr[j][2] = -1e30f;
                if (cbase + 1 > r1g) sfr[j][3] = -1e30f;
            }
        }

        // ---- online softmax ----
        float mx0 = -1e30f, mx1 = -1e30f;
#pragma unroll
        for (int j = 0; j < 8; j++) {
            mx0 = fmaxf(mx0, fmaxf(sfr[j][0], sfr[j][1]));
            mx1 = fmaxf(mx1, fmaxf(sfr[j][2], sfr[j][3]));
        }
        mx0 = fmaxf(mx0, __shfl_xor_sync(0xffffffffu, mx0, 1));
        mx0 = fmaxf(mx0, __shfl_xor_sync(0xffffffffu, mx0, 2));
        mx1 = fmaxf(mx1, __shfl_xor_sync(0xffffffffu, mx1, 1));
        mx1 = fmaxf(mx1, __shfl_xor_sync(0xffffffffu, mx1, 2));

        float mn0 = fmaxf(m0r, mx0), mn1 = fmaxf(m1r, mx1);
        float corr0 = __expf(m0r - mn0), corr1 = __expf(m1r - mn1);
        m0r = mn0; m1r = mn1;

        float rs0 = 0.f, rs1 = 0.f;
#pragma unroll
        for (int j = 0; j < 8; j++) {
            sfr[j][0] = __expf(sfr[j][0] - mn0);
            sfr[j][1] = __expf(sfr[j][1] - mn0);
            sfr[j][2] = __expf(sfr[j][2] - mn1);
            sfr[j][3] = __expf(sfr[j][3] - mn1);
            rs0 += sfr[j][0] + sfr[j][1];
            rs1 += sfr[j][2] + sfr[j][3];
        }
        rs0 += __shfl_xor_sync(0xffffffffu, rs0, 1);
        rs0 += __shfl_xor_sync(0xffffffffu, rs0, 2);
        rs1 += __shfl_xor_sync(0xffffffffu, rs1, 1);
        rs1 += __shfl_xor_sync(0xffffffffu, rs1, 2);
        l0r = l0r * corr0 + rs0;
        l1r = l1r * corr1 + rs1;

#pragma unroll
        for (int j = 0; j < 8; j++) {
            ofr[j][0] *= corr0; ofr[j][1] *= corr0;
            ofr[j][2] *= corr1; ofr[j][3] *= corr1;
        }

        // ---- pack P to fp16 A-fragments (single plane) ----
        uint32_t pah[4][4];
#pragma unroll
        for (int s = 0; s < 4; s++) {
            const int ja = 2 * s, jb = 2 * s + 1;
            pah[s][0] = pack_f16x2(sfr[ja][0], sfr[ja][1]);
            pah[s][1] = pack_f16x2(sfr[ja][2], sfr[ja][3]);
            pah[s][2] = pack_f16x2(sfr[jb][0], sfr[jb][1]);
            pah[s][3] = pack_f16x2(sfr[jb][2], sfr[jb][3]);
        }

        // ---- O += P*V (single-pass fp16), V B-frags via ldmatrix.trans ----
#pragma unroll
        for (int j = 0; j < 8; j++) {
#pragma unroll
            for (int s = 0; s < 4; s++) {
                uint32_t rv = (uint32_t)(s * 16 + v_row) * APB + (uint32_t)j * 16u;
                uint32_t bvf[2];
                ldm_x2t(bvf, sVf + rv);
                mma_f16(ofr[j], pah[s], bvf);
            }
        }
    }

    // ---- epilogue: normalize, single fp16 plane for WO GEMM ----
    float inv0 = 1.f / l0r, inv1 = 1.f / l1r;
    __half* afp = g_af + hoff;
#pragma unroll
    for (int j = 0; j < 8; j++) {
        int col = j * 8 + 2 * (lane & 3);
        *(__half2*)&afp[(size_t)r0g * CC + col] =
            __floats2half2_rn(ofr[j][0] * inv0, ofr[j][1] * inv0);
        *(__half2*)&afp[(size_t)r1g * CC + col] =
            __floats2half2_rn(ofr[j][2] * inv1, ofr[j][3] * inv1);
    }
}

// ---------------------------------------------------------------------------
extern "C" void kernel_launch(void* const* d_in, const int* in_sizes, int n_in,
                              void* d_out, int out_size)
{
    const float* x   = (const float*)d_in[0];
    const float* W_Q = (const float*)d_in[1];
    const float* W_K = (const float*)d_in[2];
    const float* W_V = (const float*)d_in[3];
    const float* W_O = (const float*)d_in[4];
    float* out = (float*)d_out;

    __half *xh, *xl, *qh, *ql, *kf, *vf, *af, *w16;
    cudaGetSymbolAddress((void**)&xh,  g_xh);
    cudaGetSymbolAddress((void**)&xl,  g_xl);
    cudaGetSymbolAddress((void**)&qh,  g_qh);
    cudaGetSymbolAddress((void**)&ql,  g_ql);
    cudaGetSymbolAddress((void**)&kf,  g_kf);
    cudaGetSymbolAddress((void**)&vf,  g_vf);
    cudaGetSymbolAddress((void**)&af,  g_af);
    cudaGetSymbolAddress((void**)&w16, g_w16);

    const int gemm_smem = NSTAGE * (int)STAGEB;   // 110592 -> 2 CTAs/SM
    cudaFuncSetAttribute(gemm_qkv,
                         cudaFuncAttributeMaxDynamicSharedMemorySize, gemm_smem);
    cudaFuncSetAttribute(gemm_one,
                         cudaFuncAttributeMaxDynamicSharedMemorySize, gemm_smem);
    const int attn_smem = 4 * ATILE * (int)sizeof(__half);   // 36864 -> 4 CTAs/SM
    cudaFuncSetAttribute(attn_tc,
                         cudaFuncAttributeMaxDynamicSharedMemorySize, attn_smem);

    {
        int n4 = MM * CC / 4;
        split16_kernel<<<(n4 + 255) / 256, 256>>>(x, xh, xl, n4);
        int w4 = CC * CC / 4;
        dim3 wg((w4 + 255) / 256, 4);
        conv16x4_kernel<<<wg, 256>>>(W_Q, W_K, W_V, W_O, w16, w4);
    }

    dim3 qkvgrid(24, MM / 128);   // (24, 64)
    gemm_qkv<<<qkvgrid, 256, gemm_smem>>>(xh, xl, w16, qh, ql, kf, vf);

    dim3 agrid(TT / 64, BB * HH);   // (32, 64)
    attn_tc<<<agrid, 128, attn_smem>>>();

    dim3 ogrid(CC / 128, MM / 128);
    gemm_one<<<ogrid, 256, gemm_smem>>>(af, w16 + 3 * (size_t)CC * CC, out);
}

// round 14
// speedup vs baseline: 2.6577x; 1.0820x over previous
#include <cuda_runtime.h>
#include <cuda_bf16.h>
#include <cuda_fp16.h>
#include <math.h>
#include <stdint.h>

#define BB 4
#define TT 2048
#define CC 1024
#define HH 16
#define DD 64
#define MM (BB*TT)   // 8192

// ---------------------------------------------------------------------------
// Scratch (device globals; no allocation allowed)
// ---------------------------------------------------------------------------
__device__ __half g_xh[MM * CC];
__device__ __half g_xl[MM * CC];
__device__ __half g_qf[MM * CC];   // Q scaled 1/8, fp16
__device__ __half g_kf[MM * CC];   // K fp16
__device__ __half g_vf[MM * CC];   // V fp16
__device__ __half g_af[MM * CC];   // attn-out fp16
__device__ __half g_w16[4 * CC * CC];

// ---------------------------------------------------------------------------
__device__ __forceinline__ uint32_t smem_u32(const void* p) {
    uint32_t a;
    asm("{ .reg .u64 t; cvta.to.shared.u64 t, %1; cvt.u32.u64 %0, t; }"
        : "=r"(a) : "l"(p));
    return a;
}

__device__ __forceinline__ void cp16(uint32_t dst, const void* src) {
    asm volatile("cp.async.cg.shared.global [%0], [%1], 16;"
                 :: "r"(dst), "l"(src) : "memory");
}
#define CP_COMMIT() asm volatile("cp.async.commit_group;" ::: "memory")
#define CP_WAIT(n)  asm volatile("cp.async.wait_group %0;" :: "n"(n) : "memory")

__device__ __forceinline__ void mma_f16(float* d, const uint32_t* a, const uint32_t* b) {
    asm volatile(
        "mma.sync.aligned.m16n8k16.row.col.f32.f16.f16.f32 "
        "{%0,%1,%2,%3}, {%4,%5,%6,%7}, {%8,%9}, {%0,%1,%2,%3};"
        : "+f"(d[0]), "+f"(d[1]), "+f"(d[2]), "+f"(d[3])
        : "r"(a[0]), "r"(a[1]), "r"(a[2]), "r"(a[3]), "r"(b[0]), "r"(b[1]));
}

__device__ __forceinline__ void ldm_x4(uint32_t* r, uint32_t addr) {
    asm volatile("ldmatrix.sync.aligned.m8n8.x4.shared.b16 {%0,%1,%2,%3}, [%4];"
                 : "=r"(r[0]), "=r"(r[1]), "=r"(r[2]), "=r"(r[3]) : "r"(addr));
}
__device__ __forceinline__ void ldm_x2(uint32_t* r, uint32_t addr) {
    asm volatile("ldmatrix.sync.aligned.m8n8.x2.shared.b16 {%0,%1}, [%2];"
                 : "=r"(r[0]), "=r"(r[1]) : "r"(addr));
}
__device__ __forceinline__ void ldm_x4t(uint32_t* r, uint32_t addr) {
    asm volatile("ldmatrix.sync.aligned.m8n8.x4.trans.shared.b16 {%0,%1,%2,%3}, [%4];"
                 : "=r"(r[0]), "=r"(r[1]), "=r"(r[2]), "=r"(r[3]) : "r"(addr));
}

__device__ __forceinline__ uint32_t pack_f16x2(float lo, float hi) {
    __half2 hv = __floats2half2_rn(lo, hi);
    return *(uint32_t*)&hv;
}

// ---------------------------------------------------------------------------
// Conversion kernels
// ---------------------------------------------------------------------------
__global__ void conv16x4_kernel(const float* __restrict__ w0,
                                const float* __restrict__ w1,
                                const float* __restrict__ w2,
                                const float* __restrict__ w3,
                                __half* __restrict__ out, int n4)
{
    int i = blockIdx.x * blockDim.x + threadIdx.x;
    if (i >= n4) return;
    const float* src = (blockIdx.y == 0) ? w0 : (blockIdx.y == 1) ? w1
                     : (blockIdx.y == 2) ? w2 : w3;
    float4 v = ((const float4*)src)[i];
    __half2* op = (__half2*)(out + (size_t)blockIdx.y * CC * CC);
    op[2 * i + 0] = __floats2half2_rn(v.x, v.y);
    op[2 * i + 1] = __floats2half2_rn(v.z, v.w);
}

__global__ void split16_kernel(const float* __restrict__ in,
                               __half* __restrict__ hi,
                               __half* __restrict__ lo, int n4)
{
    int i = blockIdx.x * blockDim.x + threadIdx.x;
    if (i >= n4) return;
    float4 v = ((const float4*)in)[i];
    __half h0 = __float2half_rn(v.x);
    __half h1 = __float2half_rn(v.y);
    __half h2 = __float2half_rn(v.z);
    __half h3 = __float2half_rn(v.w);
    __half l0 = __float2half_rn(v.x - __half2float(h0));
    __half l1 = __float2half_rn(v.y - __half2float(h1));
    __half l2 = __float2half_rn(v.z - __half2float(h2));
    __half l3 = __float2half_rn(v.w - __half2float(h3));
    __half2* hp = (__half2*)hi;
    __half2* lp = (__half2*)lo;
    hp[2 * i + 0] = __halves2half2(h0, h1);
    hp[2 * i + 1] = __halves2half2(h2, h3);
    lp[2 * i + 0] = __halves2half2(l0, l1);
    lp[2 * i + 1] = __halves2half2(l2, l3);
}

// ---------------------------------------------------------------------------
// Core GEMM tile: C[128,128] = A[M,K] x W[N,K]^T
// TWO=true : fp16 asymmetric 2-pass (A = Ah + Al). TWO=false: single-pass.
// BK=64, 2-stage cp.async ring, 2 CTAs/SM.
// Epilogue modes: 0 = fp32; 1 = fp16 scaled 1/8 (Q); 2 = fp16 (K/V).
// ---------------------------------------------------------------------------
#define ROWB 144u
#define TILEB (128u*ROWB)        // 18432
#define STAGEB (3u*TILEB)        // 55296
#define NSTAGE 2
#define NCHUNK (CC/64)           // 16

template<bool TWO>
__device__ __forceinline__ void gemm_tile(
    const __half* __restrict__ Ah, const __half* __restrict__ Al,
    const __half* __restrict__ B,
    void* out0, int mode,
    int m0, int n0, char* smem)
{
    const uint32_t sb = smem_u32(smem);
    const int tid  = threadIdx.x;
    const int lane = tid & 31;
    const int wid  = tid >> 5;
    const int wm   = wid >> 1;
    const int wn   = wid & 1;

    const __half* srcA0 = Ah + (size_t)m0 * CC;
    const __half* srcA1 = TWO ? (Al + (size_t)m0 * CC) : nullptr;
    const __half* srcB  = B + (size_t)n0 * CC;

    auto issue_stage = [&](int chunk, int stage) {
        const int kc = chunk * 64;
        const uint32_t base = sb + (uint32_t)stage * STAGEB;
        const int NT = TWO ? 12 : 8;
#pragma unroll
        for (int t = 0; t < NT; t++) {
            int lin  = tid + t * 256;
            int tile = lin >> 10;
            int idx  = lin & 1023;
            int row  = idx >> 3;
            int seg  = idx & 7;
            const __half* src;
            uint32_t slot;
            if (TWO) {
                src  = (tile == 0) ? srcA0 : (tile == 1) ? srcA1 : srcB;
                slot = (uint32_t)tile;
            } else {
                src  = (tile == 0) ? srcA0 : srcB;
                slot = (tile == 0) ? 0u : 2u;
            }
            uint32_t dst = base + slot * TILEB + (uint32_t)row * ROWB + (uint32_t)seg * 16u;
            cp16(dst, src + (size_t)row * CC + kc + seg * 8);
        }
        CP_COMMIT();
    };

    float acc[2][8][4];
#pragma unroll
    for (int i = 0; i < 2; i++)
#pragma unroll
        for (int j = 0; j < 8; j++)
#pragma unroll
            for (int r = 0; r < 4; r++) acc[i][j][r] = 0.f;

    issue_stage(0, 0);

    const uint32_t a_row  = (uint32_t)(lane & 15);
    const uint32_t a_koff = (uint32_t)(lane >> 4) * 16u;
    const uint32_t b_row  = (uint32_t)(lane & 7);
    const uint32_t b_koff = (uint32_t)((lane >> 3) & 1) * 16u;

    for (int c = 0; c < NCHUNK; c++) {
        const int stage = c & 1;
        if (c + 1 < NCHUNK) { issue_stage(c + 1, stage ^ 1); CP_WAIT(1); }
        else                { CP_WAIT(0); }
        __syncthreads();

        const uint32_t base  = sb + (uint32_t)stage * STAGEB;
        const uint32_t Aho   = base;
        const uint32_t Alo_o = base + TILEB;
        const uint32_t Bo    = base + 2u * TILEB;

#pragma unroll
        for (int kk = 0; kk < 4; kk++) {
            const uint32_t ko = (uint32_t)kk * 32u;
            uint32_t ah[2][4], al[2][4];
#pragma unroll
            for (int fi = 0; fi < 2; fi++) {
                uint32_t ra = (uint32_t)(wm * 32 + fi * 16) * ROWB + a_row * ROWB + ko + a_koff;
                ldm_x4(ah[fi], Aho + ra);
                if (TWO) ldm_x4(al[fi], Alo_o + ra);
            }
#pragma unroll
            for (int j = 0; j < 8; j++) {
                uint32_t rb = (uint32_t)(wn * 64 + j * 8) * ROWB + b_row * ROWB + ko + b_koff;
                uint32_t bf[2];
                ldm_x2(bf, Bo + rb);
#pragma unroll
                for (int fi = 0; fi < 2; fi++) {
                    mma_f16(acc[fi][j], ah[fi], bf);
                    if (TWO) mma_f16(acc[fi][j], al[fi], bf);
                }
            }
        }
        __syncthreads();
    }

#pragma unroll
    for (int fi = 0; fi < 2; fi++) {
        int row0 = m0 + wm * 32 + fi * 16 + (lane >> 2);
#pragma unroll
        for (int j = 0; j < 8; j++) {
            int col = n0 + wn * 64 + j * 8 + (lane & 3) * 2;
            float a0 = acc[fi][j][0], a1 = acc[fi][j][1];
            float a2 = acc[fi][j][2], a3 = acc[fi][j][3];
            if (mode == 0) {
                float* C = (float*)out0;
                *(float2*)&C[(size_t)row0 * CC + col]       = make_float2(a0, a1);
                *(float2*)&C[(size_t)(row0 + 8) * CC + col] = make_float2(a2, a3);
            } else {
                __half* Cf = (__half*)out0;
                float sc = (mode == 1) ? 0.125f : 1.0f;
                *(__half2*)&Cf[(size_t)row0 * CC + col] =
                    __floats2half2_rn(a0 * sc, a1 * sc);
                *(__half2*)&Cf[(size_t)(row0 + 8) * CC + col] =
                    __floats2half2_rn(a2 * sc, a3 * sc);
            }
        }
    }
}

// Fused QKV: grid.x in [0,24): wsel = x>>3, n0 = (x&7)*128
// Q, K: 2-pass compute (score path, accurate). V: single-pass (value path).
__global__ __launch_bounds__(256, 2) void gemm_qkv(
    const __half* __restrict__ xh, const __half* __restrict__ xl,
    const __half* __restrict__ w16,
    __half* __restrict__ qf, __half* __restrict__ kf, __half* __restrict__ vf)
{
    extern __shared__ char smem[];
    const int wsel = blockIdx.x >> 3;
    const int n0 = (blockIdx.x & 7) * 128;
    const int m0 = blockIdx.y * 128;
    if (wsel == 0)
        gemm_tile<true>(xh, xl, w16, qf, 1, m0, n0, smem);
    else if (wsel == 1)
        gemm_tile<true>(xh, xl, w16 + (size_t)CC * CC, kf, 2, m0, n0, smem);
    else
        gemm_tile<false>(xh, nullptr, w16 + 2 * (size_t)CC * CC, vf, 2, m0, n0, smem);
}

// Output projection: single-pass fp16 (value path).
__global__ __launch_bounds__(256, 2) void gemm_one(
    const __half* __restrict__ Af,
    const __half* __restrict__ B, float* __restrict__ C)
{
    extern __shared__ char smem[];
    gemm_tile<false>(Af, nullptr, B, C, 0, blockIdx.y * 128, blockIdx.x * 128, smem);
}

// ---------------------------------------------------------------------------
// Tensor-core flash attention (causal), all-single-pass fp16 MMAs.
// 128 threads / 4 warps, 64 queries/CTA, 4 CTAs/SM.
// K and V fragments loaded with paired ldmatrix.x4 (V via .trans).
// SMEM: Qf, Kf, Vf — 3 x 64 x 72 fp16 = 27 KB.
// ---------------------------------------------------------------------------
#define AP 72
#define APB (AP * 2)          // 144 bytes per row
#define ATILE (64 * AP)

__global__ __launch_bounds__(128, 4) void attn_tc()
{
    extern __shared__ __half ash[];
    __half* Qf = ash;
    __half* Kf = Qf + ATILE;
    __half* Vf = Kf + ATILE;
    const uint32_t sQf = smem_u32(Qf);
    const uint32_t sKf = smem_u32(Kf), sVf = smem_u32(Vf);

    const int tid  = threadIdx.x;
    const int lane = tid & 31;
    const int w    = tid >> 5;            // 0..3
    const int qtile = blockIdx.x;         // 0..31
    const int bh = blockIdx.y;
    const int b = bh / HH, h = bh % HH;
    const int q0 = qtile * 64;

    const size_t hoff = (size_t)b * TT * CC + h * DD;
    const __half* qfp = g_qf + hoff;
    const __half* kfp = g_kf + hoff;
    const __half* vfp = g_vf + hoff;

    // ---- load Q (straight 16B copies) ----
#pragma unroll
    for (int it = 0; it < 4; it++) {
        int lin = tid + it * 128;       // 0..511
        int row = lin >> 3;             // 0..63
        int seg = lin & 7;
        uint4 vq = *(const uint4*)&qfp[(size_t)(q0 + row) * CC + seg * 8];
        *(uint4*)&Qf[row * AP + seg * 8] = vq;
    }

    float m0r = -1e30f, m1r = -1e30f, l0r = 0.f, l1r = 0.f;
    float ofr[8][4];
#pragma unroll
    for (int j = 0; j < 8; j++)
#pragma unroll
        for (int r = 0; r < 4; r++) ofr[j][r] = 0.f;

    const int r0g = q0 + w * 16 + (lane >> 2);
    const int r1g = r0g + 8;

    // ldmatrix lane-address components
    const uint32_t a_row  = (uint32_t)(lane & 15);
    const uint32_t a_koff = (uint32_t)(lane >> 4) * 16u;
    const uint32_t lg  = (uint32_t)(lane >> 3);   // group 0..3
    const uint32_t lr  = (uint32_t)(lane & 7);    // row in group
    // K x4 pairing: row = jp*16 + (g>>1)*8 + r ; koff += (g&1)*16
    const uint32_t k_rowoff = ((lg >> 1) & 1u) * 8u + lr;
    const uint32_t k_koff   = (lg & 1u) * 16u;
    // V x4t pairing: row = s*16 + (g&1)*8 + r ; dbyte = jp*32 + (g>>1)*16
    const uint32_t v_rowoff = (lg & 1u) * 8u + lr;
    const uint32_t v_doff   = ((lg >> 1) & 1u) * 16u;

    const int nkt = qtile + 1;
    for (int kt = 0; kt < nkt; kt++) {
        const int k0 = kt * 64;
        __syncthreads();
#pragma unroll
        for (int it = 0; it < 4; it++) {
            int lin = tid + it * 128;   // 0..511
            int row = lin >> 3;
            int seg = lin & 7;
            uint4 kv = *(const uint4*)&kfp[(size_t)(k0 + row) * CC + seg * 8];
            uint4 vv = *(const uint4*)&vfp[(size_t)(k0 + row) * CC + seg * 8];
            *(uint4*)&Kf[row * AP + seg * 8] = kv;
            *(uint4*)&Vf[row * AP + seg * 8] = vv;
        }
        __syncthreads();

        // ---- S = Q*K^T (single-pass fp16, K frags paired x4) ----
        float sfr[8][4];
#pragma unroll
        for (int j = 0; j < 8; j++)
#pragma unroll
            for (int r = 0; r < 4; r++) sfr[j][r] = 0.f;

#pragma unroll
        for (int s = 0; s < 4; s++) {
            const uint32_t ko = (uint32_t)s * 32u;
            uint32_t aq[4];
            uint32_t ra = (uint32_t)(w * 16) * APB + a_row * APB + ko + a_koff;
            ldm_x4(aq, sQf + ra);
#pragma unroll
            for (int jp = 0; jp < 4; jp++) {
                uint32_t rb = (uint32_t)(jp * 16) * APB + k_rowoff * APB + ko + k_koff;
                uint32_t bk[4];
                ldm_x4(bk, sKf + rb);
                mma_f16(sfr[jp * 2 + 0], aq, bk);
                mma_f16(sfr[jp * 2 + 1], aq, bk + 2);
            }
        }

        // ---- causal mask on diagonal tile ----
        if (kt == qtile) {
#pragma unroll
            for (int j = 0; j < 8; j++) {
                int cbase = k0 + j * 8 + 2 * (lane & 3);
                if (cbase > r0g)     sfr[j][0] = -1e30f;
                if (cbase + 1 > r0g) sfr[j][1] = -1e30f;
                if (cbase > r1g)     sfr[j][2] = -1e30f;
                if (cbase + 1 > r1g) sfr[j][3] = -1e30f;
            }
        }

        // ---- online softmax ----
        float mx0 = -1e30f, mx1 = -1e30f;
#pragma unroll
        for (int j = 0; j < 8; j++) {
            mx0 = fmaxf(mx0, fmaxf(sfr[j][0], sfr[j][1]));
            mx1 = fmaxf(mx1, fmaxf(sfr[j][2], sfr[j][3]));
        }
        mx0 = fmaxf(mx0, __shfl_xor_sync(0xffffffffu, mx0, 1));
        mx0 = fmaxf(mx0, __shfl_xor_sync(0xffffffffu, mx0, 2));
        mx1 = fmaxf(mx1, __shfl_xor_sync(0xffffffffu, mx1, 1));
        mx1 = fmaxf(mx1, __shfl_xor_sync(0xffffffffu, mx1, 2));

        float mn0 = fmaxf(m0r, mx0), mn1 = fmaxf(m1r, mx1);
        float corr0 = __expf(m0r - mn0), corr1 = __expf(m1r - mn1);
        m0r = mn0; m1r = mn1;

        float rs0 = 0.f, rs1 = 0.f;
#pragma unroll
        for (int j = 0; j < 8; j++) {
            sfr[j][0] = __expf(sfr[j][0] - mn0);
            sfr[j][1] = __expf(sfr[j][1] - mn0);
            sfr[j][2] = __expf(sfr[j][2] - mn1);
            sfr[j][3] = __expf(sfr[j][3] - mn1);
            rs0 += sfr[j][0] + sfr[j][1];
            rs1 += sfr[j][2] + sfr[j][3];
        }
        rs0 += __shfl_xor_sync(0xffffffffu, rs0, 1);
        rs0 += __shfl_xor_sync(0xffffffffu, rs0, 2);
        rs1 += __shfl_xor_sync(0xffffffffu, rs1, 1);
        rs1 += __shfl_xor_sync(0xffffffffu, rs1, 2);
        l0r = l0r * corr0 + rs0;
        l1r = l1r * corr1 + rs1;

#pragma unroll
        for (int j = 0; j < 8; j++) {
            ofr[j][0] *= corr0; ofr[j][1] *= corr0;
            ofr[j][2] *= corr1; ofr[j][3] *= corr1;
        }

        // ---- pack P to fp16 A-fragments (single plane) ----
        uint32_t pah[4][4];
#pragma unroll
        for (int s = 0; s < 4; s++) {
            const int ja = 2 * s, jb = 2 * s + 1;
            pah[s][0] = pack_f16x2(sfr[ja][0], sfr[ja][1]);
            pah[s][1] = pack_f16x2(sfr[ja][2], sfr[ja][3]);
            pah[s][2] = pack_f16x2(sfr[jb][0], sfr[jb][1]);
            pah[s][3] = pack_f16x2(sfr[jb][2], sfr[jb][3]);
        }

        // ---- O += P*V (single-pass fp16), V frags paired x4 trans ----
#pragma unroll
        for (int jp = 0; jp < 4; jp++) {
#pragma unroll
            for (int s = 0; s < 4; s++) {
                uint32_t rv = (uint32_t)(s * 16) * APB + v_rowoff * APB
                            + (uint32_t)(jp * 32) + v_doff;
                uint32_t bv[4];
                ldm_x4t(bv, sVf + rv);
                mma_f16(ofr[jp * 2 + 0], pah[s], bv);
                mma_f16(ofr[jp * 2 + 1], pah[s], bv + 2);
            }
        }
    }

    // ---- epilogue: normalize, single fp16 plane for WO GEMM ----
    float inv0 = 1.f / l0r, inv1 = 1.f / l1r;
    __half* afp = g_af + hoff;
#pragma unroll
    for (int j = 0; j < 8; j++) {
        int col = j * 8 + 2 * (lane & 3);
        *(__half2*)&afp[(size_t)r0g * CC + col] =
            __floats2half2_rn(ofr[j][0] * inv0, ofr[j][1] * inv0);
        *(__half2*)&afp[(size_t)r1g * CC + col] =
            __floats2half2_rn(ofr[j][2] * inv1, ofr[j][3] * inv1);
    }
}

// ---------------------------------------------------------------------------
extern "C" void kernel_launch(void* const* d_in, const int* in_sizes, int n_in,
                              void* d_out, int out_size)
{
    const float* x   = (const float*)d_in[0];
    const float* W_Q = (const float*)d_in[1];
    const float* W_K = (const float*)d_in[2];
    const float* W_V = (const float*)d_in[3];
    const float* W_O = (const float*)d_in[4];
    float* out = (float*)d_out;

    __half *xh, *xl, *qf, *kf, *vf, *af, *w16;
    cudaGetSymbolAddress((void**)&xh,  g_xh);
    cudaGetSymbolAddress((void**)&xl,  g_xl);
    cudaGetSymbolAddress((void**)&qf,  g_qf);
    cudaGetSymbolAddress((void**)&kf,  g_kf);
    cudaGetSymbolAddress((void**)&vf,  g_vf);
    cudaGetSymbolAddress((void**)&af,  g_af);
    cudaGetSymbolAddress((void**)&w16, g_w16);

    const int gemm_smem = NSTAGE * (int)STAGEB;   // 110592 -> 2 CTAs/SM
    cudaFuncSetAttribute(gemm_qkv,
                         cudaFuncAttributeMaxDynamicSharedMemorySize, gemm_smem);
    cudaFuncSetAttribute(gemm_one,
                         cudaFuncAttributeMaxDynamicSharedMemorySize, gemm_smem);
    const int attn_smem = 3 * ATILE * (int)sizeof(__half);   // 27648 -> 4 CTAs/SM
    cudaFuncSetAttribute(attn_tc,
                         cudaFuncAttributeMaxDynamicSharedMemorySize, attn_smem);

    {
        int n4 = MM * CC / 4;
        split16_kernel<<<(n4 + 255) / 256, 256>>>(x, xh, xl, n4);
        int w4 = CC * CC / 4;
        dim3 wg((w4 + 255) / 256, 4);
        conv16x4_kernel<<<wg, 256>>>(W_Q, W_K, W_V, W_O, w16, w4);
    }

    dim3 qkvgrid(24, MM / 128);   // (24, 64)
    gemm_qkv<<<qkvgrid, 256, gemm_smem>>>(xh, xl, w16, qf, kf, vf);

    dim3 agrid(TT / 64, BB * HH);   // (32, 64)
    attn_tc<<<agrid, 128, attn_smem>>>();

    dim3 ogrid(CC / 128, MM / 128);
    gemm_one<<<ogrid, 256, gemm_smem>>>(af, w16 + 3 * (size_t)CC * CC, out);
}